// round 1
// baseline (speedup 1.0000x reference)
#include <cuda_runtime.h>
#include <cuda_bf16.h>
#include <cstdint>
#include <cstddef>

// ---------------------------------------------------------------------------
// Hyena operator: B=2, L=4096, D=1024, ORDER=2, OD=3072, EMB=33, FREQ=10
// Pipeline:
//   1) res[b,od,l] = (u @ w_in^T + b_in) transposed           (SGEMM, 51.5 GF)
//   2) conv3 along l (+conv_b)                                 (mem-bound)
//   3) h[n,d,l] filter MLP + decay                             (small GEMM)
//   4) Hf = DIF-FFT(h, 8192)  (bit-reversed spectra, cached)
//   5) per order n: v <- (IFFT(FFT(v) * Hf[n])[:L]) * x[n]     (fused kernel)
//   6) out = v^T @ w_out^T + b_out                             (SGEMM, 17.2 GF)
// FFT: length 8192 complex in 64KB smem, DIF fwd + DIT inv (no bit reversal).
// ---------------------------------------------------------------------------

#define LSEQ 4096
#define NF   8192
#define DDIM 1024
#define ODIM 3072
#define BSZ  2
#define FFT_THREADS 512

// Scratch (device .bss — allocation-free)
__device__ float  g_res[(size_t)BSZ * ODIM * LSEQ];   // GEMM-in output [b,od,l]
__device__ float  g_cv [(size_t)BSZ * ODIM * LSEQ];   // conv3 output   [b,od,l]
__device__ float  g_v  [(size_t)BSZ * DDIM * LSEQ];   // running v      [b,d,l]
__device__ float  g_h  [(size_t)2   * DDIM * LSEQ];   // filter h       [n,d,l]
__device__ float2 g_Hf [(size_t)2   * DDIM * NF];     // DIF spectra of h
__device__ float2 g_tw [NF / 2];                      // twiddles exp(-2pi i k/NF)

// ---------------------------------------------------------------------------
__global__ void twiddle_kernel() {
    int k = blockIdx.x * blockDim.x + threadIdx.x;
    if (k < NF / 2) {
        double ang = -2.0 * 3.141592653589793238462643 * (double)k / (double)NF;
        g_tw[k] = make_float2((float)cos(ang), (float)sin(ang));
    }
}

// ---------------------------------------------------------------------------
// Filter MLP: per position l, compute h[n,d,l]
__global__ __launch_bounds__(256) void filter_kernel(
    const float* __restrict__ w1, const float* __restrict__ b1,
    const float* __restrict__ w2, const float* __restrict__ b2,
    const float* __restrict__ fb, const float* __restrict__ fd)
{
    __shared__ float pe[33];
    __shared__ float sact[64];
    const int l = blockIdx.x;
    const float t = (float)l * (1.0f / (float)(LSEQ - 1));
    const int tid = threadIdx.x;

    if (tid < 33) pe[tid] = sinf(t * (float)tid * 10.0f);
    __syncthreads();
    if (tid < 64) {
        float z = b1[tid];
        #pragma unroll
        for (int j = 0; j < 33; j++) z += pe[j] * w1[tid * 33 + j];
        sact[tid] = sinf(10.0f * z);
    }
    __syncthreads();

    for (int o = tid; o < 2 * DDIM; o += 256) {
        float acc = b2[o];
        #pragma unroll
        for (int i = 0; i < 64; i++) acc += sact[i] * w2[o * 64 + i];
        float dec = expf(-expf(fd[o]) * t);
        float hv  = (acc * dec + fb[o]) * (1.0f / (float)LSEQ);
        g_h[(size_t)o * LSEQ + l] = hv;
    }
}

// ---------------------------------------------------------------------------
// FFT helpers (shared-memory, 8192-point complex, 512 threads)
__device__ __forceinline__ float2 cmulf(float2 a, float2 b) {
    return make_float2(a.x * b.x - a.y * b.y, a.x * b.y + a.y * b.x);
}

// Forward DIF: natural order in -> bit-reversed order out
__device__ __forceinline__ void fft_dif(float2* S) {
    #pragma unroll
    for (int s = 12; s >= 0; s--) {
        const int half = 1 << s;
        const int tsh  = 12 - s;
        #pragma unroll
        for (int jj = 0; jj < (NF / 2) / FFT_THREADS; jj++) {
            int j  = threadIdx.x + jj * FFT_THREADS;
            int p  = j & (half - 1);
            int i0 = ((j >> s) << (s + 1)) | p;
            int i1 = i0 + half;
            float2 a = S[i0], b = S[i1];
            float2 w = g_tw[p << tsh];
            S[i0] = make_float2(a.x + b.x, a.y + b.y);
            float2 d = make_float2(a.x - b.x, a.y - b.y);
            S[i1] = make_float2(d.x * w.x - d.y * w.y, d.x * w.y + d.y * w.x);
        }
        __syncthreads();
    }
}

// Inverse DIT (conjugate twiddles): bit-reversed order in -> natural out (unscaled)
__device__ __forceinline__ void fft_dit_inv(float2* S) {
    #pragma unroll
    for (int s = 0; s <= 12; s++) {
        const int half = 1 << s;
        const int tsh  = 12 - s;
        #pragma unroll
        for (int jj = 0; jj < (NF / 2) / FFT_THREADS; jj++) {
            int j  = threadIdx.x + jj * FFT_THREADS;
            int p  = j & (half - 1);
            int i0 = ((j >> s) << (s + 1)) | p;
            int i1 = i0 + half;
            float2 w = g_tw[p << tsh];
            float2 b = S[i1];
            // b * conj(w)
            float2 tt = make_float2(b.x * w.x + b.y * w.y, b.y * w.x - b.x * w.y);
            float2 a = S[i0];
            S[i0] = make_float2(a.x + tt.x, a.y + tt.y);
            S[i1] = make_float2(a.x - tt.x, a.y - tt.y);
        }
        __syncthreads();
    }
}

// Precompute H spectra (bit-reversed domain)
__global__ __launch_bounds__(FFT_THREADS) void hfft_kernel() {
    extern __shared__ float2 S[];
    const int c = blockIdx.x;                 // n*1024 + d
    const float* h = g_h + (size_t)c * LSEQ;
    for (int i = threadIdx.x; i < LSEQ; i += FFT_THREADS) S[i] = make_float2(h[i], 0.0f);
    for (int i = LSEQ + threadIdx.x; i < NF; i += FFT_THREADS) S[i] = make_float2(0.0f, 0.0f);
    __syncthreads();
    fft_dif(S);
    float2* out = g_Hf + (size_t)c * NF;
    for (int i = threadIdx.x; i < NF; i += FFT_THREADS) out[i] = S[i];
}

// Fused: v <- irfft(fft(v) * Hf)[:L] * x   (one CTA per (b,d) channel)
__global__ __launch_bounds__(FFT_THREADS) void fftconv_kernel(int order) {
    extern __shared__ float2 S[];
    const int c = blockIdx.x;
    const int b = c >> 10;
    const int d = c & 1023;

    const float* v = (order == 0)
        ? &g_cv[((size_t)(b * 3 + 2) * DDIM + d) * LSEQ]
        : &g_v [((size_t)b * DDIM + d) * LSEQ];
    const float* x = &g_cv[((size_t)(b * 3 + order) * DDIM + d) * LSEQ];
    const float2* H = &g_Hf[((size_t)order * DDIM + d) * NF];
    float* o = &g_v[((size_t)b * DDIM + d) * LSEQ];

    for (int i = threadIdx.x; i < LSEQ; i += FFT_THREADS) S[i] = make_float2(v[i], 0.0f);
    for (int i = LSEQ + threadIdx.x; i < NF; i += FFT_THREADS) S[i] = make_float2(0.0f, 0.0f);
    __syncthreads();

    fft_dif(S);

    for (int i = threadIdx.x; i < NF; i += FFT_THREADS) S[i] = cmulf(S[i], H[i]);
    __syncthreads();

    fft_dit_inv(S);

    const float inv = 1.0f / (float)NF;
    for (int l = threadIdx.x; l < LSEQ; l += FFT_THREADS)
        o[l] = S[l].x * inv * x[l];
}

// ---------------------------------------------------------------------------
// SGEMM 1: g_res[b, od, l] = sum_d w_in[od,d] * u[b,l,d] + b_in[od]
#define BM 128
#define BN 128
#define BK 16

__global__ __launch_bounds__(256) void gemm_in_kernel(
    const float* __restrict__ W,    // [3072,1024] K-contig
    const float* __restrict__ U,    // [2,4096,1024] K-contig
    const float* __restrict__ bias) // [3072]
{
    __shared__ float As[BK][BM];
    __shared__ float Bs[BK][BN];
    const int b  = blockIdx.z;
    const int m0 = blockIdx.y * BM;     // od
    const int n0 = blockIdx.x * BN;     // l
    const float* Bm = U + (size_t)b * LSEQ * DDIM;
    float* C = g_res + (size_t)b * ODIM * LSEQ;

    const int tid  = threadIdx.x;
    const int tm   = tid >> 4;
    const int tn   = tid & 15;
    const int lrow = tid >> 1;
    const int lk   = (tid & 1) * 8;

    float acc[8][8];
    #pragma unroll
    for (int i = 0; i < 8; i++)
        #pragma unroll
        for (int j = 0; j < 8; j++) acc[i][j] = 0.0f;

    for (int k0 = 0; k0 < DDIM; k0 += BK) {
        float4 a0 = *(const float4*)&W[(size_t)(m0 + lrow) * DDIM + k0 + lk];
        float4 a1 = *(const float4*)&W[(size_t)(m0 + lrow) * DDIM + k0 + lk + 4];
        As[lk + 0][lrow] = a0.x; As[lk + 1][lrow] = a0.y;
        As[lk + 2][lrow] = a0.z; As[lk + 3][lrow] = a0.w;
        As[lk + 4][lrow] = a1.x; As[lk + 5][lrow] = a1.y;
        As[lk + 6][lrow] = a1.z; As[lk + 7][lrow] = a1.w;
        float4 c0 = *(const float4*)&Bm[(size_t)(n0 + lrow) * DDIM + k0 + lk];
        float4 c1 = *(const float4*)&Bm[(size_t)(n0 + lrow) * DDIM + k0 + lk + 4];
        Bs[lk + 0][lrow] = c0.x; Bs[lk + 1][lrow] = c0.y;
        Bs[lk + 2][lrow] = c0.z; Bs[lk + 3][lrow] = c0.w;
        Bs[lk + 4][lrow] = c1.x; Bs[lk + 5][lrow] = c1.y;
        Bs[lk + 6][lrow] = c1.z; Bs[lk + 7][lrow] = c1.w;
        __syncthreads();

        #pragma unroll
        for (int k = 0; k < BK; k++) {
            float4 ra0 = *(const float4*)&As[k][tm * 8];
            float4 ra1 = *(const float4*)&As[k][tm * 8 + 4];
            float4 rb0 = *(const float4*)&Bs[k][tn * 8];
            float4 rb1 = *(const float4*)&Bs[k][tn * 8 + 4];
            float ra[8] = {ra0.x, ra0.y, ra0.z, ra0.w, ra1.x, ra1.y, ra1.z, ra1.w};
            float rb[8] = {rb0.x, rb0.y, rb0.z, rb0.w, rb1.x, rb1.y, rb1.z, rb1.w};
            #pragma unroll
            for (int i = 0; i < 8; i++)
                #pragma unroll
                for (int j = 0; j < 8; j++) acc[i][j] += ra[i] * rb[j];
        }
        __syncthreads();
    }

    #pragma unroll
    for (int i = 0; i < 8; i++) {
        int m = m0 + tm * 8 + i;
        float bv = bias[m];
        float4 o0 = make_float4(acc[i][0] + bv, acc[i][1] + bv, acc[i][2] + bv, acc[i][3] + bv);
        float4 o1 = make_float4(acc[i][4] + bv, acc[i][5] + bv, acc[i][6] + bv, acc[i][7] + bv);
        *(float4*)&C[(size_t)m * LSEQ + n0 + tn * 8]     = o0;
        *(float4*)&C[(size_t)m * LSEQ + n0 + tn * 8 + 4] = o1;
    }
}

// ---------------------------------------------------------------------------
// Depthwise conv3 along l (+bias): g_cv = conv3(g_res)
__global__ void conv3_kernel(const float* __restrict__ cw, const float* __restrict__ cb) {
    const int row = blockIdx.y;            // b*3072 + od
    const int od  = row % ODIM;
    const int l   = blockIdx.x * 256 + threadIdx.x;
    const float* r = g_res + (size_t)row * LSEQ;
    float left  = (l > 0)        ? r[l - 1] : 0.0f;
    float mid   = r[l];
    float right = (l < LSEQ - 1) ? r[l + 1] : 0.0f;
    float w0 = cw[od * 3], w1 = cw[od * 3 + 1], w2 = cw[od * 3 + 2];
    g_cv[(size_t)row * LSEQ + l] = w0 * left + w1 * mid + w2 * right + cb[od];
}

// ---------------------------------------------------------------------------
// SGEMM 2: out[b,l,e] = sum_d g_v[b,d,l] * w_out[e,d] + b_out[e]
__global__ __launch_bounds__(256) void gemm_out_kernel(
    const float* __restrict__ Wo,    // [1024,1024] K-contig
    const float* __restrict__ bias,  // [1024]
    float* __restrict__ O)           // [2,4096,1024]
{
    __shared__ float As[BK][BM];
    __shared__ float Bs[BK][BN];
    const int b  = blockIdx.z;
    const int m0 = blockIdx.y * BM;     // l
    const int n0 = blockIdx.x * BN;     // e
    const float* Av = g_v + (size_t)b * DDIM * LSEQ;   // [d][l]
    float* C = O + (size_t)b * LSEQ * DDIM;

    const int tid  = threadIdx.x;
    const int tm   = tid >> 4;
    const int tn   = tid & 15;
    const int lak  = tid >> 4;          // 0..15 : k-row for A tile
    const int lam  = (tid & 15) * 8;    // m offset
    const int lrow = tid >> 1;          // B tile loader (like gemm_in)
    const int lk   = (tid & 1) * 8;

    float acc[8][8];
    #pragma unroll
    for (int i = 0; i < 8; i++)
        #pragma unroll
        for (int j = 0; j < 8; j++) acc[i][j] = 0.0f;

    for (int k0 = 0; k0 < DDIM; k0 += BK) {
        // A tile: As[k][m] = v[(k0+k)*L + m0+m] — contiguous along m
        float4 a0 = *(const float4*)&Av[(size_t)(k0 + lak) * LSEQ + m0 + lam];
        float4 a1 = *(const float4*)&Av[(size_t)(k0 + lak) * LSEQ + m0 + lam + 4];
        *(float4*)&As[lak][lam]     = a0;
        *(float4*)&As[lak][lam + 4] = a1;
        // B tile: Bs[k][n] = Wo[(n0+n)*K + k0+k]
        float4 c0 = *(const float4*)&Wo[(size_t)(n0 + lrow) * DDIM + k0 + lk];
        float4 c1 = *(const float4*)&Wo[(size_t)(n0 + lrow) * DDIM + k0 + lk + 4];
        Bs[lk + 0][lrow] = c0.x; Bs[lk + 1][lrow] = c0.y;
        Bs[lk + 2][lrow] = c0.z; Bs[lk + 3][lrow] = c0.w;
        Bs[lk + 4][lrow] = c1.x; Bs[lk + 5][lrow] = c1.y;
        Bs[lk + 6][lrow] = c1.z; Bs[lk + 7][lrow] = c1.w;
        __syncthreads();

        #pragma unroll
        for (int k = 0; k < BK; k++) {
            float4 ra0 = *(const float4*)&As[k][tm * 8];
            float4 ra1 = *(const float4*)&As[k][tm * 8 + 4];
            float4 rb0 = *(const float4*)&Bs[k][tn * 8];
            float4 rb1 = *(const float4*)&Bs[k][tn * 8 + 4];
            float ra[8] = {ra0.x, ra0.y, ra0.z, ra0.w, ra1.x, ra1.y, ra1.z, ra1.w};
            float rb[8] = {rb0.x, rb0.y, rb0.z, rb0.w, rb1.x, rb1.y, rb1.z, rb1.w};
            #pragma unroll
            for (int i = 0; i < 8; i++)
                #pragma unroll
                for (int j = 0; j < 8; j++) acc[i][j] += ra[i] * rb[j];
        }
        __syncthreads();
    }

    float bb[8];
    #pragma unroll
    for (int j = 0; j < 8; j++) bb[j] = bias[n0 + tn * 8 + j];

    #pragma unroll
    for (int i = 0; i < 8; i++) {
        int m = m0 + tm * 8 + i;
        float4 o0 = make_float4(acc[i][0] + bb[0], acc[i][1] + bb[1],
                                acc[i][2] + bb[2], acc[i][3] + bb[3]);
        float4 o1 = make_float4(acc[i][4] + bb[4], acc[i][5] + bb[5],
                                acc[i][6] + bb[6], acc[i][7] + bb[7]);
        *(float4*)&C[(size_t)m * DDIM + n0 + tn * 8]     = o0;
        *(float4*)&C[(size_t)m * DDIM + n0 + tn * 8 + 4] = o1;
    }
}

// ---------------------------------------------------------------------------
extern "C" void kernel_launch(void* const* d_in, const int* in_sizes, int n_in,
                              void* d_out, int out_size)
{
    const float* u          = (const float*)d_in[0];
    const float* w_in       = (const float*)d_in[1];
    const float* b_in       = (const float*)d_in[2];
    const float* conv_w     = (const float*)d_in[3];
    const float* conv_b     = (const float*)d_in[4];
    const float* w1         = (const float*)d_in[5];
    const float* b1         = (const float*)d_in[6];
    const float* w2         = (const float*)d_in[7];
    const float* b2         = (const float*)d_in[8];
    const float* filt_bias  = (const float*)d_in[9];
    const float* filt_decay = (const float*)d_in[10];
    const float* w_out      = (const float*)d_in[11];
    const float* b_out      = (const float*)d_in[12];
    float* out = (float*)d_out;

    static bool attr_set = false;
    if (!attr_set) {
        cudaFuncSetAttribute(hfft_kernel,    cudaFuncAttributeMaxDynamicSharedMemorySize, 65536);
        cudaFuncSetAttribute(fftconv_kernel, cudaFuncAttributeMaxDynamicSharedMemorySize, 65536);
        attr_set = true;
    }

    // Filter path (independent of u)
    twiddle_kernel<<<16, 256>>>();
    filter_kernel<<<LSEQ, 256>>>(w1, b1, w2, b2, filt_bias, filt_decay);
    hfft_kernel<<<2 * DDIM, FFT_THREADS, 65536>>>();

    // Main path
    gemm_in_kernel<<<dim3(LSEQ / BN, ODIM / BM, BSZ), 256>>>(w_in, u, b_in);
    conv3_kernel<<<dim3(LSEQ / 256, BSZ * ODIM), 256>>>(conv_w, conv_b);

    fftconv_kernel<<<BSZ * DDIM, FFT_THREADS, 65536>>>(0);
    fftconv_kernel<<<BSZ * DDIM, FFT_THREADS, 65536>>>(1);

    gemm_out_kernel<<<dim3(DDIM / BN, LSEQ / BM, BSZ), 256>>>(w_out, b_out, out);
}

// round 2
// speedup vs baseline: 1.0561x; 1.0561x over previous
#include <cuda_runtime.h>
#include <cuda_bf16.h>
#include <cstdint>
#include <cstddef>

// ---------------------------------------------------------------------------
// Hyena operator: B=2, L=4096, D=1024, ORDER=2, OD=3072
// Round 2: radix-4 FFT (padded split re/im smem, no bit-reversal via DIF fwd +
// mirrored DIT inverse), fused 2-order fftconv, double-buffered SGEMMs.
// ---------------------------------------------------------------------------

#define LSEQ 4096
#define NF   8192
#define DDIM 1024
#define ODIM 3072
#define BSZ  2
#define FFT_THREADS 512
#define PADI(i) ((i) + ((i) >> 5))
#define SM_HALF 8448            // 8192 + 256 padding
#define FFT_SMEM (2 * SM_HALF * 4)

// Scratch (device .bss — allocation-free)
__device__ float  g_res[(size_t)BSZ * ODIM * LSEQ];   // GEMM-in output [b,od,l]
__device__ float  g_cv [(size_t)BSZ * ODIM * LSEQ];   // conv3 output   [b,od,l]
__device__ float  g_v  [(size_t)BSZ * DDIM * LSEQ];   // final v        [b,d,l]
__device__ float  g_h  [(size_t)2   * DDIM * LSEQ];   // filter h       [n,d,l]
__device__ float2 g_Hf [(size_t)2   * DDIM * NF];     // DIF spectra of h
__device__ float2 g_tw [NF];                          // exp(-2pi i k/NF), k<NF

// ---------------------------------------------------------------------------
__global__ void twiddle_kernel() {
    int k = blockIdx.x * blockDim.x + threadIdx.x;
    if (k < NF) {
        double ang = -2.0 * 3.141592653589793238462643 * (double)k / (double)NF;
        g_tw[k] = make_float2((float)cos(ang), (float)sin(ang));
    }
}

// ---------------------------------------------------------------------------
// Filter MLP: per position l, compute h[n,d,l]
__global__ __launch_bounds__(256) void filter_kernel(
    const float* __restrict__ w1, const float* __restrict__ b1,
    const float* __restrict__ w2, const float* __restrict__ b2,
    const float* __restrict__ fb, const float* __restrict__ fd)
{
    __shared__ float pe[33];
    __shared__ float sact[64];
    const int l = blockIdx.x;
    const float t = (float)l * (1.0f / (float)(LSEQ - 1));
    const int tid = threadIdx.x;

    if (tid < 33) pe[tid] = sinf(t * (float)tid * 10.0f);
    __syncthreads();
    if (tid < 64) {
        float z = b1[tid];
        #pragma unroll
        for (int j = 0; j < 33; j++) z += pe[j] * w1[tid * 33 + j];
        sact[tid] = sinf(10.0f * z);
    }
    __syncthreads();

    for (int o = tid; o < 2 * DDIM; o += 256) {
        float acc = b2[o];
        #pragma unroll
        for (int i = 0; i < 64; i++) acc += sact[i] * w2[o * 64 + i];
        float dec = expf(-expf(fd[o]) * t);
        g_h[(size_t)o * LSEQ + l] = (acc * dec + fb[o]) * (1.0f / (float)LSEQ);
    }
}

// ---------------------------------------------------------------------------
// 8192-pt FFT in smem, 512 threads. Forward: radix-2 (span 4096) then 6
// radix-4 DIF stages (m = 1024..1). Output digit-reversed. Inverse mirrors
// with conjugate twiddles; 1/NF applied by caller.
__device__ __forceinline__ void fft_fwd(float* __restrict__ SR, float* __restrict__ SI) {
    // radix-2 stage, span 4096
    #pragma unroll
    for (int jj = 0; jj < 8; jj++) {
        int j  = threadIdx.x + jj * FFT_THREADS;
        int i0 = PADI(j), i1 = PADI(j + 4096);
        float ar = SR[i0], ai = SI[i0];
        float br = SR[i1], bi = SI[i1];
        float2 w = g_tw[j];
        SR[i0] = ar + br; SI[i0] = ai + bi;
        float dr = ar - br, di = ai - bi;
        SR[i1] = dr * w.x - di * w.y;
        SI[i1] = dr * w.y + di * w.x;
    }
    __syncthreads();
    // 6 radix-4 stages
    #pragma unroll
    for (int st = 0; st < 6; st++) {
        const int lm  = 10 - 2 * st;
        const int m   = 1 << lm;
        const int str = 2048 >> lm;
        #pragma unroll
        for (int jj = 0; jj < 4; jj++) {
            int t = threadIdx.x + jj * FFT_THREADS;
            int q = t & (m - 1);
            int base = ((t >> lm) << (lm + 2)) | q;
            int i0 = PADI(base), i1 = PADI(base + m),
                i2 = PADI(base + 2 * m), i3 = PADI(base + 3 * m);
            float x0r = SR[i0], x0i = SI[i0];
            float x1r = SR[i1], x1i = SI[i1];
            float x2r = SR[i2], x2i = SI[i2];
            float x3r = SR[i3], x3i = SI[i3];
            float2 w1 = g_tw[q * str];
            float2 w2 = g_tw[2 * q * str];
            float2 w3 = g_tw[3 * q * str];
            float t0r = x0r + x2r, t0i = x0i + x2i;
            float t1r = x1r + x3r, t1i = x1i + x3i;
            float t2r = x0r - x2r, t2i = x0i - x2i;
            float t3r = x1i - x3i, t3i = x3r - x1r;   // -i*(x1-x3)
            SR[i0] = t0r + t1r; SI[i0] = t0i + t1i;
            float ur = t2r + t3r, ui = t2i + t3i;
            SR[i1] = ur * w1.x - ui * w1.y; SI[i1] = ur * w1.y + ui * w1.x;
            ur = t0r - t1r; ui = t0i - t1i;
            SR[i2] = ur * w2.x - ui * w2.y; SI[i2] = ur * w2.y + ui * w2.x;
            ur = t2r - t3r; ui = t2i - t3i;
            SR[i3] = ur * w3.x - ui * w3.y; SI[i3] = ur * w3.y + ui * w3.x;
        }
        __syncthreads();
    }
}

__device__ __forceinline__ void fft_inv(float* __restrict__ SR, float* __restrict__ SI) {
    // 6 inverse radix-4 stages (m = 1..1024)
    #pragma unroll
    for (int st = 0; st < 6; st++) {
        const int lm  = 2 * st;
        const int m   = 1 << lm;
        const int str = 2048 >> lm;
        #pragma unroll
        for (int jj = 0; jj < 4; jj++) {
            int t = threadIdx.x + jj * FFT_THREADS;
            int q = t & (m - 1);
            int base = ((t >> lm) << (lm + 2)) | q;
            int i0 = PADI(base), i1 = PADI(base + m),
                i2 = PADI(base + 2 * m), i3 = PADI(base + 3 * m);
            float u0r = SR[i0], u0i = SI[i0];
            float u1r = SR[i1], u1i = SI[i1];
            float u2r = SR[i2], u2i = SI[i2];
            float u3r = SR[i3], u3i = SI[i3];
            float2 w1 = g_tw[q * str];
            float2 w2 = g_tw[2 * q * str];
            float2 w3 = g_tw[3 * q * str];
            // c = u * conj(w)
            float c1r = u1r * w1.x + u1i * w1.y, c1i = u1i * w1.x - u1r * w1.y;
            float c2r = u2r * w2.x + u2i * w2.y, c2i = u2i * w2.x - u2r * w2.y;
            float c3r = u3r * w3.x + u3i * w3.y, c3i = u3i * w3.x - u3r * w3.y;
            float s0r = u0r + c2r, s0i = u0i + c2i;
            float s1r = u0r - c2r, s1i = u0i - c2i;
            float s2r = c1r + c3r, s2i = c1i + c3i;
            float s3r = c1r - c3r, s3i = c1i - c3i;
            SR[i0] = s0r + s2r; SI[i0] = s0i + s2i;
            SR[i2] = s0r - s2r; SI[i2] = s0i - s2i;
            SR[i1] = s1r - s3i; SI[i1] = s1i + s3r;   // s1 + i*s3
            SR[i3] = s1r + s3i; SI[i3] = s1i - s3r;   // s1 - i*s3
        }
        __syncthreads();
    }
    // inverse radix-2 stage, span 4096
    #pragma unroll
    for (int jj = 0; jj < 8; jj++) {
        int j  = threadIdx.x + jj * FFT_THREADS;
        int i0 = PADI(j), i1 = PADI(j + 4096);
        float2 w = g_tw[j];
        float br = SR[i1], bi = SI[i1];
        float tr = br * w.x + bi * w.y;   // b * conj(w)
        float ti = bi * w.x - br * w.y;
        float ar = SR[i0], ai = SI[i0];
        SR[i0] = ar + tr; SI[i0] = ai + ti;
        SR[i1] = ar - tr; SI[i1] = ai - ti;
    }
    __syncthreads();
}

// Precompute H spectra (digit-reversed domain)
__global__ __launch_bounds__(FFT_THREADS) void hfft_kernel() {
    extern __shared__ float sm[];
    float* SR = sm;
    float* SI = sm + SM_HALF;
    const int c = blockIdx.x;                 // n*1024 + d
    const float* h = g_h + (size_t)c * LSEQ;
    for (int i = threadIdx.x; i < LSEQ; i += FFT_THREADS) {
        SR[PADI(i)] = h[i]; SI[PADI(i)] = 0.0f;
    }
    for (int i = LSEQ + threadIdx.x; i < NF; i += FFT_THREADS) {
        SR[PADI(i)] = 0.0f; SI[PADI(i)] = 0.0f;
    }
    __syncthreads();
    fft_fwd(SR, SI);
    float2* out = g_Hf + (size_t)c * NF;
    for (int i = threadIdx.x; i < NF; i += FFT_THREADS)
        out[i] = make_float2(SR[PADI(i)], SI[PADI(i)]);
}

// Fused both-order conv: v <- (irfft(fft(v)*H0)[:L])*x0; v <- (irfft(fft(v)*H1)[:L])*x1
__global__ __launch_bounds__(FFT_THREADS) void fftconv_kernel() {
    extern __shared__ float sm[];
    float* SR = sm;
    float* SI = sm + SM_HALF;
    const int c = blockIdx.x;
    const int b = c >> 10;
    const int d = c & 1023;
    const float inv = 1.0f / (float)NF;

    const float* v  = &g_cv[((size_t)(b * 3 + 2) * DDIM + d) * LSEQ];
    const float* x0 = &g_cv[((size_t)(b * 3 + 0) * DDIM + d) * LSEQ];
    const float* x1 = &g_cv[((size_t)(b * 3 + 1) * DDIM + d) * LSEQ];
    const float2* H0 = &g_Hf[(size_t)d * NF];
    const float2* H1 = &g_Hf[((size_t)DDIM + d) * NF];
    float* o = &g_v[((size_t)b * DDIM + d) * LSEQ];

    for (int i = threadIdx.x; i < LSEQ; i += FFT_THREADS) {
        SR[PADI(i)] = v[i]; SI[PADI(i)] = 0.0f;
    }
    for (int i = LSEQ + threadIdx.x; i < NF; i += FFT_THREADS) {
        SR[PADI(i)] = 0.0f; SI[PADI(i)] = 0.0f;
    }
    __syncthreads();

    // ---- order 0 ----
    fft_fwd(SR, SI);
    for (int i = threadIdx.x; i < NF; i += FFT_THREADS) {
        int ip = PADI(i);
        float2 hv = H0[i];
        float ar = SR[ip], ai = SI[ip];
        SR[ip] = ar * hv.x - ai * hv.y;
        SI[ip] = ar * hv.y + ai * hv.x;
    }
    __syncthreads();
    fft_inv(SR, SI);
    for (int l = threadIdx.x; l < LSEQ; l += FFT_THREADS) {
        int ip = PADI(l);
        SR[ip] = SR[ip] * inv * x0[l];
        SI[ip] = 0.0f;
    }
    for (int i = LSEQ + threadIdx.x; i < NF; i += FFT_THREADS) {
        SR[PADI(i)] = 0.0f; SI[PADI(i)] = 0.0f;
    }
    __syncthreads();

    // ---- order 1 ----
    fft_fwd(SR, SI);
    for (int i = threadIdx.x; i < NF; i += FFT_THREADS) {
        int ip = PADI(i);
        float2 hv = H1[i];
        float ar = SR[ip], ai = SI[ip];
        SR[ip] = ar * hv.x - ai * hv.y;
        SI[ip] = ar * hv.y + ai * hv.x;
    }
    __syncthreads();
    fft_inv(SR, SI);
    for (int l = threadIdx.x; l < LSEQ; l += FFT_THREADS)
        o[l] = SR[PADI(l)] * inv * x1[l];
}

// ---------------------------------------------------------------------------
// SGEMM 1 (double-buffered): g_res[b,od,l] = sum_d w_in[od,d]*u[b,l,d] + b_in[od]
#define BM 128
#define BN 128
#define BK 16

__global__ __launch_bounds__(256) void gemm_in_kernel(
    const float* __restrict__ W,    // [3072,1024] K-contig
    const float* __restrict__ U,    // [2,4096,1024] K-contig
    const float* __restrict__ bias) // [3072]
{
    __shared__ float As[2][BK][BM];
    __shared__ float Bs[2][BK][BN];
    const int b  = blockIdx.z;
    const int m0 = blockIdx.y * BM;     // od
    const int n0 = blockIdx.x * BN;     // l
    const float* Bm = U + (size_t)b * LSEQ * DDIM;
    float* C = g_res + (size_t)b * ODIM * LSEQ;

    const int tid  = threadIdx.x;
    const int tm   = tid >> 4;
    const int tn   = tid & 15;
    const int lrow = tid >> 1;
    const int lk   = (tid & 1) * 8;

    float acc[8][8];
    #pragma unroll
    for (int i = 0; i < 8; i++)
        #pragma unroll
        for (int j = 0; j < 8; j++) acc[i][j] = 0.0f;

    float4 a0 = *(const float4*)&W[(size_t)(m0 + lrow) * DDIM + lk];
    float4 a1 = *(const float4*)&W[(size_t)(m0 + lrow) * DDIM + lk + 4];
    float4 c0 = *(const float4*)&Bm[(size_t)(n0 + lrow) * DDIM + lk];
    float4 c1 = *(const float4*)&Bm[(size_t)(n0 + lrow) * DDIM + lk + 4];

    As[0][lk + 0][lrow] = a0.x; As[0][lk + 1][lrow] = a0.y;
    As[0][lk + 2][lrow] = a0.z; As[0][lk + 3][lrow] = a0.w;
    As[0][lk + 4][lrow] = a1.x; As[0][lk + 5][lrow] = a1.y;
    As[0][lk + 6][lrow] = a1.z; As[0][lk + 7][lrow] = a1.w;
    Bs[0][lk + 0][lrow] = c0.x; Bs[0][lk + 1][lrow] = c0.y;
    Bs[0][lk + 2][lrow] = c0.z; Bs[0][lk + 3][lrow] = c0.w;
    Bs[0][lk + 4][lrow] = c1.x; Bs[0][lk + 5][lrow] = c1.y;
    Bs[0][lk + 6][lrow] = c1.z; Bs[0][lk + 7][lrow] = c1.w;
    __syncthreads();

    int buf = 0;
    for (int k0 = 0; k0 < DDIM; k0 += BK) {
        const bool has_next = (k0 + BK) < DDIM;
        if (has_next) {
            a0 = *(const float4*)&W[(size_t)(m0 + lrow) * DDIM + k0 + BK + lk];
            a1 = *(const float4*)&W[(size_t)(m0 + lrow) * DDIM + k0 + BK + lk + 4];
            c0 = *(const float4*)&Bm[(size_t)(n0 + lrow) * DDIM + k0 + BK + lk];
            c1 = *(const float4*)&Bm[(size_t)(n0 + lrow) * DDIM + k0 + BK + lk + 4];
        }
        const float (*Ab)[BM] = As[buf];
        const float (*Bb)[BN] = Bs[buf];
        #pragma unroll
        for (int k = 0; k < BK; k++) {
            float4 ra0 = *(const float4*)&Ab[k][tm * 8];
            float4 ra1 = *(const float4*)&Ab[k][tm * 8 + 4];
            float4 rb0 = *(const float4*)&Bb[k][tn * 8];
            float4 rb1 = *(const float4*)&Bb[k][tn * 8 + 4];
            float ra[8] = {ra0.x, ra0.y, ra0.z, ra0.w, ra1.x, ra1.y, ra1.z, ra1.w};
            float rb[8] = {rb0.x, rb0.y, rb0.z, rb0.w, rb1.x, rb1.y, rb1.z, rb1.w};
            #pragma unroll
            for (int i = 0; i < 8; i++)
                #pragma unroll
                for (int j = 0; j < 8; j++) acc[i][j] += ra[i] * rb[j];
        }
        if (has_next) {
            int nb = buf ^ 1;
            As[nb][lk + 0][lrow] = a0.x; As[nb][lk + 1][lrow] = a0.y;
            As[nb][lk + 2][lrow] = a0.z; As[nb][lk + 3][lrow] = a0.w;
            As[nb][lk + 4][lrow] = a1.x; As[nb][lk + 5][lrow] = a1.y;
            As[nb][lk + 6][lrow] = a1.z; As[nb][lk + 7][lrow] = a1.w;
            Bs[nb][lk + 0][lrow] = c0.x; Bs[nb][lk + 1][lrow] = c0.y;
            Bs[nb][lk + 2][lrow] = c0.z; Bs[nb][lk + 3][lrow] = c0.w;
            Bs[nb][lk + 4][lrow] = c1.x; Bs[nb][lk + 5][lrow] = c1.y;
            Bs[nb][lk + 6][lrow] = c1.z; Bs[nb][lk + 7][lrow] = c1.w;
            __syncthreads();
            buf = nb;
        }
    }

    #pragma unroll
    for (int i = 0; i < 8; i++) {
        int m = m0 + tm * 8 + i;
        float bv = bias[m];
        float4 o0 = make_float4(acc[i][0] + bv, acc[i][1] + bv, acc[i][2] + bv, acc[i][3] + bv);
        float4 o1 = make_float4(acc[i][4] + bv, acc[i][5] + bv, acc[i][6] + bv, acc[i][7] + bv);
        *(float4*)&C[(size_t)m * LSEQ + n0 + tn * 8]     = o0;
        *(float4*)&C[(size_t)m * LSEQ + n0 + tn * 8 + 4] = o1;
    }
}

// ---------------------------------------------------------------------------
// Depthwise conv3 along l (+bias)
__global__ void conv3_kernel(const float* __restrict__ cw, const float* __restrict__ cb) {
    const int row = blockIdx.y;            // b*3072 + od
    const int od  = row % ODIM;
    const int l   = blockIdx.x * 256 + threadIdx.x;
    const float* r = g_res + (size_t)row * LSEQ;
    float left  = (l > 0)        ? r[l - 1] : 0.0f;
    float mid   = r[l];
    float right = (l < LSEQ - 1) ? r[l + 1] : 0.0f;
    float w0 = cw[od * 3], w1 = cw[od * 3 + 1], w2 = cw[od * 3 + 2];
    g_cv[(size_t)row * LSEQ + l] = w0 * left + w1 * mid + w2 * right + cb[od];
}

// ---------------------------------------------------------------------------
// SGEMM 2 (double-buffered): out[b,l,e] = sum_d g_v[b,d,l]*w_out[e,d] + b_out[e]
__global__ __launch_bounds__(256) void gemm_out_kernel(
    const float* __restrict__ Wo,    // [1024,1024] K-contig
    const float* __restrict__ bias,  // [1024]
    float* __restrict__ O)           // [2,4096,1024]
{
    __shared__ float As[2][BK][BM];
    __shared__ float Bs[2][BK][BN];
    const int b  = blockIdx.z;
    const int m0 = blockIdx.y * BM;     // l
    const int n0 = blockIdx.x * BN;     // e
    const float* Av = g_v + (size_t)b * DDIM * LSEQ;   // [d][l]
    float* C = O + (size_t)b * LSEQ * DDIM;

    const int tid  = threadIdx.x;
    const int tm   = tid >> 4;
    const int tn   = tid & 15;
    const int lak  = tid >> 4;          // k-row for A tile
    const int lam  = (tid & 15) * 8;    // m offset
    const int lrow = tid >> 1;
    const int lk   = (tid & 1) * 8;

    float acc[8][8];
    #pragma unroll
    for (int i = 0; i < 8; i++)
        #pragma unroll
        for (int j = 0; j < 8; j++) acc[i][j] = 0.0f;

    float4 a0 = *(const float4*)&Av[(size_t)lak * LSEQ + m0 + lam];
    float4 a1 = *(const float4*)&Av[(size_t)lak * LSEQ + m0 + lam + 4];
    float4 c0 = *(const float4*)&Wo[(size_t)(n0 + lrow) * DDIM + lk];
    float4 c1 = *(const float4*)&Wo[(size_t)(n0 + lrow) * DDIM + lk + 4];
    *(float4*)&As[0][lak][lam]     = a0;
    *(float4*)&As[0][lak][lam + 4] = a1;
    Bs[0][lk + 0][lrow] = c0.x; Bs[0][lk + 1][lrow] = c0.y;
    Bs[0][lk + 2][lrow] = c0.z; Bs[0][lk + 3][lrow] = c0.w;
    Bs[0][lk + 4][lrow] = c1.x; Bs[0][lk + 5][lrow] = c1.y;
    Bs[0][lk + 6][lrow] = c1.z; Bs[0][lk + 7][lrow] = c1.w;
    __syncthreads();

    int buf = 0;
    for (int k0 = 0; k0 < DDIM; k0 += BK) {
        const bool has_next = (k0 + BK) < DDIM;
        if (has_next) {
            a0 = *(const float4*)&Av[(size_t)(k0 + BK + lak) * LSEQ + m0 + lam];
            a1 = *(const float4*)&Av[(size_t)(k0 + BK + lak) * LSEQ + m0 + lam + 4];
            c0 = *(const float4*)&Wo[(size_t)(n0 + lrow) * DDIM + k0 + BK + lk];
            c1 = *(const float4*)&Wo[(size_t)(n0 + lrow) * DDIM + k0 + BK + lk + 4];
        }
        const float (*Ab)[BM] = As[buf];
        const float (*Bb)[BN] = Bs[buf];
        #pragma unroll
        for (int k = 0; k < BK; k++) {
            float4 ra0 = *(const float4*)&Ab[k][tm * 8];
            float4 ra1 = *(const float4*)&Ab[k][tm * 8 + 4];
            float4 rb0 = *(const float4*)&Bb[k][tn * 8];
            float4 rb1 = *(const float4*)&Bb[k][tn * 8 + 4];
            float ra[8] = {ra0.x, ra0.y, ra0.z, ra0.w, ra1.x, ra1.y, ra1.z, ra1.w};
            float rb[8] = {rb0.x, rb0.y, rb0.z, rb0.w, rb1.x, rb1.y, rb1.z, rb1.w};
            #pragma unroll
            for (int i = 0; i < 8; i++)
                #pragma unroll
                for (int j = 0; j < 8; j++) acc[i][j] += ra[i] * rb[j];
        }
        if (has_next) {
            int nb = buf ^ 1;
            *(float4*)&As[nb][lak][lam]     = a0;
            *(float4*)&As[nb][lak][lam + 4] = a1;
            Bs[nb][lk + 0][lrow] = c0.x; Bs[nb][lk + 1][lrow] = c0.y;
            Bs[nb][lk + 2][lrow] = c0.z; Bs[nb][lk + 3][lrow] = c0.w;
            Bs[nb][lk + 4][lrow] = c1.x; Bs[nb][lk + 5][lrow] = c1.y;
            Bs[nb][lk + 6][lrow] = c1.z; Bs[nb][lk + 7][lrow] = c1.w;
            __syncthreads();
            buf = nb;
        }
    }

    float bb[8];
    #pragma unroll
    for (int j = 0; j < 8; j++) bb[j] = bias[n0 + tn * 8 + j];

    #pragma unroll
    for (int i = 0; i < 8; i++) {
        int m = m0 + tm * 8 + i;
        float4 o0 = make_float4(acc[i][0] + bb[0], acc[i][1] + bb[1],
                                acc[i][2] + bb[2], acc[i][3] + bb[3]);
        float4 o1 = make_float4(acc[i][4] + bb[4], acc[i][5] + bb[5],
                                acc[i][6] + bb[6], acc[i][7] + bb[7]);
        *(float4*)&C[(size_t)m * DDIM + n0 + tn * 8]     = o0;
        *(float4*)&C[(size_t)m * DDIM + n0 + tn * 8 + 4] = o1;
    }
}

// ---------------------------------------------------------------------------
extern "C" void kernel_launch(void* const* d_in, const int* in_sizes, int n_in,
                              void* d_out, int out_size)
{
    const float* u          = (const float*)d_in[0];
    const float* w_in       = (const float*)d_in[1];
    const float* b_in       = (const float*)d_in[2];
    const float* conv_w     = (const float*)d_in[3];
    const float* conv_b     = (const float*)d_in[4];
    const float* w1         = (const float*)d_in[5];
    const float* b1         = (const float*)d_in[6];
    const float* w2         = (const float*)d_in[7];
    const float* b2         = (const float*)d_in[8];
    const float* filt_bias  = (const float*)d_in[9];
    const float* filt_decay = (const float*)d_in[10];
    const float* w_out      = (const float*)d_in[11];
    const float* b_out      = (const float*)d_in[12];
    float* out = (float*)d_out;

    static bool attr_set = false;
    if (!attr_set) {
        cudaFuncSetAttribute(hfft_kernel,    cudaFuncAttributeMaxDynamicSharedMemorySize, FFT_SMEM);
        cudaFuncSetAttribute(fftconv_kernel, cudaFuncAttributeMaxDynamicSharedMemorySize, FFT_SMEM);
        attr_set = true;
    }

    // Filter path (independent of u)
    twiddle_kernel<<<32, 256>>>();
    filter_kernel<<<LSEQ, 256>>>(w1, b1, w2, b2, filt_bias, filt_decay);
    hfft_kernel<<<2 * DDIM, FFT_THREADS, FFT_SMEM>>>();

    // Main path
    gemm_in_kernel<<<dim3(LSEQ / BN, ODIM / BM, BSZ), 256>>>(w_in, u, b_in);
    conv3_kernel<<<dim3(LSEQ / 256, BSZ * ODIM), 256>>>(conv_w, conv_b);

    fftconv_kernel<<<BSZ * DDIM, FFT_THREADS, FFT_SMEM>>>();

    gemm_out_kernel<<<dim3(DDIM / BN, LSEQ / BM, BSZ), 256>>>(w_out, b_out, out);
}

// round 3
// speedup vs baseline: 1.1857x; 1.1227x over previous
#include <cuda_runtime.h>
#include <cuda_bf16.h>
#include <cstdint>
#include <cstddef>

// ---------------------------------------------------------------------------
// Hyena operator: B=2, L=4096, D=1024, ORDER=2, OD=3072
// Round 3: real-pair-packed FFT conv (2 channels per complex FFT, reflection
// table in digit-reversed domain), zero-pad-specialized forward stage,
// half-output inverse stage. GEMMs unchanged from R2.
// ---------------------------------------------------------------------------

#define LSEQ 4096
#define NF   8192
#define DDIM 1024
#define ODIM 3072
#define BSZ  2
#define NPAIR 512
#define FFT_THREADS 512
#define PADI(i) ((i) + ((i) >> 5))
#define SM_HALF 8448            // 8192 + 256 padding
#define FFT_SMEM (2 * SM_HALF * 4)

// Scratch (device .bss — allocation-free)
__device__ float  g_res[(size_t)BSZ * ODIM * LSEQ];   // GEMM-in output [b,od,l]
__device__ float  g_cv [(size_t)BSZ * ODIM * LSEQ];   // conv3 output   [b,od,l]
__device__ float  g_v  [(size_t)BSZ * DDIM * LSEQ];   // final v        [b,d,l]
__device__ float  g_h  [(size_t)2   * DDIM * LSEQ];   // filter h       [n,d,l]
__device__ float2 g_A  [(size_t)2 * NPAIR * NF];      // (G0+G1)/2 per pair
__device__ float2 g_B  [(size_t)2 * NPAIR * NF];      // (G0-G1)/2 per pair
__device__ float2 g_tw [NF];                          // exp(-2pi i k/NF)
__device__ unsigned short g_refl[NF];                 // slot of N-k given slot of k

// ---------------------------------------------------------------------------
// digit-reversed slot <-> frequency maps for this specific DIF ordering:
// p12=k0, p11=k2, p10=k1, p9=k4, p8=k3, p7=k6, p6=k5,
// p5=k8, p4=k7, p3=k10, p2=k9, p1=k12, p0=k11
__device__ __forceinline__ int slot_to_freq(int p) {
    int k = 0;
    k |= ((p >> 12) & 1) << 0;
    k |= ((p >> 10) & 1) << 1;
    k |= ((p >> 11) & 1) << 2;
    k |= ((p >>  8) & 1) << 3;
    k |= ((p >>  9) & 1) << 4;
    k |= ((p >>  6) & 1) << 5;
    k |= ((p >>  7) & 1) << 6;
    k |= ((p >>  4) & 1) << 7;
    k |= ((p >>  5) & 1) << 8;
    k |= ((p >>  2) & 1) << 9;
    k |= ((p >>  3) & 1) << 10;
    k |= ((p >>  0) & 1) << 11;
    k |= ((p >>  1) & 1) << 12;
    return k;
}
__device__ __forceinline__ int freq_to_slot(int k) {
    int p = 0;
    p |= ((k >>  0) & 1) << 12;
    p |= ((k >>  1) & 1) << 10;
    p |= ((k >>  2) & 1) << 11;
    p |= ((k >>  3) & 1) << 8;
    p |= ((k >>  4) & 1) << 9;
    p |= ((k >>  5) & 1) << 6;
    p |= ((k >>  6) & 1) << 7;
    p |= ((k >>  7) & 1) << 4;
    p |= ((k >>  8) & 1) << 5;
    p |= ((k >>  9) & 1) << 2;
    p |= ((k >> 10) & 1) << 3;
    p |= ((k >> 11) & 1) << 0;
    p |= ((k >> 12) & 1) << 1;
    return p;
}

__global__ void init_kernel() {
    int i = blockIdx.x * blockDim.x + threadIdx.x;
    if (i < NF) {
        double ang = -2.0 * 3.141592653589793238462643 * (double)i / (double)NF;
        g_tw[i] = make_float2((float)cos(ang), (float)sin(ang));
        int k  = slot_to_freq(i);
        int kp = (NF - k) & (NF - 1);
        g_refl[i] = (unsigned short)freq_to_slot(kp);
    }
}

// ---------------------------------------------------------------------------
// Filter MLP: per position l, compute h[n,d,l]
__global__ __launch_bounds__(256) void filter_kernel(
    const float* __restrict__ w1, const float* __restrict__ b1,
    const float* __restrict__ w2, const float* __restrict__ b2,
    const float* __restrict__ fb, const float* __restrict__ fd)
{
    __shared__ float pe[33];
    __shared__ float sact[64];
    const int l = blockIdx.x;
    const float t = (float)l * (1.0f / (float)(LSEQ - 1));
    const int tid = threadIdx.x;

    if (tid < 33) pe[tid] = sinf(t * (float)tid * 10.0f);
    __syncthreads();
    if (tid < 64) {
        float z = b1[tid];
        #pragma unroll
        for (int j = 0; j < 33; j++) z += pe[j] * w1[tid * 33 + j];
        sact[tid] = sinf(10.0f * z);
    }
    __syncthreads();

    for (int o = tid; o < 2 * DDIM; o += 256) {
        float acc = b2[o];
        #pragma unroll
        for (int i = 0; i < 64; i++) acc += sact[i] * w2[o * 64 + i];
        float dec = expf(-expf(fd[o]) * t);
        g_h[(size_t)o * LSEQ + l] = (acc * dec + fb[o]) * (1.0f / (float)LSEQ);
    }
}

// ---------------------------------------------------------------------------
// FFT pieces (8192-pt, 512 threads, split re/im padded smem)

// Forward with zero-padded upper half: radix-2 first stage reads lower only.
__device__ __forceinline__ void fft_fwd_zp(float* __restrict__ SR, float* __restrict__ SI) {
    #pragma unroll
    for (int jj = 0; jj < 8; jj++) {
        int j  = threadIdx.x + jj * FFT_THREADS;
        int i0 = PADI(j), i1 = PADI(j + 4096);
        float ar = SR[i0], ai = SI[i0];
        float2 w = g_tw[j];
        SR[i1] = ar * w.x - ai * w.y;
        SI[i1] = ar * w.y + ai * w.x;
        // S[i0] = a (already in place)
    }
    __syncthreads();
    #pragma unroll
    for (int st = 0; st < 6; st++) {
        const int lm  = 10 - 2 * st;
        const int m   = 1 << lm;
        const int str = 2048 >> lm;
        #pragma unroll
        for (int jj = 0; jj < 4; jj++) {
            int t = threadIdx.x + jj * FFT_THREADS;
            int q = t & (m - 1);
            int base = ((t >> lm) << (lm + 2)) | q;
            int i0 = PADI(base), i1 = PADI(base + m),
                i2 = PADI(base + 2 * m), i3 = PADI(base + 3 * m);
            float x0r = SR[i0], x0i = SI[i0];
            float x1r = SR[i1], x1i = SI[i1];
            float x2r = SR[i2], x2i = SI[i2];
            float x3r = SR[i3], x3i = SI[i3];
            float2 w1 = g_tw[q * str];
            float2 w2 = g_tw[2 * q * str];
            float2 w3 = g_tw[3 * q * str];
            float t0r = x0r + x2r, t0i = x0i + x2i;
            float t1r = x1r + x3r, t1i = x1i + x3i;
            float t2r = x0r - x2r, t2i = x0i - x2i;
            float t3r = x1i - x3i, t3i = x3r - x1r;   // -i*(x1-x3)
            SR[i0] = t0r + t1r; SI[i0] = t0i + t1i;
            float ur = t2r + t3r, ui = t2i + t3i;
            SR[i1] = ur * w1.x - ui * w1.y; SI[i1] = ur * w1.y + ui * w1.x;
            ur = t0r - t1r; ui = t0i - t1i;
            SR[i2] = ur * w2.x - ui * w2.y; SI[i2] = ur * w2.y + ui * w2.x;
            ur = t2r - t3r; ui = t2i - t3i;
            SR[i3] = ur * w3.x - ui * w3.y; SI[i3] = ur * w3.y + ui * w3.x;
        }
        __syncthreads();
    }
}

// Inverse, computing only the lower 4096 time-domain outputs in last stage.
__device__ __forceinline__ void fft_inv_half(float* __restrict__ SR, float* __restrict__ SI) {
    #pragma unroll
    for (int st = 0; st < 6; st++) {
        const int lm  = 2 * st;
        const int m   = 1 << lm;
        const int str = 2048 >> lm;
        #pragma unroll
        for (int jj = 0; jj < 4; jj++) {
            int t = threadIdx.x + jj * FFT_THREADS;
            int q = t & (m - 1);
            int base = ((t >> lm) << (lm + 2)) | q;
            int i0 = PADI(base), i1 = PADI(base + m),
                i2 = PADI(base + 2 * m), i3 = PADI(base + 3 * m);
            float u0r = SR[i0], u0i = SI[i0];
            float u1r = SR[i1], u1i = SI[i1];
            float u2r = SR[i2], u2i = SI[i2];
            float u3r = SR[i3], u3i = SI[i3];
            float2 w1 = g_tw[q * str];
            float2 w2 = g_tw[2 * q * str];
            float2 w3 = g_tw[3 * q * str];
            float c1r = u1r * w1.x + u1i * w1.y, c1i = u1i * w1.x - u1r * w1.y;
            float c2r = u2r * w2.x + u2i * w2.y, c2i = u2i * w2.x - u2r * w2.y;
            float c3r = u3r * w3.x + u3i * w3.y, c3i = u3i * w3.x - u3r * w3.y;
            float s0r = u0r + c2r, s0i = u0i + c2i;
            float s1r = u0r - c2r, s1i = u0i - c2i;
            float s2r = c1r + c3r, s2i = c1i + c3i;
            float s3r = c1r - c3r, s3i = c1i - c3i;
            SR[i0] = s0r + s2r; SI[i0] = s0i + s2i;
            SR[i2] = s0r - s2r; SI[i2] = s0i - s2i;
            SR[i1] = s1r - s3i; SI[i1] = s1i + s3r;
            SR[i3] = s1r + s3i; SI[i3] = s1i - s3r;
        }
        __syncthreads();
    }
    // final radix-2: only lower outputs needed
    #pragma unroll
    for (int jj = 0; jj < 8; jj++) {
        int j  = threadIdx.x + jj * FFT_THREADS;
        int i0 = PADI(j), i1 = PADI(j + 4096);
        float2 w = g_tw[j];
        float br = SR[i1], bi = SI[i1];
        float tr = br * w.x + bi * w.y;
        float ti = bi * w.x - br * w.y;
        SR[i0] += tr; SI[i0] += ti;
    }
    __syncthreads();
}

// ---------------------------------------------------------------------------
// Paired H spectra -> A/B tables. One CTA per (order n, channel pair).
__global__ __launch_bounds__(FFT_THREADS) void hfft_kernel() {
    extern __shared__ float sm[];
    float* SR = sm;
    float* SI = sm + SM_HALF;
    const int c = blockIdx.x;              // n*512 + dpair
    const int n = c >> 9;
    const int dpair = c & (NPAIR - 1);
    const float* h0 = g_h + ((size_t)n * DDIM + 2 * dpair)     * LSEQ;
    const float* h1 = g_h + ((size_t)n * DDIM + 2 * dpair + 1) * LSEQ;

    for (int i = threadIdx.x; i < LSEQ; i += FFT_THREADS) {
        SR[PADI(i)] = h0[i]; SI[PADI(i)] = h1[i];
    }
    __syncthreads();
    fft_fwd_zp(SR, SI);

    float2* Ao = g_A + (size_t)c * NF;
    float2* Bo = g_B + (size_t)c * NF;
    for (int p = threadIdx.x; p < NF; p += FFT_THREADS) {
        int q = g_refl[p];
        float zpr = SR[PADI(p)], zpi = SI[PADI(p)];
        float zqr = SR[PADI(q)], zqi = SI[PADI(q)];
        // G0 = (Zp + conj(Zq))/2 ; G1 = (Zp - conj(Zq)) * (-i/2)
        float g0r = 0.5f * (zpr + zqr), g0i = 0.5f * (zpi - zqi);
        float g1r = 0.5f * (zpi + zqi), g1i = 0.5f * (zqr - zpr);
        Ao[p] = make_float2(0.5f * (g0r + g1r), 0.5f * (g0i + g1i));
        Bo[p] = make_float2(0.5f * (g0r - g1r), 0.5f * (g0i - g1i));
    }
}

// ---------------------------------------------------------------------------
// Paired fftconv: one CTA per (b, channel-pair); both orders chained.
__global__ __launch_bounds__(FFT_THREADS) void fftconv_kernel() {
    extern __shared__ float sm[];
    float* SR = sm;
    float* SI = sm + SM_HALF;
    const int c = blockIdx.x;              // b*512 + dpair
    const int b = c >> 9;
    const int dpair = c & (NPAIR - 1);
    const int ch0 = 2 * dpair, ch1 = ch0 + 1;
    const float inv = 1.0f / (float)NF;

    const float* v0 = &g_cv[((size_t)(b * 3 + 2) * DDIM + ch0) * LSEQ];
    const float* v1 = &g_cv[((size_t)(b * 3 + 2) * DDIM + ch1) * LSEQ];

    for (int i = threadIdx.x; i < LSEQ; i += FFT_THREADS) {
        SR[PADI(i)] = v0[i]; SI[PADI(i)] = v1[i];
    }
    __syncthreads();

    #pragma unroll 1
    for (int n = 0; n < 2; n++) {
        fft_fwd_zp(SR, SI);

        const float2* Ap = g_A + ((size_t)n * NPAIR + dpair) * NF;
        const float2* Bp = g_B + ((size_t)n * NPAIR + dpair) * NF;
        // spectrum combine: pairs (p, q=refl[p]) are disjoint -> in-place safe
        #pragma unroll
        for (int jj = 0; jj < 16; jj++) {
            int p = threadIdx.x + jj * FFT_THREADS;
            int q = g_refl[p];
            if (q < p) continue;
            int ip = PADI(p), iq = PADI(q);
            float zr = SR[ip], zi = SI[ip];
            float wr = SR[iq], wi = SI[iq];
            float2 a  = Ap[p];
            float2 bb = Bp[p];
            // Y[p] = a*z + b*conj(w)
            float ypr = a.x * zr - a.y * zi + bb.x * wr + bb.y * wi;
            float ypi = a.x * zi + a.y * zr + bb.y * wr - bb.x * wi;
            // Y[q] = conj(a)*w + conj(b)*conj(z)
            float yqr = a.x * wr + a.y * wi + bb.x * zr - bb.y * zi;
            float yqi = a.x * wi - a.y * wr - bb.x * zi - bb.y * zr;
            SR[ip] = ypr; SI[ip] = ypi;
            SR[iq] = yqr; SI[iq] = yqi;
        }
        __syncthreads();

        fft_inv_half(SR, SI);

        if (n == 0) {
            const float* xa = &g_cv[((size_t)(b * 3 + 0) * DDIM + ch0) * LSEQ];
            const float* xb = &g_cv[((size_t)(b * 3 + 0) * DDIM + ch1) * LSEQ];
            for (int l = threadIdx.x; l < LSEQ; l += FFT_THREADS) {
                int ip = PADI(l);
                SR[ip] = SR[ip] * inv * xa[l];
                SI[ip] = SI[ip] * inv * xb[l];
            }
            __syncthreads();
        } else {
            const float* xa = &g_cv[((size_t)(b * 3 + 1) * DDIM + ch0) * LSEQ];
            const float* xb = &g_cv[((size_t)(b * 3 + 1) * DDIM + ch1) * LSEQ];
            float* o0 = &g_v[((size_t)b * DDIM + ch0) * LSEQ];
            float* o1 = &g_v[((size_t)b * DDIM + ch1) * LSEQ];
            for (int l = threadIdx.x; l < LSEQ; l += FFT_THREADS) {
                int ip = PADI(l);
                o0[l] = SR[ip] * inv * xa[l];
                o1[l] = SI[ip] * inv * xb[l];
            }
        }
    }
}

// ---------------------------------------------------------------------------
// SGEMM 1 (double-buffered): g_res[b,od,l] = sum_d w_in[od,d]*u[b,l,d] + b_in[od]
#define BM 128
#define BN 128
#define BK 16

__global__ __launch_bounds__(256) void gemm_in_kernel(
    const float* __restrict__ W,    // [3072,1024] K-contig
    const float* __restrict__ U,    // [2,4096,1024] K-contig
    const float* __restrict__ bias) // [3072]
{
    __shared__ float As[2][BK][BM];
    __shared__ float Bs[2][BK][BN];
    const int b  = blockIdx.z;
    const int m0 = blockIdx.y * BM;     // od
    const int n0 = blockIdx.x * BN;     // l
    const float* Bm = U + (size_t)b * LSEQ * DDIM;
    float* C = g_res + (size_t)b * ODIM * LSEQ;

    const int tid  = threadIdx.x;
    const int tm   = tid >> 4;
    const int tn   = tid & 15;
    const int lrow = tid >> 1;
    const int lk   = (tid & 1) * 8;

    float acc[8][8];
    #pragma unroll
    for (int i = 0; i < 8; i++)
        #pragma unroll
        for (int j = 0; j < 8; j++) acc[i][j] = 0.0f;

    float4 a0 = *(const float4*)&W[(size_t)(m0 + lrow) * DDIM + lk];
    float4 a1 = *(const float4*)&W[(size_t)(m0 + lrow) * DDIM + lk + 4];
    float4 c0 = *(const float4*)&Bm[(size_t)(n0 + lrow) * DDIM + lk];
    float4 c1 = *(const float4*)&Bm[(size_t)(n0 + lrow) * DDIM + lk + 4];

    As[0][lk + 0][lrow] = a0.x; As[0][lk + 1][lrow] = a0.y;
    As[0][lk + 2][lrow] = a0.z; As[0][lk + 3][lrow] = a0.w;
    As[0][lk + 4][lrow] = a1.x; As[0][lk + 5][lrow] = a1.y;
    As[0][lk + 6][lrow] = a1.z; As[0][lk + 7][lrow] = a1.w;
    Bs[0][lk + 0][lrow] = c0.x; Bs[0][lk + 1][lrow] = c0.y;
    Bs[0][lk + 2][lrow] = c0.z; Bs[0][lk + 3][lrow] = c0.w;
    Bs[0][lk + 4][lrow] = c1.x; Bs[0][lk + 5][lrow] = c1.y;
    Bs[0][lk + 6][lrow] = c1.z; Bs[0][lk + 7][lrow] = c1.w;
    __syncthreads();

    int buf = 0;
    for (int k0 = 0; k0 < DDIM; k0 += BK) {
        const bool has_next = (k0 + BK) < DDIM;
        if (has_next) {
            a0 = *(const float4*)&W[(size_t)(m0 + lrow) * DDIM + k0 + BK + lk];
            a1 = *(const float4*)&W[(size_t)(m0 + lrow) * DDIM + k0 + BK + lk + 4];
            c0 = *(const float4*)&Bm[(size_t)(n0 + lrow) * DDIM + k0 + BK + lk];
            c1 = *(const float4*)&Bm[(size_t)(n0 + lrow) * DDIM + k0 + BK + lk + 4];
        }
        const float (*Ab)[BM] = As[buf];
        const float (*Bb)[BN] = Bs[buf];
        #pragma unroll
        for (int k = 0; k < BK; k++) {
            float4 ra0 = *(const float4*)&Ab[k][tm * 8];
            float4 ra1 = *(const float4*)&Ab[k][tm * 8 + 4];
            float4 rb0 = *(const float4*)&Bb[k][tn * 8];
            float4 rb1 = *(const float4*)&Bb[k][tn * 8 + 4];
            float ra[8] = {ra0.x, ra0.y, ra0.z, ra0.w, ra1.x, ra1.y, ra1.z, ra1.w};
            float rb[8] = {rb0.x, rb0.y, rb0.z, rb0.w, rb1.x, rb1.y, rb1.z, rb1.w};
            #pragma unroll
            for (int i = 0; i < 8; i++)
                #pragma unroll
                for (int j = 0; j < 8; j++) acc[i][j] += ra[i] * rb[j];
        }
        if (has_next) {
            int nb = buf ^ 1;
            As[nb][lk + 0][lrow] = a0.x; As[nb][lk + 1][lrow] = a0.y;
            As[nb][lk + 2][lrow] = a0.z; As[nb][lk + 3][lrow] = a0.w;
            As[nb][lk + 4][lrow] = a1.x; As[nb][lk + 5][lrow] = a1.y;
            As[nb][lk + 6][lrow] = a1.z; As[nb][lk + 7][lrow] = a1.w;
            Bs[nb][lk + 0][lrow] = c0.x; Bs[nb][lk + 1][lrow] = c0.y;
            Bs[nb][lk + 2][lrow] = c0.z; Bs[nb][lk + 3][lrow] = c0.w;
            Bs[nb][lk + 4][lrow] = c1.x; Bs[nb][lk + 5][lrow] = c1.y;
            Bs[nb][lk + 6][lrow] = c1.z; Bs[nb][lk + 7][lrow] = c1.w;
            __syncthreads();
            buf = nb;
        }
    }

    #pragma unroll
    for (int i = 0; i < 8; i++) {
        int m = m0 + tm * 8 + i;
        float bv = bias[m];
        float4 o0 = make_float4(acc[i][0] + bv, acc[i][1] + bv, acc[i][2] + bv, acc[i][3] + bv);
        float4 o1 = make_float4(acc[i][4] + bv, acc[i][5] + bv, acc[i][6] + bv, acc[i][7] + bv);
        *(float4*)&C[(size_t)m * LSEQ + n0 + tn * 8]     = o0;
        *(float4*)&C[(size_t)m * LSEQ + n0 + tn * 8 + 4] = o1;
    }
}

// ---------------------------------------------------------------------------
// Depthwise conv3 along l (+bias)
__global__ void conv3_kernel(const float* __restrict__ cw, const float* __restrict__ cb) {
    const int row = blockIdx.y;            // b*3072 + od
    const int od  = row % ODIM;
    const int l   = blockIdx.x * 256 + threadIdx.x;
    const float* r = g_res + (size_t)row * LSEQ;
    float left  = (l > 0)        ? r[l - 1] : 0.0f;
    float mid   = r[l];
    float right = (l < LSEQ - 1) ? r[l + 1] : 0.0f;
    float w0 = cw[od * 3], w1 = cw[od * 3 + 1], w2 = cw[od * 3 + 2];
    g_cv[(size_t)row * LSEQ + l] = w0 * left + w1 * mid + w2 * right + cb[od];
}

// ---------------------------------------------------------------------------
// SGEMM 2 (double-buffered): out[b,l,e] = sum_d g_v[b,d,l]*w_out[e,d] + b_out[e]
__global__ __launch_bounds__(256) void gemm_out_kernel(
    const float* __restrict__ Wo,    // [1024,1024] K-contig
    const float* __restrict__ bias,  // [1024]
    float* __restrict__ O)           // [2,4096,1024]
{
    __shared__ float As[2][BK][BM];
    __shared__ float Bs[2][BK][BN];
    const int b  = blockIdx.z;
    const int m0 = blockIdx.y * BM;     // l
    const int n0 = blockIdx.x * BN;     // e
    const float* Av = g_v + (size_t)b * DDIM * LSEQ;   // [d][l]
    float* C = O + (size_t)b * LSEQ * DDIM;

    const int tid  = threadIdx.x;
    const int tm   = tid >> 4;
    const int tn   = tid & 15;
    const int lak  = tid >> 4;
    const int lam  = (tid & 15) * 8;
    const int lrow = tid >> 1;
    const int lk   = (tid & 1) * 8;

    float acc[8][8];
    #pragma unroll
    for (int i = 0; i < 8; i++)
        #pragma unroll
        for (int j = 0; j < 8; j++) acc[i][j] = 0.0f;

    float4 a0 = *(const float4*)&Av[(size_t)lak * LSEQ + m0 + lam];
    float4 a1 = *(const float4*)&Av[(size_t)lak * LSEQ + m0 + lam + 4];
    float4 c0 = *(const float4*)&Wo[(size_t)(n0 + lrow) * DDIM + lk];
    float4 c1 = *(const float4*)&Wo[(size_t)(n0 + lrow) * DDIM + lk + 4];
    *(float4*)&As[0][lak][lam]     = a0;
    *(float4*)&As[0][lak][lam + 4] = a1;
    Bs[0][lk + 0][lrow] = c0.x; Bs[0][lk + 1][lrow] = c0.y;
    Bs[0][lk + 2][lrow] = c0.z; Bs[0][lk + 3][lrow] = c0.w;
    Bs[0][lk + 4][lrow] = c1.x; Bs[0][lk + 5][lrow] = c1.y;
    Bs[0][lk + 6][lrow] = c1.z; Bs[0][lk + 7][lrow] = c1.w;
    __syncthreads();

    int buf = 0;
    for (int k0 = 0; k0 < DDIM; k0 += BK) {
        const bool has_next = (k0 + BK) < DDIM;
        if (has_next) {
            a0 = *(const float4*)&Av[(size_t)(k0 + BK + lak) * LSEQ + m0 + lam];
            a1 = *(const float4*)&Av[(size_t)(k0 + BK + lak) * LSEQ + m0 + lam + 4];
            c0 = *(const float4*)&Wo[(size_t)(n0 + lrow) * DDIM + k0 + BK + lk];
            c1 = *(const float4*)&Wo[(size_t)(n0 + lrow) * DDIM + k0 + BK + lk + 4];
        }
        const float (*Ab)[BM] = As[buf];
        const float (*Bb)[BN] = Bs[buf];
        #pragma unroll
        for (int k = 0; k < BK; k++) {
            float4 ra0 = *(const float4*)&Ab[k][tm * 8];
            float4 ra1 = *(const float4*)&Ab[k][tm * 8 + 4];
            float4 rb0 = *(const float4*)&Bb[k][tn * 8];
            float4 rb1 = *(const float4*)&Bb[k][tn * 8 + 4];
            float ra[8] = {ra0.x, ra0.y, ra0.z, ra0.w, ra1.x, ra1.y, ra1.z, ra1.w};
            float rb[8] = {rb0.x, rb0.y, rb0.z, rb0.w, rb1.x, rb1.y, rb1.z, rb1.w};
            #pragma unroll
            for (int i = 0; i < 8; i++)
                #pragma unroll
                for (int j = 0; j < 8; j++) acc[i][j] += ra[i] * rb[j];
        }
        if (has_next) {
            int nb = buf ^ 1;
            *(float4*)&As[nb][lak][lam]     = a0;
            *(float4*)&As[nb][lak][lam + 4] = a1;
            Bs[nb][lk + 0][lrow] = c0.x; Bs[nb][lk + 1][lrow] = c0.y;
            Bs[nb][lk + 2][lrow] = c0.z; Bs[nb][lk + 3][lrow] = c0.w;
            Bs[nb][lk + 4][lrow] = c1.x; Bs[nb][lk + 5][lrow] = c1.y;
            Bs[nb][lk + 6][lrow] = c1.z; Bs[nb][lk + 7][lrow] = c1.w;
            __syncthreads();
            buf = nb;
        }
    }

    float bb[8];
    #pragma unroll
    for (int j = 0; j < 8; j++) bb[j] = bias[n0 + tn * 8 + j];

    #pragma unroll
    for (int i = 0; i < 8; i++) {
        int m = m0 + tm * 8 + i;
        float4 o0 = make_float4(acc[i][0] + bb[0], acc[i][1] + bb[1],
                                acc[i][2] + bb[2], acc[i][3] + bb[3]);
        float4 o1 = make_float4(acc[i][4] + bb[4], acc[i][5] + bb[5],
                                acc[i][6] + bb[6], acc[i][7] + bb[7]);
        *(float4*)&C[(size_t)m * DDIM + n0 + tn * 8]     = o0;
        *(float4*)&C[(size_t)m * DDIM + n0 + tn * 8 + 4] = o1;
    }
}

// ---------------------------------------------------------------------------
extern "C" void kernel_launch(void* const* d_in, const int* in_sizes, int n_in,
                              void* d_out, int out_size)
{
    const float* u          = (const float*)d_in[0];
    const float* w_in       = (const float*)d_in[1];
    const float* b_in       = (const float*)d_in[2];
    const float* conv_w     = (const float*)d_in[3];
    const float* conv_b     = (const float*)d_in[4];
    const float* w1         = (const float*)d_in[5];
    const float* b1         = (const float*)d_in[6];
    const float* w2         = (const float*)d_in[7];
    const float* b2         = (const float*)d_in[8];
    const float* filt_bias  = (const float*)d_in[9];
    const float* filt_decay = (const float*)d_in[10];
    const float* w_out      = (const float*)d_in[11];
    const float* b_out      = (const float*)d_in[12];
    float* out = (float*)d_out;

    static bool attr_set = false;
    if (!attr_set) {
        cudaFuncSetAttribute(hfft_kernel,    cudaFuncAttributeMaxDynamicSharedMemorySize, FFT_SMEM);
        cudaFuncSetAttribute(fftconv_kernel, cudaFuncAttributeMaxDynamicSharedMemorySize, FFT_SMEM);
        attr_set = true;
    }

    // Filter path (independent of u)
    init_kernel<<<32, 256>>>();
    filter_kernel<<<LSEQ, 256>>>(w1, b1, w2, b2, filt_bias, filt_decay);
    hfft_kernel<<<2 * NPAIR, FFT_THREADS, FFT_SMEM>>>();

    // Main path
    gemm_in_kernel<<<dim3(LSEQ / BN, ODIM / BM, BSZ), 256>>>(w_in, u, b_in);
    conv3_kernel<<<dim3(LSEQ / 256, BSZ * ODIM), 256>>>(conv_w, conv_b);

    fftconv_kernel<<<BSZ * NPAIR, FFT_THREADS, FFT_SMEM>>>();

    gemm_out_kernel<<<dim3(DDIM / BN, LSEQ / BM, BSZ), 256>>>(w_out, b_out, out);
}

// round 5
// speedup vs baseline: 1.3865x; 1.1693x over previous
#include <cuda_runtime.h>
#include <cuda_bf16.h>
#include <cstdint>
#include <cstddef>

// ---------------------------------------------------------------------------
// Hyena operator: B=2, L=4096, D=1024, ORDER=2, OD=3072
// Round 5: gemm_in via mma.sync bf16 split-2 (sm_103-legal HMMA path).
// FFT path and gemm_out unchanged from R3.
// ---------------------------------------------------------------------------

#define LSEQ 4096
#define NF   8192
#define DDIM 1024
#define ODIM 3072
#define BSZ  2
#define NPAIR 512
#define FFT_THREADS 512
#define PADI(i) ((i) + ((i) >> 5))
#define SM_HALF 8448
#define FFT_SMEM (2 * SM_HALF * 4)

// Scratch (device .bss — allocation-free)
__device__ float  g_res[(size_t)BSZ * ODIM * LSEQ];
__device__ float  g_cv [(size_t)BSZ * ODIM * LSEQ];
__device__ float  g_v  [(size_t)BSZ * DDIM * LSEQ];
__device__ float  g_h  [(size_t)2   * DDIM * LSEQ];
__device__ float2 g_A  [(size_t)2 * NPAIR * NF];
__device__ float2 g_B  [(size_t)2 * NPAIR * NF];
__device__ float2 g_tw [NF];
__device__ unsigned short g_refl[NF];

// ---------------------------------------------------------------------------
__device__ __forceinline__ uint32_t smem_u32(const void* p) {
    uint32_t a;
    asm("{ .reg .u64 t; cvta.to.shared.u64 t, %1; cvt.u32.u64 %0, t; }" : "=r"(a) : "l"(p));
    return a;
}

#define LDSM_X4(r0, r1, r2, r3, addr) \
    asm volatile("ldmatrix.sync.aligned.m8n8.x4.shared.b16 {%0,%1,%2,%3}, [%4];" \
                 : "=r"(r0), "=r"(r1), "=r"(r2), "=r"(r3) : "r"(addr))
#define LDSM_X2(r0, r1, addr) \
    asm volatile("ldmatrix.sync.aligned.m8n8.x2.shared.b16 {%0,%1}, [%2];" \
                 : "=r"(r0), "=r"(r1) : "r"(addr))

__device__ __forceinline__ void mma_bf16(float* c, const uint32_t* a, const uint32_t* b) {
    asm volatile(
        "mma.sync.aligned.m16n8k16.row.col.f32.bf16.bf16.f32 "
        "{%0,%1,%2,%3}, {%4,%5,%6,%7}, {%8,%9}, {%0,%1,%2,%3};"
        : "+f"(c[0]), "+f"(c[1]), "+f"(c[2]), "+f"(c[3])
        : "r"(a[0]), "r"(a[1]), "r"(a[2]), "r"(a[3]), "r"(b[0]), "r"(b[1]));
}

__device__ __forceinline__ uint32_t pack_hi(float x, float y) {
    __nv_bfloat16 hx = __float2bfloat16(x);
    __nv_bfloat16 hy = __float2bfloat16(y);
    return (uint32_t)__bfloat16_as_ushort(hx) | ((uint32_t)__bfloat16_as_ushort(hy) << 16);
}
__device__ __forceinline__ uint32_t pack_lo(float x, float y) {
    __nv_bfloat16 hx = __float2bfloat16(x);
    __nv_bfloat16 hy = __float2bfloat16(y);
    __nv_bfloat16 lx = __float2bfloat16(x - __bfloat162float(hx));
    __nv_bfloat16 ly = __float2bfloat16(y - __bfloat162float(hy));
    return (uint32_t)__bfloat16_as_ushort(lx) | ((uint32_t)__bfloat16_as_ushort(ly) << 16);
}

// ---------------------------------------------------------------------------
// gemm_in via mma.sync: g_res[b,od,l] = sum_d w_in[od,d]*u[b,l,d] + b_in[od]
// CTA 128x128, warps 2x4 (warp tile 64x32), BK=32, double-buffered smem.
// Smem row stride 40 bf16 (80B) -> conflict-free ldmatrix.
#define MB_A_HI 0
#define MB_A_LO 10240
#define MB_B_HI 20480
#define MB_B_LO 30720
#define MB_BUF  40960
#define MB_SMEM 81920

__global__ __launch_bounds__(256) void gemm_in_mma(
    const float* __restrict__ W,    // [3072,1024] K-contig
    const float* __restrict__ U,    // [2,4096,1024] K-contig
    const float* __restrict__ bias) // [3072]
{
    extern __shared__ char smem[];
    const uint32_t sb = smem_u32(smem);
    const int tid  = threadIdx.x;
    const int lane = tid & 31;
    const int wid  = tid >> 5;
    const int warp_m = wid >> 2;       // 0..1
    const int warp_n = wid & 3;        // 0..3

    const int b  = blockIdx.z;
    const int m0 = blockIdx.y * 128;   // od
    const int n0 = blockIdx.x * 128;   // l
    const float* Wt = W + (size_t)m0 * DDIM;
    const float* Ut = U + ((size_t)b * LSEQ + n0) * DDIM;
    float* C = g_res + (size_t)b * ODIM * LSEQ;

    float acc[4][4][4];
    #pragma unroll
    for (int i = 0; i < 4; i++)
        #pragma unroll
        for (int j = 0; j < 4; j++)
            #pragma unroll
            for (int r = 0; r < 4; r++) acc[i][j][r] = 0.0f;

    // ldmatrix lane byte offsets
    const int a_off = ((lane & 7) + ((lane & 8) ? 8 : 0)) * 80 + ((lane & 16) ? 16 : 0);
    const int b_off = (lane & 7) * 80 + ((lane & 8) ? 16 : 0);

    // staging indices: per i, idx = tid + i*256 in [0,1024): row=idx>>3, c4=idx&7
    const int srow = tid >> 3;           // row for i=0; rows advance by 32 per i
    const int sc4  = tid & 7;            // float4 column index within 32-wide chunk

    float4 wv[4], uv[4];
    #pragma unroll
    for (int i = 0; i < 4; i++) {
        int row = srow + i * 32;
        wv[i] = *(const float4*)(Wt + (size_t)row * DDIM + sc4 * 4);
        uv[i] = *(const float4*)(Ut + (size_t)row * DDIM + sc4 * 4);
    }

    int buf = 0;
    // store chunk 0
    #pragma unroll
    for (int i = 0; i < 4; i++) {
        int row = srow + i * 32;
        int off = row * 80 + sc4 * 8;
        *(uint2*)(smem + MB_A_HI + off) = make_uint2(pack_hi(wv[i].x, wv[i].y), pack_hi(wv[i].z, wv[i].w));
        *(uint2*)(smem + MB_A_LO + off) = make_uint2(pack_lo(wv[i].x, wv[i].y), pack_lo(wv[i].z, wv[i].w));
        *(uint2*)(smem + MB_B_HI + off) = make_uint2(pack_hi(uv[i].x, uv[i].y), pack_hi(uv[i].z, uv[i].w));
        *(uint2*)(smem + MB_B_LO + off) = make_uint2(pack_lo(uv[i].x, uv[i].y), pack_lo(uv[i].z, uv[i].w));
    }
    __syncthreads();

    for (int ch = 0; ch < 32; ch++) {
        const bool has_next = (ch + 1) < 32;
        if (has_next) {
            #pragma unroll
            for (int i = 0; i < 4; i++) {
                int row = srow + i * 32;
                wv[i] = *(const float4*)(Wt + (size_t)row * DDIM + (ch + 1) * 32 + sc4 * 4);
                uv[i] = *(const float4*)(Ut + (size_t)row * DDIM + (ch + 1) * 32 + sc4 * 4);
            }
        }

        const uint32_t base = sb + buf * MB_BUF;
        #pragma unroll
        for (int k16 = 0; k16 < 2; k16++) {
            uint32_t ah[4][4], al[4][4], bh[4][2], bl[4][2];
            #pragma unroll
            for (int i = 0; i < 4; i++) {
                uint32_t ra = base + (warp_m * 64 + i * 16) * 80 + k16 * 32 + a_off;
                LDSM_X4(ah[i][0], ah[i][1], ah[i][2], ah[i][3], ra + MB_A_HI);
                LDSM_X4(al[i][0], al[i][1], al[i][2], al[i][3], ra + MB_A_LO);
            }
            #pragma unroll
            for (int j = 0; j < 4; j++) {
                uint32_t rb = base + (warp_n * 32 + j * 8) * 80 + k16 * 32 + b_off;
                LDSM_X2(bh[j][0], bh[j][1], rb + MB_B_HI);
                LDSM_X2(bl[j][0], bl[j][1], rb + MB_B_LO);
            }
            #pragma unroll
            for (int i = 0; i < 4; i++)
                #pragma unroll
                for (int j = 0; j < 4; j++) {
                    mma_bf16(acc[i][j], ah[i], bh[j]);
                    mma_bf16(acc[i][j], ah[i], bl[j]);
                    mma_bf16(acc[i][j], al[i], bh[j]);
                }
        }

        if (has_next) {
            char* dst = smem + (buf ^ 1) * MB_BUF;
            #pragma unroll
            for (int i = 0; i < 4; i++) {
                int row = srow + i * 32;
                int off = row * 80 + sc4 * 8;
                *(uint2*)(dst + MB_A_HI + off) = make_uint2(pack_hi(wv[i].x, wv[i].y), pack_hi(wv[i].z, wv[i].w));
                *(uint2*)(dst + MB_A_LO + off) = make_uint2(pack_lo(wv[i].x, wv[i].y), pack_lo(wv[i].z, wv[i].w));
                *(uint2*)(dst + MB_B_HI + off) = make_uint2(pack_hi(uv[i].x, uv[i].y), pack_hi(uv[i].z, uv[i].w));
                *(uint2*)(dst + MB_B_LO + off) = make_uint2(pack_lo(uv[i].x, uv[i].y), pack_lo(uv[i].z, uv[i].w));
            }
            __syncthreads();
        }
        buf ^= 1;
    }

    // Epilogue: fragment -> global with bias
    const int g = lane >> 2;
    const int t = lane & 3;
    #pragma unroll
    for (int i = 0; i < 4; i++) {
        int od0 = m0 + warp_m * 64 + i * 16 + g;
        float bv0 = bias[od0];
        float bv1 = bias[od0 + 8];
        #pragma unroll
        for (int j = 0; j < 4; j++) {
            int l = n0 + warp_n * 32 + j * 8 + t * 2;
            *(float2*)&C[(size_t)od0 * LSEQ + l] =
                make_float2(acc[i][j][0] + bv0, acc[i][j][1] + bv0);
            *(float2*)&C[(size_t)(od0 + 8) * LSEQ + l] =
                make_float2(acc[i][j][2] + bv1, acc[i][j][3] + bv1);
        }
    }
}

// ---------------------------------------------------------------------------
// digit-reversed slot <-> frequency maps (DIF ordering of this implementation)
__device__ __forceinline__ int slot_to_freq(int p) {
    int k = 0;
    k |= ((p >> 12) & 1) << 0;
    k |= ((p >> 10) & 1) << 1;
    k |= ((p >> 11) & 1) << 2;
    k |= ((p >>  8) & 1) << 3;
    k |= ((p >>  9) & 1) << 4;
    k |= ((p >>  6) & 1) << 5;
    k |= ((p >>  7) & 1) << 6;
    k |= ((p >>  4) & 1) << 7;
    k |= ((p >>  5) & 1) << 8;
    k |= ((p >>  2) & 1) << 9;
    k |= ((p >>  3) & 1) << 10;
    k |= ((p >>  0) & 1) << 11;
    k |= ((p >>  1) & 1) << 12;
    return k;
}
__device__ __forceinline__ int freq_to_slot(int k) {
    int p = 0;
    p |= ((k >>  0) & 1) << 12;
    p |= ((k >>  1) & 1) << 10;
    p |= ((k >>  2) & 1) << 11;
    p |= ((k >>  3) & 1) << 8;
    p |= ((k >>  4) & 1) << 9;
    p |= ((k >>  5) & 1) << 6;
    p |= ((k >>  6) & 1) << 7;
    p |= ((k >>  7) & 1) << 4;
    p |= ((k >>  8) & 1) << 5;
    p |= ((k >>  9) & 1) << 2;
    p |= ((k >> 10) & 1) << 3;
    p |= ((k >> 11) & 1) << 0;
    p |= ((k >> 12) & 1) << 1;
    return p;
}

__global__ void init_kernel() {
    int i = blockIdx.x * blockDim.x + threadIdx.x;
    if (i < NF) {
        double ang = -2.0 * 3.141592653589793238462643 * (double)i / (double)NF;
        g_tw[i] = make_float2((float)cos(ang), (float)sin(ang));
        int k  = slot_to_freq(i);
        int kp = (NF - k) & (NF - 1);
        g_refl[i] = (unsigned short)freq_to_slot(kp);
    }
}

// ---------------------------------------------------------------------------
__global__ __launch_bounds__(256) void filter_kernel(
    const float* __restrict__ w1, const float* __restrict__ b1,
    const float* __restrict__ w2, const float* __restrict__ b2,
    const float* __restrict__ fb, const float* __restrict__ fd)
{
    __shared__ float pe[33];
    __shared__ float sact[64];
    const int l = blockIdx.x;
    const float t = (float)l * (1.0f / (float)(LSEQ - 1));
    const int tid = threadIdx.x;

    if (tid < 33) pe[tid] = sinf(t * (float)tid * 10.0f);
    __syncthreads();
    if (tid < 64) {
        float z = b1[tid];
        #pragma unroll
        for (int j = 0; j < 33; j++) z += pe[j] * w1[tid * 33 + j];
        sact[tid] = sinf(10.0f * z);
    }
    __syncthreads();

    for (int o = tid; o < 2 * DDIM; o += 256) {
        float acc = b2[o];
        #pragma unroll
        for (int i = 0; i < 64; i++) acc += sact[i] * w2[o * 64 + i];
        float dec = expf(-expf(fd[o]) * t);
        g_h[(size_t)o * LSEQ + l] = (acc * dec + fb[o]) * (1.0f / (float)LSEQ);
    }
}

// ---------------------------------------------------------------------------
// FFT pieces (8192-pt, 512 threads, split re/im padded smem)
__device__ __forceinline__ void fft_fwd_zp(float* __restrict__ SR, float* __restrict__ SI) {
    #pragma unroll
    for (int jj = 0; jj < 8; jj++) {
        int j  = threadIdx.x + jj * FFT_THREADS;
        int i0 = PADI(j), i1 = PADI(j + 4096);
        float ar = SR[i0], ai = SI[i0];
        float2 w = g_tw[j];
        SR[i1] = ar * w.x - ai * w.y;
        SI[i1] = ar * w.y + ai * w.x;
    }
    __syncthreads();
    #pragma unroll
    for (int st = 0; st < 6; st++) {
        const int lm  = 10 - 2 * st;
        const int m   = 1 << lm;
        const int str = 2048 >> lm;
        #pragma unroll
        for (int jj = 0; jj < 4; jj++) {
            int t = threadIdx.x + jj * FFT_THREADS;
            int q = t & (m - 1);
            int base = ((t >> lm) << (lm + 2)) | q;
            int i0 = PADI(base), i1 = PADI(base + m),
                i2 = PADI(base + 2 * m), i3 = PADI(base + 3 * m);
            float x0r = SR[i0], x0i = SI[i0];
            float x1r = SR[i1], x1i = SI[i1];
            float x2r = SR[i2], x2i = SI[i2];
            float x3r = SR[i3], x3i = SI[i3];
            float2 w1 = g_tw[q * str];
            float2 w2 = g_tw[2 * q * str];
            float2 w3 = g_tw[3 * q * str];
            float t0r = x0r + x2r, t0i = x0i + x2i;
            float t1r = x1r + x3r, t1i = x1i + x3i;
            float t2r = x0r - x2r, t2i = x0i - x2i;
            float t3r = x1i - x3i, t3i = x3r - x1r;
            SR[i0] = t0r + t1r; SI[i0] = t0i + t1i;
            float ur = t2r + t3r, ui = t2i + t3i;
            SR[i1] = ur * w1.x - ui * w1.y; SI[i1] = ur * w1.y + ui * w1.x;
            ur = t0r - t1r; ui = t0i - t1i;
            SR[i2] = ur * w2.x - ui * w2.y; SI[i2] = ur * w2.y + ui * w2.x;
            ur = t2r - t3r; ui = t2i - t3i;
            SR[i3] = ur * w3.x - ui * w3.y; SI[i3] = ur * w3.y + ui * w3.x;
        }
        __syncthreads();
    }
}

__device__ __forceinline__ void fft_inv_half(float* __restrict__ SR, float* __restrict__ SI) {
    #pragma unroll
    for (int st = 0; st < 6; st++) {
        const int lm  = 2 * st;
        const int m   = 1 << lm;
        const int str = 2048 >> lm;
        #pragma unroll
        for (int jj = 0; jj < 4; jj++) {
            int t = threadIdx.x + jj * FFT_THREADS;
            int q = t & (m - 1);
            int base = ((t >> lm) << (lm + 2)) | q;
            int i0 = PADI(base), i1 = PADI(base + m),
                i2 = PADI(base + 2 * m), i3 = PADI(base + 3 * m);
            float u0r = SR[i0], u0i = SI[i0];
            float u1r = SR[i1], u1i = SI[i1];
            float u2r = SR[i2], u2i = SI[i2];
            float u3r = SR[i3], u3i = SI[i3];
            float2 w1 = g_tw[q * str];
            float2 w2 = g_tw[2 * q * str];
            float2 w3 = g_tw[3 * q * str];
            float c1r = u1r * w1.x + u1i * w1.y, c1i = u1i * w1.x - u1r * w1.y;
            float c2r = u2r * w2.x + u2i * w2.y, c2i = u2i * w2.x - u2r * w2.y;
            float c3r = u3r * w3.x + u3i * w3.y, c3i = u3i * w3.x - u3r * w3.y;
            float s0r = u0r + c2r, s0i = u0i + c2i;
            float s1r = u0r - c2r, s1i = u0i - c2i;
            float s2r = c1r + c3r, s2i = c1i + c3i;
            float s3r = c1r - c3r, s3i = c1i - c3i;
            SR[i0] = s0r + s2r; SI[i0] = s0i + s2i;
            SR[i2] = s0r - s2r; SI[i2] = s0i - s2i;
            SR[i1] = s1r - s3i; SI[i1] = s1i + s3r;
            SR[i3] = s1r + s3i; SI[i3] = s1i - s3r;
        }
        __syncthreads();
    }
    #pragma unroll
    for (int jj = 0; jj < 8; jj++) {
        int j  = threadIdx.x + jj * FFT_THREADS;
        int i0 = PADI(j), i1 = PADI(j + 4096);
        float2 w = g_tw[j];
        float br = SR[i1], bi = SI[i1];
        float tr = br * w.x + bi * w.y;
        float ti = bi * w.x - br * w.y;
        SR[i0] += tr; SI[i0] += ti;
    }
    __syncthreads();
}

// ---------------------------------------------------------------------------
__global__ __launch_bounds__(FFT_THREADS) void hfft_kernel() {
    extern __shared__ float sm[];
    float* SR = sm;
    float* SI = sm + SM_HALF;
    const int c = blockIdx.x;
    const int n = c >> 9;
    const int dpair = c & (NPAIR - 1);
    const float* h0 = g_h + ((size_t)n * DDIM + 2 * dpair)     * LSEQ;
    const float* h1 = g_h + ((size_t)n * DDIM + 2 * dpair + 1) * LSEQ;

    for (int i = threadIdx.x; i < LSEQ; i += FFT_THREADS) {
        SR[PADI(i)] = h0[i]; SI[PADI(i)] = h1[i];
    }
    __syncthreads();
    fft_fwd_zp(SR, SI);

    float2* Ao = g_A + (size_t)c * NF;
    float2* Bo = g_B + (size_t)c * NF;
    for (int p = threadIdx.x; p < NF; p += FFT_THREADS) {
        int q = g_refl[p];
        float zpr = SR[PADI(p)], zpi = SI[PADI(p)];
        float zqr = SR[PADI(q)], zqi = SI[PADI(q)];
        float g0r = 0.5f * (zpr + zqr), g0i = 0.5f * (zpi - zqi);
        float g1r = 0.5f * (zpi + zqi), g1i = 0.5f * (zqr - zpr);
        Ao[p] = make_float2(0.5f * (g0r + g1r), 0.5f * (g0i + g1i));
        Bo[p] = make_float2(0.5f * (g0r - g1r), 0.5f * (g0i - g1i));
    }
}

// ---------------------------------------------------------------------------
__global__ __launch_bounds__(FFT_THREADS) void fftconv_kernel() {
    extern __shared__ float sm[];
    float* SR = sm;
    float* SI = sm + SM_HALF;
    const int c = blockIdx.x;
    const int b = c >> 9;
    const int dpair = c & (NPAIR - 1);
    const int ch0 = 2 * dpair, ch1 = ch0 + 1;
    const float inv = 1.0f / (float)NF;

    const float* v0 = &g_cv[((size_t)(b * 3 + 2) * DDIM + ch0) * LSEQ];
    const float* v1 = &g_cv[((size_t)(b * 3 + 2) * DDIM + ch1) * LSEQ];

    for (int i = threadIdx.x; i < LSEQ; i += FFT_THREADS) {
        SR[PADI(i)] = v0[i]; SI[PADI(i)] = v1[i];
    }
    __syncthreads();

    #pragma unroll 1
    for (int n = 0; n < 2; n++) {
        fft_fwd_zp(SR, SI);

        const float2* Ap = g_A + ((size_t)n * NPAIR + dpair) * NF;
        const float2* Bp = g_B + ((size_t)n * NPAIR + dpair) * NF;
        #pragma unroll
        for (int jj = 0; jj < 16; jj++) {
            int p = threadIdx.x + jj * FFT_THREADS;
            int q = g_refl[p];
            if (q < p) continue;
            int ip = PADI(p), iq = PADI(q);
            float zr = SR[ip], zi = SI[ip];
            float wr = SR[iq], wi = SI[iq];
            float2 a  = Ap[p];
            float2 bb = Bp[p];
            float ypr = a.x * zr - a.y * zi + bb.x * wr + bb.y * wi;
            float ypi = a.x * zi + a.y * zr + bb.y * wr - bb.x * wi;
            float yqr = a.x * wr + a.y * wi + bb.x * zr - bb.y * zi;
            float yqi = a.x * wi - a.y * wr - bb.x * zi - bb.y * zr;
            SR[ip] = ypr; SI[ip] = ypi;
            SR[iq] = yqr; SI[iq] = yqi;
        }
        __syncthreads();

        fft_inv_half(SR, SI);

        if (n == 0) {
            const float* xa = &g_cv[((size_t)(b * 3 + 0) * DDIM + ch0) * LSEQ];
            const float* xb = &g_cv[((size_t)(b * 3 + 0) * DDIM + ch1) * LSEQ];
            for (int l = threadIdx.x; l < LSEQ; l += FFT_THREADS) {
                int ip = PADI(l);
                SR[ip] = SR[ip] * inv * xa[l];
                SI[ip] = SI[ip] * inv * xb[l];
            }
            __syncthreads();
        } else {
            const float* xa = &g_cv[((size_t)(b * 3 + 1) * DDIM + ch0) * LSEQ];
            const float* xb = &g_cv[((size_t)(b * 3 + 1) * DDIM + ch1) * LSEQ];
            float* o0 = &g_v[((size_t)b * DDIM + ch0) * LSEQ];
            float* o1 = &g_v[((size_t)b * DDIM + ch1) * LSEQ];
            for (int l = threadIdx.x; l < LSEQ; l += FFT_THREADS) {
                int ip = PADI(l);
                o0[l] = SR[ip] * inv * xa[l];
                o1[l] = SI[ip] * inv * xb[l];
            }
        }
    }
}

// ---------------------------------------------------------------------------
__global__ void conv3_kernel(const float* __restrict__ cw, const float* __restrict__ cb) {
    const int row = blockIdx.y;            // b*3072 + od
    const int od  = row % ODIM;
    const int l   = blockIdx.x * 256 + threadIdx.x;
    const float* r = g_res + (size_t)row * LSEQ;
    float left  = (l > 0)        ? r[l - 1] : 0.0f;
    float mid   = r[l];
    float right = (l < LSEQ - 1) ? r[l + 1] : 0.0f;
    float w0 = cw[od * 3], w1 = cw[od * 3 + 1], w2 = cw[od * 3 + 2];
    g_cv[(size_t)row * LSEQ + l] = w0 * left + w1 * mid + w2 * right + cb[od];
}

// ---------------------------------------------------------------------------
// SGEMM 2 (double-buffered fp32): out[b,l,e] = sum_d g_v[b,d,l]*w_out[e,d] + b_out[e]
#define BM 128
#define BN 128
#define BK 16

__global__ __launch_bounds__(256) void gemm_out_kernel(
    const float* __restrict__ Wo,
    const float* __restrict__ bias,
    float* __restrict__ O)
{
    __shared__ float As[2][BK][BM];
    __shared__ float Bs[2][BK][BN];
    const int b  = blockIdx.z;
    const int m0 = blockIdx.y * BM;
    const int n0 = blockIdx.x * BN;
    const float* Av = g_v + (size_t)b * DDIM * LSEQ;
    float* C = O + (size_t)b * LSEQ * DDIM;

    const int tid  = threadIdx.x;
    const int tm   = tid >> 4;
    const int tn   = tid & 15;
    const int lak  = tid >> 4;
    const int lam  = (tid & 15) * 8;
    const int lrow = tid >> 1;
    const int lk   = (tid & 1) * 8;

    float acc[8][8];
    #pragma unroll
    for (int i = 0; i < 8; i++)
        #pragma unroll
        for (int j = 0; j < 8; j++) acc[i][j] = 0.0f;

    float4 a0 = *(const float4*)&Av[(size_t)lak * LSEQ + m0 + lam];
    float4 a1 = *(const float4*)&Av[(size_t)lak * LSEQ + m0 + lam + 4];
    float4 c0 = *(const float4*)&Wo[(size_t)(n0 + lrow) * DDIM + lk];
    float4 c1 = *(const float4*)&Wo[(size_t)(n0 + lrow) * DDIM + lk + 4];
    *(float4*)&As[0][lak][lam]     = a0;
    *(float4*)&As[0][lak][lam + 4] = a1;
    Bs[0][lk + 0][lrow] = c0.x; Bs[0][lk + 1][lrow] = c0.y;
    Bs[0][lk + 2][lrow] = c0.z; Bs[0][lk + 3][lrow] = c0.w;
    Bs[0][lk + 4][lrow] = c1.x; Bs[0][lk + 5][lrow] = c1.y;
    Bs[0][lk + 6][lrow] = c1.z; Bs[0][lk + 7][lrow] = c1.w;
    __syncthreads();

    int buf = 0;
    for (int k0 = 0; k0 < DDIM; k0 += BK) {
        const bool has_next = (k0 + BK) < DDIM;
        if (has_next) {
            a0 = *(const float4*)&Av[(size_t)(k0 + BK + lak) * LSEQ + m0 + lam];
            a1 = *(const float4*)&Av[(size_t)(k0 + BK + lak) * LSEQ + m0 + lam + 4];
            c0 = *(const float4*)&Wo[(size_t)(n0 + lrow) * DDIM + k0 + BK + lk];
            c1 = *(const float4*)&Wo[(size_t)(n0 + lrow) * DDIM + k0 + BK + lk + 4];
        }
        const float (*Ab)[BM] = As[buf];
        const float (*Bb)[BN] = Bs[buf];
        #pragma unroll
        for (int k = 0; k < BK; k++) {
            float4 ra0 = *(const float4*)&Ab[k][tm * 8];
            float4 ra1 = *(const float4*)&Ab[k][tm * 8 + 4];
            float4 rb0 = *(const float4*)&Bb[k][tn * 8];
            float4 rb1 = *(const float4*)&Bb[k][tn * 8 + 4];
            float ra[8] = {ra0.x, ra0.y, ra0.z, ra0.w, ra1.x, ra1.y, ra1.z, ra1.w};
            float rb[8] = {rb0.x, rb0.y, rb0.z, rb0.w, rb1.x, rb1.y, rb1.z, rb1.w};
            #pragma unroll
            for (int i = 0; i < 8; i++)
                #pragma unroll
                for (int j = 0; j < 8; j++) acc[i][j] += ra[i] * rb[j];
        }
        if (has_next) {
            int nb = buf ^ 1;
            *(float4*)&As[nb][lak][lam]     = a0;
            *(float4*)&As[nb][lak][lam + 4] = a1;
            Bs[nb][lk + 0][lrow] = c0.x; Bs[nb][lk + 1][lrow] = c0.y;
            Bs[nb][lk + 2][lrow] = c0.z; Bs[nb][lk + 3][lrow] = c0.w;
            Bs[nb][lk + 4][lrow] = c1.x; Bs[nb][lk + 5][lrow] = c1.y;
            Bs[nb][lk + 6][lrow] = c1.z; Bs[nb][lk + 7][lrow] = c1.w;
            __syncthreads();
            buf = nb;
        }
    }

    float bb[8];
    #pragma unroll
    for (int j = 0; j < 8; j++) bb[j] = bias[n0 + tn * 8 + j];

    #pragma unroll
    for (int i = 0; i < 8; i++) {
        int m = m0 + tm * 8 + i;
        float4 o0 = make_float4(acc[i][0] + bb[0], acc[i][1] + bb[1],
                                acc[i][2] + bb[2], acc[i][3] + bb[3]);
        float4 o1 = make_float4(acc[i][4] + bb[4], acc[i][5] + bb[5],
                                acc[i][6] + bb[6], acc[i][7] + bb[7]);
        *(float4*)&C[(size_t)m * DDIM + n0 + tn * 8]     = o0;
        *(float4*)&C[(size_t)m * DDIM + n0 + tn * 8 + 4] = o1;
    }
}

// ---------------------------------------------------------------------------
extern "C" void kernel_launch(void* const* d_in, const int* in_sizes, int n_in,
                              void* d_out, int out_size)
{
    const float* u          = (const float*)d_in[0];
    const float* w_in       = (const float*)d_in[1];
    const float* b_in       = (const float*)d_in[2];
    const float* conv_w     = (const float*)d_in[3];
    const float* conv_b     = (const float*)d_in[4];
    const float* w1         = (const float*)d_in[5];
    const float* b1         = (const float*)d_in[6];
    const float* w2         = (const float*)d_in[7];
    const float* b2         = (const float*)d_in[8];
    const float* filt_bias  = (const float*)d_in[9];
    const float* filt_decay = (const float*)d_in[10];
    const float* w_out      = (const float*)d_in[11];
    const float* b_out      = (const float*)d_in[12];
    float* out = (float*)d_out;

    static bool attr_set = false;
    if (!attr_set) {
        cudaFuncSetAttribute(hfft_kernel,    cudaFuncAttributeMaxDynamicSharedMemorySize, FFT_SMEM);
        cudaFuncSetAttribute(fftconv_kernel, cudaFuncAttributeMaxDynamicSharedMemorySize, FFT_SMEM);
        cudaFuncSetAttribute(gemm_in_mma,    cudaFuncAttributeMaxDynamicSharedMemorySize, MB_SMEM);
        attr_set = true;
    }

    // Filter path (independent of u)
    init_kernel<<<32, 256>>>();
    filter_kernel<<<LSEQ, 256>>>(w1, b1, w2, b2, filt_bias, filt_decay);
    hfft_kernel<<<2 * NPAIR, FFT_THREADS, FFT_SMEM>>>();

    // Main path
    gemm_in_mma<<<dim3(LSEQ / 128, ODIM / 128, BSZ), 256, MB_SMEM>>>(w_in, u, b_in);
    conv3_kernel<<<dim3(LSEQ / 256, BSZ * ODIM), 256>>>(conv_w, conv_b);

    fftconv_kernel<<<BSZ * NPAIR, FFT_THREADS, FFT_SMEM>>>();

    gemm_out_kernel<<<dim3(DDIM / BN, LSEQ / BM, BSZ), 256>>>(w_out, b_out, out);
}

// round 6
// speedup vs baseline: 1.5585x; 1.1241x over previous
#include <cuda_runtime.h>
#include <cuda_bf16.h>
#include <cstdint>
#include <cstddef>

// ---------------------------------------------------------------------------
// Hyena operator: B=2, L=4096, D=1024, ORDER=2, OD=3072
// Round 6: both GEMMs via mma.sync bf16 split-2 with cp.async 3-stage
// pipelines; operands pre-converted to packed bf16 hi/lo; fftconv emits v
// as bf16 hi/lo directly.
// ---------------------------------------------------------------------------

#define LSEQ 4096
#define NF   8192
#define DDIM 1024
#define ODIM 3072
#define BSZ  2
#define NPAIR 512
#define FFT_THREADS 512
#define PADI(i) ((i) + ((i) >> 5))
#define SM_HALF 8448
#define FFT_SMEM (2 * SM_HALF * 4)

// Scratch (device .bss — allocation-free)
__device__ float  g_res[(size_t)BSZ * ODIM * LSEQ];
__device__ float  g_cv [(size_t)BSZ * ODIM * LSEQ];
__device__ float  g_h  [(size_t)2   * DDIM * LSEQ];
__device__ float2 g_A  [(size_t)2 * NPAIR * NF];
__device__ float2 g_B  [(size_t)2 * NPAIR * NF];
__device__ float2 g_tw [NF];
__device__ unsigned short g_refl[NF];
// packed bf16 hi/lo operands (uint32 = 2 bf16)
__device__ uint32_t g_wh[(size_t)ODIM * DDIM / 2];
__device__ uint32_t g_wl[(size_t)ODIM * DDIM / 2];
__device__ uint32_t g_uh[(size_t)BSZ * LSEQ * DDIM / 2];
__device__ uint32_t g_ul[(size_t)BSZ * LSEQ * DDIM / 2];
__device__ uint32_t g_oh[(size_t)DDIM * DDIM / 2];
__device__ uint32_t g_ol[(size_t)DDIM * DDIM / 2];
__device__ uint32_t g_vh[(size_t)BSZ * DDIM * LSEQ / 2];
__device__ uint32_t g_vl[(size_t)BSZ * DDIM * LSEQ / 2];

// ---------------------------------------------------------------------------
__device__ __forceinline__ uint32_t smem_u32(const void* p) {
    uint32_t a;
    asm("{ .reg .u64 t; cvta.to.shared.u64 t, %1; cvt.u32.u64 %0, t; }" : "=r"(a) : "l"(p));
    return a;
}

#define LDSM_X4(r0, r1, r2, r3, addr) \
    asm volatile("ldmatrix.sync.aligned.m8n8.x4.shared.b16 {%0,%1,%2,%3}, [%4];" \
                 : "=r"(r0), "=r"(r1), "=r"(r2), "=r"(r3) : "r"(addr))
#define LDSM_X4_T(r0, r1, r2, r3, addr) \
    asm volatile("ldmatrix.sync.aligned.m8n8.x4.trans.shared.b16 {%0,%1,%2,%3}, [%4];" \
                 : "=r"(r0), "=r"(r1), "=r"(r2), "=r"(r3) : "r"(addr))
#define LDSM_X2(r0, r1, addr) \
    asm volatile("ldmatrix.sync.aligned.m8n8.x2.shared.b16 {%0,%1}, [%2];" \
                 : "=r"(r0), "=r"(r1) : "r"(addr))
#define CP_ASYNC16(dst, src) \
    asm volatile("cp.async.cg.shared.global [%0], [%1], 16;" :: "r"(dst), "l"(src))
#define CP_COMMIT() asm volatile("cp.async.commit_group;" ::: "memory")
#define CP_WAIT2()  asm volatile("cp.async.wait_group 2;" ::: "memory")

__device__ __forceinline__ void mma_bf16(float* c, const uint32_t* a, const uint32_t* b) {
    asm volatile(
        "mma.sync.aligned.m16n8k16.row.col.f32.bf16.bf16.f32 "
        "{%0,%1,%2,%3}, {%4,%5,%6,%7}, {%8,%9}, {%0,%1,%2,%3};"
        : "+f"(c[0]), "+f"(c[1]), "+f"(c[2]), "+f"(c[3])
        : "r"(a[0]), "r"(a[1]), "r"(a[2]), "r"(a[3]), "r"(b[0]), "r"(b[1]));
}

__device__ __forceinline__ uint32_t pack_hi(float x, float y) {
    __nv_bfloat16 hx = __float2bfloat16(x);
    __nv_bfloat16 hy = __float2bfloat16(y);
    return (uint32_t)__bfloat16_as_ushort(hx) | ((uint32_t)__bfloat16_as_ushort(hy) << 16);
}
__device__ __forceinline__ uint32_t pack_lo(float x, float y) {
    __nv_bfloat16 hx = __float2bfloat16(x);
    __nv_bfloat16 hy = __float2bfloat16(y);
    __nv_bfloat16 lx = __float2bfloat16(x - __bfloat162float(hx));
    __nv_bfloat16 ly = __float2bfloat16(y - __bfloat162float(hy));
    return (uint32_t)__bfloat16_as_ushort(lx) | ((uint32_t)__bfloat16_as_ushort(ly) << 16);
}

// fp32 -> packed bf16 hi/lo
__global__ void cvt_split(const float* __restrict__ src, uint32_t* __restrict__ hi,
                          uint32_t* __restrict__ lo, int n2) {
    int i = blockIdx.x * 256 + threadIdx.x;
    if (i < n2) {
        float2 v = ((const float2*)src)[i];
        hi[i] = pack_hi(v.x, v.y);
        lo[i] = pack_lo(v.x, v.y);
    }
}

// ---------------------------------------------------------------------------
// gemm_in: g_res[b,od,l] = sum_d w_in[od,d]*u[b,l,d] + b_in[od]
// CTA 128x128, 8 warps (2x4), BK=32, cp.async 3-stage pipeline.
#define GI_STAGE 40960
#define GI_SMEM  (3 * GI_STAGE)

__global__ __launch_bounds__(256) void gemm_in_mma(const float* __restrict__ bias)
{
    extern __shared__ char smem[];
    const uint32_t sb = smem_u32(smem);
    const int tid  = threadIdx.x;
    const int lane = tid & 31;
    const int wid  = tid >> 5;
    const int warp_m = wid >> 2;
    const int warp_n = wid & 3;

    const int b  = blockIdx.z;
    const int m0 = blockIdx.y * 128;   // od
    const int n0 = blockIdx.x * 128;   // l
    float* C = g_res + (size_t)b * ODIM * LSEQ;

    // cp.async per-thread assignment: tile = tid>>6 (Ahi,Alo,Bhi,Blo), 8 ops each
    const int tile = tid >> 6;
    const int tloc = tid & 63;
    const char* gbase;
    if      (tile == 0) gbase = (const char*)g_wh + (size_t)m0 * 2048;
    else if (tile == 1) gbase = (const char*)g_wl + (size_t)m0 * 2048;
    else if (tile == 2) gbase = (const char*)g_uh + (size_t)(b * LSEQ + n0) * 2048;
    else                gbase = (const char*)g_ul + (size_t)(b * LSEQ + n0) * 2048;

    float acc[4][4][4];
    #pragma unroll
    for (int i = 0; i < 4; i++)
        #pragma unroll
        for (int j = 0; j < 4; j++)
            #pragma unroll
            for (int r = 0; r < 4; r++) acc[i][j][r] = 0.0f;

    const int a_off = ((lane & 7) + ((lane & 8) ? 8 : 0)) * 80 + ((lane & 16) ? 16 : 0);
    const int b_off = (lane & 7) * 80 + ((lane & 8) ? 16 : 0);

    // prologue: stages 0..2 <- chunks 0..2
    #pragma unroll
    for (int p = 0; p < 3; p++) {
        #pragma unroll
        for (int o = 0; o < 8; o++) {
            int idx = tloc + o * 64, row = idx >> 2, c = idx & 3;
            uint32_t dst = sb + p * GI_STAGE + tile * 10240 + row * 80 + c * 16;
            CP_ASYNC16(dst, gbase + (size_t)row * 2048 + p * 64 + c * 16);
        }
        CP_COMMIT();
    }

    for (int ch = 0; ch < 32; ch++) {
        CP_WAIT2();
        __syncthreads();
        const uint32_t sbase = sb + (ch % 3) * GI_STAGE;

        #pragma unroll
        for (int k16 = 0; k16 < 2; k16++) {
            uint32_t ah[4][4], al[4][4], bh[4][2], bl[4][2];
            #pragma unroll
            for (int i = 0; i < 4; i++) {
                uint32_t ra = sbase + (warp_m * 64 + i * 16) * 80 + k16 * 32 + a_off;
                LDSM_X4(ah[i][0], ah[i][1], ah[i][2], ah[i][3], ra);
                LDSM_X4(al[i][0], al[i][1], al[i][2], al[i][3], ra + 10240);
            }
            #pragma unroll
            for (int j = 0; j < 4; j++) {
                uint32_t rb = sbase + 20480 + (warp_n * 32 + j * 8) * 80 + k16 * 32 + b_off;
                LDSM_X2(bh[j][0], bh[j][1], rb);
                LDSM_X2(bl[j][0], bl[j][1], rb + 10240);
            }
            #pragma unroll
            for (int i = 0; i < 4; i++)
                #pragma unroll
                for (int j = 0; j < 4; j++) {
                    mma_bf16(acc[i][j], ah[i], bh[j]);
                    mma_bf16(acc[i][j], ah[i], bl[j]);
                    mma_bf16(acc[i][j], al[i], bh[j]);
                }
        }

        __syncthreads();   // all warps done reading this stage
        if (ch + 3 < 32) {
            int st = (ch + 3) % 3;
            #pragma unroll
            for (int o = 0; o < 8; o++) {
                int idx = tloc + o * 64, row = idx >> 2, c = idx & 3;
                uint32_t dst = sb + st * GI_STAGE + tile * 10240 + row * 80 + c * 16;
                CP_ASYNC16(dst, gbase + (size_t)row * 2048 + (ch + 3) * 64 + c * 16);
            }
        }
        CP_COMMIT();
    }

    // epilogue
    const int g = lane >> 2;
    const int t = lane & 3;
    #pragma unroll
    for (int i = 0; i < 4; i++) {
        int od0 = m0 + warp_m * 64 + i * 16 + g;
        float bv0 = bias[od0];
        float bv1 = bias[od0 + 8];
        #pragma unroll
        for (int j = 0; j < 4; j++) {
            int l = n0 + warp_n * 32 + j * 8 + t * 2;
            *(float2*)&C[(size_t)od0 * LSEQ + l] =
                make_float2(acc[i][j][0] + bv0, acc[i][j][1] + bv0);
            *(float2*)&C[(size_t)(od0 + 8) * LSEQ + l] =
                make_float2(acc[i][j][2] + bv1, acc[i][j][3] + bv1);
        }
    }
}

// ---------------------------------------------------------------------------
// gemm_out: out[b,l,e] = sum_d v[b,d,l]*w_out[e,d] + b_out[e]
// A = v^T via ldmatrix.trans from [d][l] tiles (stride 272B), B = w_out rows.
#define GO_A_LO  8704
#define GO_B_HI  17408
#define GO_B_LO  27648
#define GO_STAGE 37888
#define GO_SMEM  (3 * GO_STAGE)

__global__ __launch_bounds__(256) void gemm_out_mma(const float* __restrict__ bias,
                                                    float* __restrict__ O)
{
    extern __shared__ char smem[];
    const uint32_t sb = smem_u32(smem);
    const int tid  = threadIdx.x;
    const int lane = tid & 31;
    const int wid  = tid >> 5;
    const int warp_m = wid >> 2;
    const int warp_n = wid & 3;

    const int b  = blockIdx.z;
    const int m0 = blockIdx.y * 128;   // l
    const int n0 = blockIdx.x * 128;   // e
    float* C = O + (size_t)b * LSEQ * DDIM;

    const int tile = tid >> 6;     // 0:v_hi 1:v_lo 2:wo_hi 3:wo_lo
    const int tloc = tid & 63;
    const char* gbase;
    if      (tile == 0) gbase = (const char*)g_vh + (size_t)(b * DDIM) * 8192 + (size_t)m0 * 2;
    else if (tile == 1) gbase = (const char*)g_vl + (size_t)(b * DDIM) * 8192 + (size_t)m0 * 2;
    else if (tile == 2) gbase = (const char*)g_oh + (size_t)n0 * 2048;
    else                gbase = (const char*)g_ol + (size_t)n0 * 2048;

    float acc[4][4][4];
    #pragma unroll
    for (int i = 0; i < 4; i++)
        #pragma unroll
        for (int j = 0; j < 4; j++)
            #pragma unroll
            for (int r = 0; r < 4; r++) acc[i][j][r] = 0.0f;

    // A (trans): row = k (d) in [0,32); col = m (l)
    const int at_off = ((lane & 7) + ((lane & 16) ? 8 : 0)) * 272 + ((lane & 8) ? 16 : 0);
    const int b_off  = (lane & 7) * 80 + ((lane & 8) ? 16 : 0);

    #pragma unroll
    for (int p = 0; p < 3; p++) {
        if (tile < 2) {
            #pragma unroll
            for (int o = 0; o < 8; o++) {
                int idx = tloc + o * 64, row = idx >> 4, c = idx & 15;
                uint32_t dst = sb + p * GO_STAGE + tile * GO_A_LO + row * 272 + c * 16;
                CP_ASYNC16(dst, gbase + (size_t)(p * 32 + row) * 8192 + c * 16);
            }
        } else {
            #pragma unroll
            for (int o = 0; o < 8; o++) {
                int idx = tloc + o * 64, row = idx >> 2, c = idx & 3;
                uint32_t dst = sb + p * GO_STAGE + GO_B_HI + (tile - 2) * 10240 + row * 80 + c * 16;
                CP_ASYNC16(dst, gbase + (size_t)row * 2048 + p * 64 + c * 16);
            }
        }
        CP_COMMIT();
    }

    for (int ch = 0; ch < 32; ch++) {
        CP_WAIT2();
        __syncthreads();
        const uint32_t sbase = sb + (ch % 3) * GO_STAGE;

        #pragma unroll
        for (int k16 = 0; k16 < 2; k16++) {
            uint32_t ah[4][4], al[4][4], bh[4][2], bl[4][2];
            #pragma unroll
            for (int i = 0; i < 4; i++) {
                uint32_t ra = sbase + k16 * 16 * 272 + (warp_m * 64 + i * 16) * 2 + at_off;
                LDSM_X4_T(ah[i][0], ah[i][1], ah[i][2], ah[i][3], ra);
                LDSM_X4_T(al[i][0], al[i][1], al[i][2], al[i][3], ra + GO_A_LO);
            }
            #pragma unroll
            for (int j = 0; j < 4; j++) {
                uint32_t rb = sbase + GO_B_HI + (warp_n * 32 + j * 8) * 80 + k16 * 32 + b_off;
                LDSM_X2(bh[j][0], bh[j][1], rb);
                LDSM_X2(bl[j][0], bl[j][1], rb + 10240);
            }
            #pragma unroll
            for (int i = 0; i < 4; i++)
                #pragma unroll
                for (int j = 0; j < 4; j++) {
                    mma_bf16(acc[i][j], ah[i], bh[j]);
                    mma_bf16(acc[i][j], ah[i], bl[j]);
                    mma_bf16(acc[i][j], al[i], bh[j]);
                }
        }

        __syncthreads();
        if (ch + 3 < 32) {
            int st = (ch + 3) % 3;
            if (tile < 2) {
                #pragma unroll
                for (int o = 0; o < 8; o++) {
                    int idx = tloc + o * 64, row = idx >> 4, c = idx & 15;
                    uint32_t dst = sb + st * GO_STAGE + tile * GO_A_LO + row * 272 + c * 16;
                    CP_ASYNC16(dst, gbase + (size_t)((ch + 3) * 32 + row) * 8192 + c * 16);
                }
            } else {
                #pragma unroll
                for (int o = 0; o < 8; o++) {
                    int idx = tloc + o * 64, row = idx >> 2, c = idx & 3;
                    uint32_t dst = sb + st * GO_STAGE + GO_B_HI + (tile - 2) * 10240 + row * 80 + c * 16;
                    CP_ASYNC16(dst, gbase + (size_t)row * 2048 + (ch + 3) * 64 + c * 16);
                }
            }
        }
        CP_COMMIT();
    }

    // epilogue: rows = l, cols = e (bias over e)
    const int g = lane >> 2;
    const int t = lane & 3;
    #pragma unroll
    for (int j = 0; j < 4; j++) {
        int e = n0 + warp_n * 32 + j * 8 + t * 2;
        float bb0 = bias[e];
        float bb1 = bias[e + 1];
        #pragma unroll
        for (int i = 0; i < 4; i++) {
            int l = m0 + warp_m * 64 + i * 16 + g;
            *(float2*)&C[(size_t)l * DDIM + e] =
                make_float2(acc[i][j][0] + bb0, acc[i][j][1] + bb1);
            *(float2*)&C[(size_t)(l + 8) * DDIM + e] =
                make_float2(acc[i][j][2] + bb0, acc[i][j][3] + bb1);
        }
    }
}

// ---------------------------------------------------------------------------
// digit-reversed slot <-> frequency maps (DIF ordering of this implementation)
__device__ __forceinline__ int slot_to_freq(int p) {
    int k = 0;
    k |= ((p >> 12) & 1) << 0;
    k |= ((p >> 10) & 1) << 1;
    k |= ((p >> 11) & 1) << 2;
    k |= ((p >>  8) & 1) << 3;
    k |= ((p >>  9) & 1) << 4;
    k |= ((p >>  6) & 1) << 5;
    k |= ((p >>  7) & 1) << 6;
    k |= ((p >>  4) & 1) << 7;
    k |= ((p >>  5) & 1) << 8;
    k |= ((p >>  2) & 1) << 9;
    k |= ((p >>  3) & 1) << 10;
    k |= ((p >>  0) & 1) << 11;
    k |= ((p >>  1) & 1) << 12;
    return k;
}
__device__ __forceinline__ int freq_to_slot(int k) {
    int p = 0;
    p |= ((k >>  0) & 1) << 12;
    p |= ((k >>  1) & 1) << 10;
    p |= ((k >>  2) & 1) << 11;
    p |= ((k >>  3) & 1) << 8;
    p |= ((k >>  4) & 1) << 9;
    p |= ((k >>  5) & 1) << 6;
    p |= ((k >>  6) & 1) << 7;
    p |= ((k >>  7) & 1) << 4;
    p |= ((k >>  8) & 1) << 5;
    p |= ((k >>  9) & 1) << 2;
    p |= ((k >> 10) & 1) << 3;
    p |= ((k >> 11) & 1) << 0;
    p |= ((k >> 12) & 1) << 1;
    return p;
}

__global__ void init_kernel() {
    int i = blockIdx.x * blockDim.x + threadIdx.x;
    if (i < NF) {
        double ang = -2.0 * 3.141592653589793238462643 * (double)i / (double)NF;
        g_tw[i] = make_float2((float)cos(ang), (float)sin(ang));
        int k  = slot_to_freq(i);
        int kp = (NF - k) & (NF - 1);
        g_refl[i] = (unsigned short)freq_to_slot(kp);
    }
}

// ---------------------------------------------------------------------------
__global__ __launch_bounds__(256) void filter_kernel(
    const float* __restrict__ w1, const float* __restrict__ b1,
    const float* __restrict__ w2, const float* __restrict__ b2,
    const float* __restrict__ fb, const float* __restrict__ fd)
{
    __shared__ float pe[33];
    __shared__ float sact[64];
    const int l = blockIdx.x;
    const float t = (float)l * (1.0f / (float)(LSEQ - 1));
    const int tid = threadIdx.x;

    if (tid < 33) pe[tid] = sinf(t * (float)tid * 10.0f);
    __syncthreads();
    if (tid < 64) {
        float z = b1[tid];
        #pragma unroll
        for (int j = 0; j < 33; j++) z += pe[j] * w1[tid * 33 + j];
        sact[tid] = sinf(10.0f * z);
    }
    __syncthreads();

    for (int o = tid; o < 2 * DDIM; o += 256) {
        float acc = b2[o];
        #pragma unroll
        for (int i = 0; i < 64; i++) acc += sact[i] * w2[o * 64 + i];
        float dec = expf(-expf(fd[o]) * t);
        g_h[(size_t)o * LSEQ + l] = (acc * dec + fb[o]) * (1.0f / (float)LSEQ);
    }
}

// ---------------------------------------------------------------------------
// FFT pieces (8192-pt, 512 threads, split re/im padded smem)
__device__ __forceinline__ void fft_fwd_zp(float* __restrict__ SR, float* __restrict__ SI) {
    #pragma unroll
    for (int jj = 0; jj < 8; jj++) {
        int j  = threadIdx.x + jj * FFT_THREADS;
        int i0 = PADI(j), i1 = PADI(j + 4096);
        float ar = SR[i0], ai = SI[i0];
        float2 w = g_tw[j];
        SR[i1] = ar * w.x - ai * w.y;
        SI[i1] = ar * w.y + ai * w.x;
    }
    __syncthreads();
    #pragma unroll
    for (int st = 0; st < 6; st++) {
        const int lm  = 10 - 2 * st;
        const int m   = 1 << lm;
        const int str = 2048 >> lm;
        #pragma unroll
        for (int jj = 0; jj < 4; jj++) {
            int t = threadIdx.x + jj * FFT_THREADS;
            int q = t & (m - 1);
            int base = ((t >> lm) << (lm + 2)) | q;
            int i0 = PADI(base), i1 = PADI(base + m),
                i2 = PADI(base + 2 * m), i3 = PADI(base + 3 * m);
            float x0r = SR[i0], x0i = SI[i0];
            float x1r = SR[i1], x1i = SI[i1];
            float x2r = SR[i2], x2i = SI[i2];
            float x3r = SR[i3], x3i = SI[i3];
            float2 w1 = g_tw[q * str];
            float2 w2 = g_tw[2 * q * str];
            float2 w3 = g_tw[3 * q * str];
            float t0r = x0r + x2r, t0i = x0i + x2i;
            float t1r = x1r + x3r, t1i = x1i + x3i;
            float t2r = x0r - x2r, t2i = x0i - x2i;
            float t3r = x1i - x3i, t3i = x3r - x1r;
            SR[i0] = t0r + t1r; SI[i0] = t0i + t1i;
            float ur = t2r + t3r, ui = t2i + t3i;
            SR[i1] = ur * w1.x - ui * w1.y; SI[i1] = ur * w1.y + ui * w1.x;
            ur = t0r - t1r; ui = t0i - t1i;
            SR[i2] = ur * w2.x - ui * w2.y; SI[i2] = ur * w2.y + ui * w2.x;
            ur = t2r - t3r; ui = t2i - t3i;
            SR[i3] = ur * w3.x - ui * w3.y; SI[i3] = ur * w3.y + ui * w3.x;
        }
        __syncthreads();
    }
}

__device__ __forceinline__ void fft_inv_half(float* __restrict__ SR, float* __restrict__ SI) {
    #pragma unroll
    for (int st = 0; st < 6; st++) {
        const int lm  = 2 * st;
        const int m   = 1 << lm;
        const int str = 2048 >> lm;
        #pragma unroll
        for (int jj = 0; jj < 4; jj++) {
            int t = threadIdx.x + jj * FFT_THREADS;
            int q = t & (m - 1);
            int base = ((t >> lm) << (lm + 2)) | q;
            int i0 = PADI(base), i1 = PADI(base + m),
                i2 = PADI(base + 2 * m), i3 = PADI(base + 3 * m);
            float u0r = SR[i0], u0i = SI[i0];
            float u1r = SR[i1], u1i = SI[i1];
            float u2r = SR[i2], u2i = SI[i2];
            float u3r = SR[i3], u3i = SI[i3];
            float2 w1 = g_tw[q * str];
            float2 w2 = g_tw[2 * q * str];
            float2 w3 = g_tw[3 * q * str];
            float c1r = u1r * w1.x + u1i * w1.y, c1i = u1i * w1.x - u1r * w1.y;
            float c2r = u2r * w2.x + u2i * w2.y, c2i = u2i * w2.x - u2r * w2.y;
            float c3r = u3r * w3.x + u3i * w3.y, c3i = u3i * w3.x - u3r * w3.y;
            float s0r = u0r + c2r, s0i = u0i + c2i;
            float s1r = u0r - c2r, s1i = u0i - c2i;
            float s2r = c1r + c3r, s2i = c1i + c3i;
            float s3r = c1r - c3r, s3i = c1i - c3i;
            SR[i0] = s0r + s2r; SI[i0] = s0i + s2i;
            SR[i2] = s0r - s2r; SI[i2] = s0i - s2i;
            SR[i1] = s1r - s3i; SI[i1] = s1i + s3r;
            SR[i3] = s1r + s3i; SI[i3] = s1i - s3r;
        }
        __syncthreads();
    }
    #pragma unroll
    for (int jj = 0; jj < 8; jj++) {
        int j  = threadIdx.x + jj * FFT_THREADS;
        int i0 = PADI(j), i1 = PADI(j + 4096);
        float2 w = g_tw[j];
        float br = SR[i1], bi = SI[i1];
        float tr = br * w.x + bi * w.y;
        float ti = bi * w.x - br * w.y;
        SR[i0] += tr; SI[i0] += ti;
    }
    __syncthreads();
}

// ---------------------------------------------------------------------------
__global__ __launch_bounds__(FFT_THREADS) void hfft_kernel() {
    extern __shared__ float sm[];
    float* SR = sm;
    float* SI = sm + SM_HALF;
    const int c = blockIdx.x;
    const int n = c >> 9;
    const int dpair = c & (NPAIR - 1);
    const float* h0 = g_h + ((size_t)n * DDIM + 2 * dpair)     * LSEQ;
    const float* h1 = g_h + ((size_t)n * DDIM + 2 * dpair + 1) * LSEQ;

    for (int i = threadIdx.x; i < LSEQ; i += FFT_THREADS) {
        SR[PADI(i)] = h0[i]; SI[PADI(i)] = h1[i];
    }
    __syncthreads();
    fft_fwd_zp(SR, SI);

    float2* Ao = g_A + (size_t)c * NF;
    float2* Bo = g_B + (size_t)c * NF;
    for (int p = threadIdx.x; p < NF; p += FFT_THREADS) {
        int q = g_refl[p];
        float zpr = SR[PADI(p)], zpi = SI[PADI(p)];
        float zqr = SR[PADI(q)], zqi = SI[PADI(q)];
        float g0r = 0.5f * (zpr + zqr), g0i = 0.5f * (zpi - zqi);
        float g1r = 0.5f * (zpi + zqi), g1i = 0.5f * (zqr - zpr);
        Ao[p] = make_float2(0.5f * (g0r + g1r), 0.5f * (g0i + g1i));
        Bo[p] = make_float2(0.5f * (g0r - g1r), 0.5f * (g0i - g1i));
    }
}

// ---------------------------------------------------------------------------
__global__ __launch_bounds__(FFT_THREADS) void fftconv_kernel() {
    extern __shared__ float sm[];
    float* SR = sm;
    float* SI = sm + SM_HALF;
    const int c = blockIdx.x;
    const int b = c >> 9;
    const int dpair = c & (NPAIR - 1);
    const int ch0 = 2 * dpair, ch1 = ch0 + 1;
    const float inv = 1.0f / (float)NF;

    const float* v0 = &g_cv[((size_t)(b * 3 + 2) * DDIM + ch0) * LSEQ];
    const float* v1 = &g_cv[((size_t)(b * 3 + 2) * DDIM + ch1) * LSEQ];

    for (int i = threadIdx.x; i < LSEQ; i += FFT_THREADS) {
        SR[PADI(i)] = v0[i]; SI[PADI(i)] = v1[i];
    }
    __syncthreads();

    #pragma unroll 1
    for (int n = 0; n < 2; n++) {
        fft_fwd_zp(SR, SI);

        const float2* Ap = g_A + ((size_t)n * NPAIR + dpair) * NF;
        const float2* Bp = g_B + ((size_t)n * NPAIR + dpair) * NF;
        #pragma unroll
        for (int jj = 0; jj < 16; jj++) {
            int p = threadIdx.x + jj * FFT_THREADS;
            int q = g_refl[p];
            if (q < p) continue;
            int ip = PADI(p), iq = PADI(q);
            float zr = SR[ip], zi = SI[ip];
            float wr = SR[iq], wi = SI[iq];
            float2 a  = Ap[p];
            float2 bb = Bp[p];
            float ypr = a.x * zr - a.y * zi + bb.x * wr + bb.y * wi;
            float ypi = a.x * zi + a.y * zr + bb.y * wr - bb.x * wi;
            float yqr = a.x * wr + a.y * wi + bb.x * zr - bb.y * zi;
            float yqi = a.x * wi - a.y * wr - bb.x * zi - bb.y * zr;
            SR[ip] = ypr; SI[ip] = ypi;
            SR[iq] = yqr; SI[iq] = yqi;
        }
        __syncthreads();

        fft_inv_half(SR, SI);

        if (n == 0) {
            const float* xa = &g_cv[((size_t)(b * 3 + 0) * DDIM + ch0) * LSEQ];
            const float* xb = &g_cv[((size_t)(b * 3 + 0) * DDIM + ch1) * LSEQ];
            for (int l = threadIdx.x; l < LSEQ; l += FFT_THREADS) {
                int ip = PADI(l);
                SR[ip] = SR[ip] * inv * xa[l];
                SI[ip] = SI[ip] * inv * xb[l];
            }
            __syncthreads();
        } else {
            const float* xa = &g_cv[((size_t)(b * 3 + 1) * DDIM + ch0) * LSEQ];
            const float* xb = &g_cv[((size_t)(b * 3 + 1) * DDIM + ch1) * LSEQ];
            uint32_t* vh0 = g_vh + ((size_t)(b * DDIM + ch0)) * (LSEQ / 2);
            uint32_t* vl0 = g_vl + ((size_t)(b * DDIM + ch0)) * (LSEQ / 2);
            uint32_t* vh1 = g_vh + ((size_t)(b * DDIM + ch1)) * (LSEQ / 2);
            uint32_t* vl1 = g_vl + ((size_t)(b * DDIM + ch1)) * (LSEQ / 2);
            for (int l2 = threadIdx.x; l2 < LSEQ / 2; l2 += FFT_THREADS) {
                int l = 2 * l2;
                float y0a = SR[PADI(l)]     * inv * xa[l];
                float y0b = SR[PADI(l + 1)] * inv * xa[l + 1];
                float y1a = SI[PADI(l)]     * inv * xb[l];
                float y1b = SI[PADI(l + 1)] * inv * xb[l + 1];
                vh0[l2] = pack_hi(y0a, y0b); vl0[l2] = pack_lo(y0a, y0b);
                vh1[l2] = pack_hi(y1a, y1b); vl1[l2] = pack_lo(y1a, y1b);
            }
        }
    }
}

// ---------------------------------------------------------------------------
__global__ void conv3_kernel(const float* __restrict__ cw, const float* __restrict__ cb) {
    const int row = blockIdx.y;            // b*3072 + od
    const int od  = row % ODIM;
    const int l   = blockIdx.x * 256 + threadIdx.x;
    const float* r = g_res + (size_t)row * LSEQ;
    float left  = (l > 0)        ? r[l - 1] : 0.0f;
    float mid   = r[l];
    float right = (l < LSEQ - 1) ? r[l + 1] : 0.0f;
    float w0 = cw[od * 3], w1 = cw[od * 3 + 1], w2 = cw[od * 3 + 2];
    g_cv[(size_t)row * LSEQ + l] = w0 * left + w1 * mid + w2 * right + cb[od];
}

// ---------------------------------------------------------------------------
extern "C" void kernel_launch(void* const* d_in, const int* in_sizes, int n_in,
                              void* d_out, int out_size)
{
    const float* u          = (const float*)d_in[0];
    const float* w_in       = (const float*)d_in[1];
    const float* b_in       = (const float*)d_in[2];
    const float* conv_w     = (const float*)d_in[3];
    const float* conv_b     = (const float*)d_in[4];
    const float* w1         = (const float*)d_in[5];
    const float* b1         = (const float*)d_in[6];
    const float* w2         = (const float*)d_in[7];
    const float* b2         = (const float*)d_in[8];
    const float* filt_bias  = (const float*)d_in[9];
    const float* filt_decay = (const float*)d_in[10];
    const float* w_out      = (const float*)d_in[11];
    const float* b_out      = (const float*)d_in[12];
    float* out = (float*)d_out;

    static bool attr_set = false;
    if (!attr_set) {
        cudaFuncSetAttribute(hfft_kernel,    cudaFuncAttributeMaxDynamicSharedMemorySize, FFT_SMEM);
        cudaFuncSetAttribute(fftconv_kernel, cudaFuncAttributeMaxDynamicSharedMemorySize, FFT_SMEM);
        cudaFuncSetAttribute(gemm_in_mma,    cudaFuncAttributeMaxDynamicSharedMemorySize, GI_SMEM);
        cudaFuncSetAttribute(gemm_out_mma,   cudaFuncAttributeMaxDynamicSharedMemorySize, GO_SMEM);
        attr_set = true;
    }

    uint32_t *p_wh, *p_wl, *p_uh, *p_ul, *p_oh, *p_ol;
    cudaGetSymbolAddress((void**)&p_wh, g_wh);
    cudaGetSymbolAddress((void**)&p_wl, g_wl);
    cudaGetSymbolAddress((void**)&p_uh, g_uh);
    cudaGetSymbolAddress((void**)&p_ul, g_ul);
    cudaGetSymbolAddress((void**)&p_oh, g_oh);
    cudaGetSymbolAddress((void**)&p_ol, g_ol);

    // operand conversions + filter path (independent)
    cvt_split<<<(ODIM * DDIM / 2 + 255) / 256, 256>>>(w_in, p_wh, p_wl, ODIM * DDIM / 2);
    cvt_split<<<(BSZ * LSEQ * DDIM / 2 + 255) / 256, 256>>>(u, p_uh, p_ul, BSZ * LSEQ * DDIM / 2);
    cvt_split<<<(DDIM * DDIM / 2 + 255) / 256, 256>>>(w_out, p_oh, p_ol, DDIM * DDIM / 2);
    init_kernel<<<32, 256>>>();
    filter_kernel<<<LSEQ, 256>>>(w1, b1, w2, b2, filt_bias, filt_decay);
    hfft_kernel<<<2 * NPAIR, FFT_THREADS, FFT_SMEM>>>();

    // main path
    gemm_in_mma<<<dim3(LSEQ / 128, ODIM / 128, BSZ), 256, GI_SMEM>>>(b_in);
    conv3_kernel<<<dim3(LSEQ / 256, BSZ * ODIM), 256>>>(conv_w, conv_b);
    fftconv_kernel<<<BSZ * NPAIR, FFT_THREADS, FFT_SMEM>>>();
    gemm_out_mma<<<dim3(DDIM / 128, LSEQ / 128, BSZ), 256, GO_SMEM>>>(b_out, out);
}

// round 7
// speedup vs baseline: 3.7637x; 2.4150x over previous
#include <cuda_runtime.h>
#include <cuda_bf16.h>
#include <cstdint>
#include <cstddef>

// ---------------------------------------------------------------------------
// Hyena operator: B=2, L=4096, D=1024, ORDER=2, OD=3072
// Round 7: 2-CTA/SM GEMM pipelines (2-stage cp.async), filter path as GEMM,
// 1024-thread FFTs. hfft placed as launch #4 for profiler visibility.
// ---------------------------------------------------------------------------

#define LSEQ 4096
#define NF   8192
#define DDIM 1024
#define ODIM 3072
#define BSZ  2
#define NPAIR 512
#define FFT_THREADS 1024
#define PADI(i) ((i) + ((i) >> 5))
#define SM_HALF 8448
#define FFT_SMEM (2 * SM_HALF * 4)

// Scratch (device .bss — allocation-free)
__device__ float  g_res[(size_t)BSZ * ODIM * LSEQ];
__device__ float  g_cv [(size_t)BSZ * ODIM * LSEQ];
__device__ float  g_h  [(size_t)2   * DDIM * LSEQ];
__device__ float  g_sact[(size_t)LSEQ * 64];
__device__ float2 g_A  [(size_t)2 * NPAIR * NF];
__device__ float2 g_B  [(size_t)2 * NPAIR * NF];
__device__ float2 g_tw [NF];
__device__ unsigned short g_refl[NF];
// packed bf16 hi/lo operands (uint32 = 2 bf16)
__device__ uint32_t g_wh[(size_t)ODIM * DDIM / 2];
__device__ uint32_t g_wl[(size_t)ODIM * DDIM / 2];
__device__ uint32_t g_uh[(size_t)BSZ * LSEQ * DDIM / 2];
__device__ uint32_t g_ul[(size_t)BSZ * LSEQ * DDIM / 2];
__device__ uint32_t g_oh[(size_t)DDIM * DDIM / 2];
__device__ uint32_t g_ol[(size_t)DDIM * DDIM / 2];
__device__ uint32_t g_vh[(size_t)BSZ * DDIM * LSEQ / 2];
__device__ uint32_t g_vl[(size_t)BSZ * DDIM * LSEQ / 2];

// ---------------------------------------------------------------------------
__device__ __forceinline__ uint32_t smem_u32(const void* p) {
    uint32_t a;
    asm("{ .reg .u64 t; cvta.to.shared.u64 t, %1; cvt.u32.u64 %0, t; }" : "=r"(a) : "l"(p));
    return a;
}

#define LDSM_X4(r0, r1, r2, r3, addr) \
    asm volatile("ldmatrix.sync.aligned.m8n8.x4.shared.b16 {%0,%1,%2,%3}, [%4];" \
                 : "=r"(r0), "=r"(r1), "=r"(r2), "=r"(r3) : "r"(addr))
#define LDSM_X4_T(r0, r1, r2, r3, addr) \
    asm volatile("ldmatrix.sync.aligned.m8n8.x4.trans.shared.b16 {%0,%1,%2,%3}, [%4];" \
                 : "=r"(r0), "=r"(r1), "=r"(r2), "=r"(r3) : "r"(addr))
#define LDSM_X2(r0, r1, addr) \
    asm volatile("ldmatrix.sync.aligned.m8n8.x2.shared.b16 {%0,%1}, [%2];" \
                 : "=r"(r0), "=r"(r1) : "r"(addr))
#define CP_ASYNC16(dst, src) \
    asm volatile("cp.async.cg.shared.global [%0], [%1], 16;" :: "r"(dst), "l"(src))
#define CP_COMMIT() asm volatile("cp.async.commit_group;" ::: "memory")
#define CP_WAIT1()  asm volatile("cp.async.wait_group 1;" ::: "memory")

__device__ __forceinline__ void mma_bf16(float* c, const uint32_t* a, const uint32_t* b) {
    asm volatile(
        "mma.sync.aligned.m16n8k16.row.col.f32.bf16.bf16.f32 "
        "{%0,%1,%2,%3}, {%4,%5,%6,%7}, {%8,%9}, {%0,%1,%2,%3};"
        : "+f"(c[0]), "+f"(c[1]), "+f"(c[2]), "+f"(c[3])
        : "r"(a[0]), "r"(a[1]), "r"(a[2]), "r"(a[3]), "r"(b[0]), "r"(b[1]));
}

__device__ __forceinline__ uint32_t pack_hi(float x, float y) {
    __nv_bfloat16 hx = __float2bfloat16(x);
    __nv_bfloat16 hy = __float2bfloat16(y);
    return (uint32_t)__bfloat16_as_ushort(hx) | ((uint32_t)__bfloat16_as_ushort(hy) << 16);
}
__device__ __forceinline__ uint32_t pack_lo(float x, float y) {
    __nv_bfloat16 hx = __float2bfloat16(x);
    __nv_bfloat16 hy = __float2bfloat16(y);
    __nv_bfloat16 lx = __float2bfloat16(x - __bfloat162float(hx));
    __nv_bfloat16 ly = __float2bfloat16(y - __bfloat162float(hy));
    return (uint32_t)__bfloat16_as_ushort(lx) | ((uint32_t)__bfloat16_as_ushort(ly) << 16);
}

// fp32 -> packed bf16 hi/lo
__global__ void cvt_split(const float* __restrict__ src, uint32_t* __restrict__ hi,
                          uint32_t* __restrict__ lo, int n2) {
    int i = blockIdx.x * 256 + threadIdx.x;
    if (i < n2) {
        float2 v = ((const float2*)src)[i];
        hi[i] = pack_hi(v.x, v.y);
        lo[i] = pack_lo(v.x, v.y);
    }
}

// ---------------------------------------------------------------------------
// gemm_in: g_res[b,od,l] = sum_d w_in[od,d]*u[b,l,d] + b_in[od]
// CTA 128x128, 8 warps (2x4), BK=32, 2-stage cp.async, 2 CTAs/SM.
#define GI_STAGE 40960
#define GI_SMEM  (2 * GI_STAGE)

__global__ __launch_bounds__(256, 2) void gemm_in_mma(const float* __restrict__ bias)
{
    extern __shared__ char smem[];
    const uint32_t sb = smem_u32(smem);
    const int tid  = threadIdx.x;
    const int lane = tid & 31;
    const int wid  = tid >> 5;
    const int warp_m = wid >> 2;
    const int warp_n = wid & 3;

    const int b  = blockIdx.z;
    const int m0 = blockIdx.y * 128;   // od
    const int n0 = blockIdx.x * 128;   // l
    float* C = g_res + (size_t)b * ODIM * LSEQ;

    const int tile = tid >> 6;
    const int tloc = tid & 63;
    const char* gbase;
    if      (tile == 0) gbase = (const char*)g_wh + (size_t)m0 * 2048;
    else if (tile == 1) gbase = (const char*)g_wl + (size_t)m0 * 2048;
    else if (tile == 2) gbase = (const char*)g_uh + (size_t)(b * LSEQ + n0) * 2048;
    else                gbase = (const char*)g_ul + (size_t)(b * LSEQ + n0) * 2048;

    float acc[4][4][4];
    #pragma unroll
    for (int i = 0; i < 4; i++)
        #pragma unroll
        for (int j = 0; j < 4; j++)
            #pragma unroll
            for (int r = 0; r < 4; r++) acc[i][j][r] = 0.0f;

    const int a_off = ((lane & 7) + ((lane & 8) ? 8 : 0)) * 80 + ((lane & 16) ? 16 : 0);
    const int b_off = (lane & 7) * 80 + ((lane & 8) ? 16 : 0);

    #pragma unroll
    for (int p = 0; p < 2; p++) {
        #pragma unroll
        for (int o = 0; o < 8; o++) {
            int idx = tloc + o * 64, row = idx >> 2, c = idx & 3;
            uint32_t dst = sb + p * GI_STAGE + tile * 10240 + row * 80 + c * 16;
            CP_ASYNC16(dst, gbase + (size_t)row * 2048 + p * 64 + c * 16);
        }
        CP_COMMIT();
    }

    for (int ch = 0; ch < 32; ch++) {
        CP_WAIT1();
        __syncthreads();
        const uint32_t sbase = sb + (ch & 1) * GI_STAGE;

        #pragma unroll
        for (int k16 = 0; k16 < 2; k16++) {
            uint32_t bh[4][2], bl[4][2];
            #pragma unroll
            for (int j = 0; j < 4; j++) {
                uint32_t rb = sbase + 20480 + (warp_n * 32 + j * 8) * 80 + k16 * 32 + b_off;
                LDSM_X2(bh[j][0], bh[j][1], rb);
                LDSM_X2(bl[j][0], bl[j][1], rb + 10240);
            }
            #pragma unroll
            for (int i = 0; i < 4; i++) {
                uint32_t ah[4], al[4];
                uint32_t ra = sbase + (warp_m * 64 + i * 16) * 80 + k16 * 32 + a_off;
                LDSM_X4(ah[0], ah[1], ah[2], ah[3], ra);
                LDSM_X4(al[0], al[1], al[2], al[3], ra + 10240);
                #pragma unroll
                for (int j = 0; j < 4; j++) {
                    mma_bf16(acc[i][j], ah, bh[j]);
                    mma_bf16(acc[i][j], ah, bl[j]);
                    mma_bf16(acc[i][j], al, bh[j]);
                }
            }
        }

        __syncthreads();
        if (ch + 2 < 32) {
            #pragma unroll
            for (int o = 0; o < 8; o++) {
                int idx = tloc + o * 64, row = idx >> 2, c = idx & 3;
                uint32_t dst = sb + (ch & 1) * GI_STAGE + tile * 10240 + row * 80 + c * 16;
                CP_ASYNC16(dst, gbase + (size_t)row * 2048 + (ch + 2) * 64 + c * 16);
            }
        }
        CP_COMMIT();
    }

    const int g = lane >> 2;
    const int t = lane & 3;
    #pragma unroll
    for (int i = 0; i < 4; i++) {
        int od0 = m0 + warp_m * 64 + i * 16 + g;
        float bv0 = bias[od0];
        float bv1 = bias[od0 + 8];
        #pragma unroll
        for (int j = 0; j < 4; j++) {
            int l = n0 + warp_n * 32 + j * 8 + t * 2;
            *(float2*)&C[(size_t)od0 * LSEQ + l] =
                make_float2(acc[i][j][0] + bv0, acc[i][j][1] + bv0);
            *(float2*)&C[(size_t)(od0 + 8) * LSEQ + l] =
                make_float2(acc[i][j][2] + bv1, acc[i][j][3] + bv1);
        }
    }
}

// ---------------------------------------------------------------------------
// gemm_out: out[b,l,e] = sum_d v[b,d,l]*w_out[e,d] + b_out[e]
#define GO_A_LO  8704
#define GO_B_HI  17408
#define GO_B_LO  27648
#define GO_STAGE 37888
#define GO_SMEM  (2 * GO_STAGE)

__global__ __launch_bounds__(256, 2) void gemm_out_mma(const float* __restrict__ bias,
                                                       float* __restrict__ O)
{
    extern __shared__ char smem[];
    const uint32_t sb = smem_u32(smem);
    const int tid  = threadIdx.x;
    const int lane = tid & 31;
    const int wid  = tid >> 5;
    const int warp_m = wid >> 2;
    const int warp_n = wid & 3;

    const int b  = blockIdx.z;
    const int m0 = blockIdx.y * 128;   // l
    const int n0 = blockIdx.x * 128;   // e
    float* C = O + (size_t)b * LSEQ * DDIM;

    const int tile = tid >> 6;     // 0:v_hi 1:v_lo 2:wo_hi 3:wo_lo
    const int tloc = tid & 63;
    const char* gbase;
    if      (tile == 0) gbase = (const char*)g_vh + (size_t)(b * DDIM) * 8192 + (size_t)m0 * 2;
    else if (tile == 1) gbase = (const char*)g_vl + (size_t)(b * DDIM) * 8192 + (size_t)m0 * 2;
    else if (tile == 2) gbase = (const char*)g_oh + (size_t)n0 * 2048;
    else                gbase = (const char*)g_ol + (size_t)n0 * 2048;

    float acc[4][4][4];
    #pragma unroll
    for (int i = 0; i < 4; i++)
        #pragma unroll
        for (int j = 0; j < 4; j++)
            #pragma unroll
            for (int r = 0; r < 4; r++) acc[i][j][r] = 0.0f;

    const int at_off = ((lane & 7) + ((lane & 16) ? 8 : 0)) * 272 + ((lane & 8) ? 16 : 0);
    const int b_off  = (lane & 7) * 80 + ((lane & 8) ? 16 : 0);

    #pragma unroll
    for (int p = 0; p < 2; p++) {
        if (tile < 2) {
            #pragma unroll
            for (int o = 0; o < 8; o++) {
                int idx = tloc + o * 64, row = idx >> 4, c = idx & 15;
                uint32_t dst = sb + p * GO_STAGE + tile * GO_A_LO + row * 272 + c * 16;
                CP_ASYNC16(dst, gbase + (size_t)(p * 32 + row) * 8192 + c * 16);
            }
        } else {
            #pragma unroll
            for (int o = 0; o < 8; o++) {
                int idx = tloc + o * 64, row = idx >> 2, c = idx & 3;
                uint32_t dst = sb + p * GO_STAGE + GO_B_HI + (tile - 2) * 10240 + row * 80 + c * 16;
                CP_ASYNC16(dst, gbase + (size_t)row * 2048 + p * 64 + c * 16);
            }
        }
        CP_COMMIT();
    }

    for (int ch = 0; ch < 32; ch++) {
        CP_WAIT1();
        __syncthreads();
        const uint32_t sbase = sb + (ch & 1) * GO_STAGE;

        #pragma unroll
        for (int k16 = 0; k16 < 2; k16++) {
            uint32_t bh[4][2], bl[4][2];
            #pragma unroll
            for (int j = 0; j < 4; j++) {
                uint32_t rb = sbase + GO_B_HI + (warp_n * 32 + j * 8) * 80 + k16 * 32 + b_off;
                LDSM_X2(bh[j][0], bh[j][1], rb);
                LDSM_X2(bl[j][0], bl[j][1], rb + 10240);
            }
            #pragma unroll
            for (int i = 0; i < 4; i++) {
                uint32_t ah[4], al[4];
                uint32_t ra = sbase + k16 * 16 * 272 + (warp_m * 64 + i * 16) * 2 + at_off;
                LDSM_X4_T(ah[0], ah[1], ah[2], ah[3], ra);
                LDSM_X4_T(al[0], al[1], al[2], al[3], ra + GO_A_LO);
                #pragma unroll
                for (int j = 0; j < 4; j++) {
                    mma_bf16(acc[i][j], ah, bh[j]);
                    mma_bf16(acc[i][j], ah, bl[j]);
                    mma_bf16(acc[i][j], al, bh[j]);
                }
            }
        }

        __syncthreads();
        if (ch + 2 < 32) {
            if (tile < 2) {
                #pragma unroll
                for (int o = 0; o < 8; o++) {
                    int idx = tloc + o * 64, row = idx >> 4, c = idx & 15;
                    uint32_t dst = sb + (ch & 1) * GO_STAGE + tile * GO_A_LO + row * 272 + c * 16;
                    CP_ASYNC16(dst, gbase + (size_t)((ch + 2) * 32 + row) * 8192 + c * 16);
                }
            } else {
                #pragma unroll
                for (int o = 0; o < 8; o++) {
                    int idx = tloc + o * 64, row = idx >> 2, c = idx & 3;
                    uint32_t dst = sb + (ch & 1) * GO_STAGE + GO_B_HI + (tile - 2) * 10240 + row * 80 + c * 16;
                    CP_ASYNC16(dst, gbase + (size_t)row * 2048 + (ch + 2) * 64 + c * 16);
                }
            }
        }
        CP_COMMIT();
    }

    const int g = lane >> 2;
    const int t = lane & 3;
    #pragma unroll
    for (int j = 0; j < 4; j++) {
        int e = n0 + warp_n * 32 + j * 8 + t * 2;
        float bb0 = bias[e];
        float bb1 = bias[e + 1];
        #pragma unroll
        for (int i = 0; i < 4; i++) {
            int l = m0 + warp_m * 64 + i * 16 + g;
            *(float2*)&C[(size_t)l * DDIM + e] =
                make_float2(acc[i][j][0] + bb0, acc[i][j][1] + bb1);
            *(float2*)&C[(size_t)(l + 8) * DDIM + e] =
                make_float2(acc[i][j][2] + bb0, acc[i][j][3] + bb1);
        }
    }
}

// ---------------------------------------------------------------------------
// digit-reversed slot <-> frequency maps (DIF ordering of this implementation)
__device__ __forceinline__ int slot_to_freq(int p) {
    int k = 0;
    k |= ((p >> 12) & 1) << 0;
    k |= ((p >> 10) & 1) << 1;
    k |= ((p >> 11) & 1) << 2;
    k |= ((p >>  8) & 1) << 3;
    k |= ((p >>  9) & 1) << 4;
    k |= ((p >>  6) & 1) << 5;
    k |= ((p >>  7) & 1) << 6;
    k |= ((p >>  4) & 1) << 7;
    k |= ((p >>  5) & 1) << 8;
    k |= ((p >>  2) & 1) << 9;
    k |= ((p >>  3) & 1) << 10;
    k |= ((p >>  0) & 1) << 11;
    k |= ((p >>  1) & 1) << 12;
    return k;
}
__device__ __forceinline__ int freq_to_slot(int k) {
    int p = 0;
    p |= ((k >>  0) & 1) << 12;
    p |= ((k >>  1) & 1) << 10;
    p |= ((k >>  2) & 1) << 11;
    p |= ((k >>  3) & 1) << 8;
    p |= ((k >>  4) & 1) << 9;
    p |= ((k >>  5) & 1) << 6;
    p |= ((k >>  6) & 1) << 7;
    p |= ((k >>  7) & 1) << 4;
    p |= ((k >>  8) & 1) << 5;
    p |= ((k >>  9) & 1) << 2;
    p |= ((k >> 10) & 1) << 3;
    p |= ((k >> 11) & 1) << 0;
    p |= ((k >> 12) & 1) << 1;
    return p;
}

__global__ void init_kernel() {
    int i = blockIdx.x * blockDim.x + threadIdx.x;
    if (i < NF) {
        double ang = -2.0 * 3.141592653589793238462643 * (double)i / (double)NF;
        g_tw[i] = make_float2((float)cos(ang), (float)sin(ang));
        int k  = slot_to_freq(i);
        int kp = (NF - k) & (NF - 1);
        g_refl[i] = (unsigned short)freq_to_slot(kp);
    }
}

// ---------------------------------------------------------------------------
// Filter path: sact[l][u] = sin(FREQ * (pe(l) . w1[u] + b1[u]))
__global__ __launch_bounds__(256) void sact_kernel(
    const float* __restrict__ w1, const float* __restrict__ b1)
{
    int idx = blockIdx.x * 256 + threadIdx.x;   // l*64 + u
    int l = idx >> 6;
    int u = idx & 63;
    float t = (float)l * (1.0f / (float)(LSEQ - 1));
    float z = b1[u];
    #pragma unroll
    for (int j = 0; j < 33; j++) z += sinf(t * (float)j * 10.0f) * w1[u * 33 + j];
    g_sact[idx] = sinf(10.0f * z);
}

// filter GEMM: g_h[o][l] = ((sum_k w2[o,k]*sact[l,k] + b2[o]) * exp(-exp(fd[o])*t_l)
//                           + fb[o]) / L.   Tile 128(o) x 128(l), K=64.
__global__ __launch_bounds__(256) void filter_gemm(
    const float* __restrict__ w2, const float* __restrict__ b2,
    const float* __restrict__ fb, const float* __restrict__ fd)
{
    extern __shared__ float fsm[];
    float (*As)[128] = (float(*)[128])fsm;              // [k][o]
    float (*Bs)[128] = (float(*)[128])(fsm + 64 * 128); // [k][l]
    const int o0 = blockIdx.y * 128;
    const int l0 = blockIdx.x * 128;
    const int tid = threadIdx.x;
    const int tm = tid >> 4;       // o micro
    const int tn = tid & 15;       // l micro
    const int lrow = tid >> 1;
    const int lk   = (tid & 1) * 32;

    #pragma unroll
    for (int f = 0; f < 8; f++) {
        float4 a = *(const float4*)&w2[(size_t)(o0 + lrow) * 64 + lk + f * 4];
        As[lk + f * 4 + 0][lrow] = a.x; As[lk + f * 4 + 1][lrow] = a.y;
        As[lk + f * 4 + 2][lrow] = a.z; As[lk + f * 4 + 3][lrow] = a.w;
        float4 s = *(const float4*)&g_sact[(size_t)(l0 + lrow) * 64 + lk + f * 4];
        Bs[lk + f * 4 + 0][lrow] = s.x; Bs[lk + f * 4 + 1][lrow] = s.y;
        Bs[lk + f * 4 + 2][lrow] = s.z; Bs[lk + f * 4 + 3][lrow] = s.w;
    }
    __syncthreads();

    float acc[8][8];
    #pragma unroll
    for (int i = 0; i < 8; i++)
        #pragma unroll
        for (int j = 0; j < 8; j++) acc[i][j] = 0.0f;

    #pragma unroll
    for (int k = 0; k < 64; k++) {
        float4 ra0 = *(const float4*)&As[k][tm * 8];
        float4 ra1 = *(const float4*)&As[k][tm * 8 + 4];
        float4 rb0 = *(const float4*)&Bs[k][tn * 8];
        float4 rb1 = *(const float4*)&Bs[k][tn * 8 + 4];
        float ra[8] = {ra0.x, ra0.y, ra0.z, ra0.w, ra1.x, ra1.y, ra1.z, ra1.w};
        float rb[8] = {rb0.x, rb0.y, rb0.z, rb0.w, rb1.x, rb1.y, rb1.z, rb1.w};
        #pragma unroll
        for (int i = 0; i < 8; i++)
            #pragma unroll
            for (int j = 0; j < 8; j++) acc[i][j] += ra[i] * rb[j];
    }

    #pragma unroll
    for (int i = 0; i < 8; i++) {
        int o = o0 + tm * 8 + i;
        float ed  = expf(fd[o]);
        float bb  = b2[o];
        float fbo = fb[o];
        float v[8];
        #pragma unroll
        for (int j = 0; j < 8; j++) {
            int l = l0 + tn * 8 + j;
            float t = (float)l * (1.0f / (float)(LSEQ - 1));
            v[j] = ((acc[i][j] + bb) * expf(-ed * t) + fbo) * (1.0f / (float)LSEQ);
        }
        *(float4*)&g_h[(size_t)o * LSEQ + l0 + tn * 8]     = make_float4(v[0], v[1], v[2], v[3]);
        *(float4*)&g_h[(size_t)o * LSEQ + l0 + tn * 8 + 4] = make_float4(v[4], v[5], v[6], v[7]);
    }
}

// ---------------------------------------------------------------------------
// FFT pieces (8192-pt, 1024 threads, split re/im padded smem)
__device__ __forceinline__ void fft_fwd_zp(float* __restrict__ SR, float* __restrict__ SI) {
    #pragma unroll
    for (int jj = 0; jj < 4096 / FFT_THREADS; jj++) {
        int j  = threadIdx.x + jj * FFT_THREADS;
        int i0 = PADI(j), i1 = PADI(j + 4096);
        float ar = SR[i0], ai = SI[i0];
        float2 w = g_tw[j];
        SR[i1] = ar * w.x - ai * w.y;
        SI[i1] = ar * w.y + ai * w.x;
    }
    __syncthreads();
    #pragma unroll
    for (int st = 0; st < 6; st++) {
        const int lm  = 10 - 2 * st;
        const int m   = 1 << lm;
        const int str = 2048 >> lm;
        #pragma unroll
        for (int jj = 0; jj < 2048 / FFT_THREADS; jj++) {
            int t = threadIdx.x + jj * FFT_THREADS;
            int q = t & (m - 1);
            int base = ((t >> lm) << (lm + 2)) | q;
            int i0 = PADI(base), i1 = PADI(base + m),
                i2 = PADI(base + 2 * m), i3 = PADI(base + 3 * m);
            float x0r = SR[i0], x0i = SI[i0];
            float x1r = SR[i1], x1i = SI[i1];
            float x2r = SR[i2], x2i = SI[i2];
            float x3r = SR[i3], x3i = SI[i3];
            float2 w1 = g_tw[q * str];
            float2 w2 = g_tw[2 * q * str];
            float2 w3 = g_tw[3 * q * str];
            float t0r = x0r + x2r, t0i = x0i + x2i;
            float t1r = x1r + x3r, t1i = x1i + x3i;
            float t2r = x0r - x2r, t2i = x0i - x2i;
            float t3r = x1i - x3i, t3i = x3r - x1r;
            SR[i0] = t0r + t1r; SI[i0] = t0i + t1i;
            float ur = t2r + t3r, ui = t2i + t3i;
            SR[i1] = ur * w1.x - ui * w1.y; SI[i1] = ur * w1.y + ui * w1.x;
            ur = t0r - t1r; ui = t0i - t1i;
            SR[i2] = ur * w2.x - ui * w2.y; SI[i2] = ur * w2.y + ui * w2.x;
            ur = t2r - t3r; ui = t2i - t3i;
            SR[i3] = ur * w3.x - ui * w3.y; SI[i3] = ur * w3.y + ui * w3.x;
        }
        __syncthreads();
    }
}

__device__ __forceinline__ void fft_inv_half(float* __restrict__ SR, float* __restrict__ SI) {
    #pragma unroll
    for (int st = 0; st < 6; st++) {
        const int lm  = 2 * st;
        const int m   = 1 << lm;
        const int str = 2048 >> lm;
        #pragma unroll
        for (int jj = 0; jj < 2048 / FFT_THREADS; jj++) {
            int t = threadIdx.x + jj * FFT_THREADS;
            int q = t & (m - 1);
            int base = ((t >> lm) << (lm + 2)) | q;
            int i0 = PADI(base), i1 = PADI(base + m),
                i2 = PADI(base + 2 * m), i3 = PADI(base + 3 * m);
            float u0r = SR[i0], u0i = SI[i0];
            float u1r = SR[i1], u1i = SI[i1];
            float u2r = SR[i2], u2i = SI[i2];
            float u3r = SR[i3], u3i = SI[i3];
            float2 w1 = g_tw[q * str];
            float2 w2 = g_tw[2 * q * str];
            float2 w3 = g_tw[3 * q * str];
            float c1r = u1r * w1.x + u1i * w1.y, c1i = u1i * w1.x - u1r * w1.y;
            float c2r = u2r * w2.x + u2i * w2.y, c2i = u2i * w2.x - u2r * w2.y;
            float c3r = u3r * w3.x + u3i * w3.y, c3i = u3i * w3.x - u3r * w3.y;
            float s0r = u0r + c2r, s0i = u0i + c2i;
            float s1r = u0r - c2r, s1i = u0i - c2i;
            float s2r = c1r + c3r, s2i = c1i + c3i;
            float s3r = c1r - c3r, s3i = c1i - c3i;
            SR[i0] = s0r + s2r; SI[i0] = s0i + s2i;
            SR[i2] = s0r - s2r; SI[i2] = s0i - s2i;
            SR[i1] = s1r - s3i; SI[i1] = s1i + s3r;
            SR[i3] = s1r + s3i; SI[i3] = s1i - s3r;
        }
        __syncthreads();
    }
    #pragma unroll
    for (int jj = 0; jj < 4096 / FFT_THREADS; jj++) {
        int j  = threadIdx.x + jj * FFT_THREADS;
        int i0 = PADI(j), i1 = PADI(j + 4096);
        float2 w = g_tw[j];
        float br = SR[i1], bi = SI[i1];
        float tr = br * w.x + bi * w.y;
        float ti = bi * w.x - br * w.y;
        SR[i0] += tr; SI[i0] += ti;
    }
    __syncthreads();
}

// ---------------------------------------------------------------------------
__global__ __launch_bounds__(FFT_THREADS) void hfft_kernel() {
    extern __shared__ float sm[];
    float* SR = sm;
    float* SI = sm + SM_HALF;
    const int c = blockIdx.x;
    const int n = c >> 9;
    const int dpair = c & (NPAIR - 1);
    const float* h0 = g_h + ((size_t)n * DDIM + 2 * dpair)     * LSEQ;
    const float* h1 = g_h + ((size_t)n * DDIM + 2 * dpair + 1) * LSEQ;

    for (int i = threadIdx.x; i < LSEQ; i += FFT_THREADS) {
        SR[PADI(i)] = h0[i]; SI[PADI(i)] = h1[i];
    }
    __syncthreads();
    fft_fwd_zp(SR, SI);

    float2* Ao = g_A + (size_t)c * NF;
    float2* Bo = g_B + (size_t)c * NF;
    for (int p = threadIdx.x; p < NF; p += FFT_THREADS) {
        int q = g_refl[p];
        float zpr = SR[PADI(p)], zpi = SI[PADI(p)];
        float zqr = SR[PADI(q)], zqi = SI[PADI(q)];
        float g0r = 0.5f * (zpr + zqr), g0i = 0.5f * (zpi - zqi);
        float g1r = 0.5f * (zpi + zqi), g1i = 0.5f * (zqr - zpr);
        Ao[p] = make_float2(0.5f * (g0r + g1r), 0.5f * (g0i + g1i));
        Bo[p] = make_float2(0.5f * (g0r - g1r), 0.5f * (g0i - g1i));
    }
}

// ---------------------------------------------------------------------------
__global__ __launch_bounds__(FFT_THREADS) void fftconv_kernel() {
    extern __shared__ float sm[];
    float* SR = sm;
    float* SI = sm + SM_HALF;
    const int c = blockIdx.x;
    const int b = c >> 9;
    const int dpair = c & (NPAIR - 1);
    const int ch0 = 2 * dpair, ch1 = ch0 + 1;
    const float inv = 1.0f / (float)NF;

    const float* v0 = &g_cv[((size_t)(b * 3 + 2) * DDIM + ch0) * LSEQ];
    const float* v1 = &g_cv[((size_t)(b * 3 + 2) * DDIM + ch1) * LSEQ];

    for (int i = threadIdx.x; i < LSEQ; i += FFT_THREADS) {
        SR[PADI(i)] = v0[i]; SI[PADI(i)] = v1[i];
    }
    __syncthreads();

    #pragma unroll 1
    for (int n = 0; n < 2; n++) {
        fft_fwd_zp(SR, SI);

        const float2* Ap = g_A + ((size_t)n * NPAIR + dpair) * NF;
        const float2* Bp = g_B + ((size_t)n * NPAIR + dpair) * NF;
        #pragma unroll
        for (int jj = 0; jj < NF / FFT_THREADS; jj++) {
            int p = threadIdx.x + jj * FFT_THREADS;
            int q = g_refl[p];
            if (q < p) continue;
            int ip = PADI(p), iq = PADI(q);
            float zr = SR[ip], zi = SI[ip];
            float wr = SR[iq], wi = SI[iq];
            float2 a  = Ap[p];
            float2 bb = Bp[p];
            float ypr = a.x * zr - a.y * zi + bb.x * wr + bb.y * wi;
            float ypi = a.x * zi + a.y * zr + bb.y * wr - bb.x * wi;
            float yqr = a.x * wr + a.y * wi + bb.x * zr - bb.y * zi;
            float yqi = a.x * wi - a.y * wr - bb.x * zi - bb.y * zr;
            SR[ip] = ypr; SI[ip] = ypi;
            SR[iq] = yqr; SI[iq] = yqi;
        }
        __syncthreads();

        fft_inv_half(SR, SI);

        if (n == 0) {
            const float* xa = &g_cv[((size_t)(b * 3 + 0) * DDIM + ch0) * LSEQ];
            const float* xb = &g_cv[((size_t)(b * 3 + 0) * DDIM + ch1) * LSEQ];
            for (int l = threadIdx.x; l < LSEQ; l += FFT_THREADS) {
                int ip = PADI(l);
                SR[ip] = SR[ip] * inv * xa[l];
                SI[ip] = SI[ip] * inv * xb[l];
            }
            __syncthreads();
        } else {
            const float* xa = &g_cv[((size_t)(b * 3 + 1) * DDIM + ch0) * LSEQ];
            const float* xb = &g_cv[((size_t)(b * 3 + 1) * DDIM + ch1) * LSEQ];
            uint32_t* vh0 = g_vh + ((size_t)(b * DDIM + ch0)) * (LSEQ / 2);
            uint32_t* vl0 = g_vl + ((size_t)(b * DDIM + ch0)) * (LSEQ / 2);
            uint32_t* vh1 = g_vh + ((size_t)(b * DDIM + ch1)) * (LSEQ / 2);
            uint32_t* vl1 = g_vl + ((size_t)(b * DDIM + ch1)) * (LSEQ / 2);
            for (int l2 = threadIdx.x; l2 < LSEQ / 2; l2 += FFT_THREADS) {
                int l = 2 * l2;
                float y0a = SR[PADI(l)]     * inv * xa[l];
                float y0b = SR[PADI(l + 1)] * inv * xa[l + 1];
                float y1a = SI[PADI(l)]     * inv * xb[l];
                float y1b = SI[PADI(l + 1)] * inv * xb[l + 1];
                vh0[l2] = pack_hi(y0a, y0b); vl0[l2] = pack_lo(y0a, y0b);
                vh1[l2] = pack_hi(y1a, y1b); vl1[l2] = pack_lo(y1a, y1b);
            }
        }
    }
}

// ---------------------------------------------------------------------------
__global__ void conv3_kernel(const float* __restrict__ cw, const float* __restrict__ cb) {
    const int row = blockIdx.y;            // b*3072 + od
    const int od  = row % ODIM;
    const int l   = blockIdx.x * 256 + threadIdx.x;
    const float* r = g_res + (size_t)row * LSEQ;
    float left  = (l > 0)        ? r[l - 1] : 0.0f;
    float mid   = r[l];
    float right = (l < LSEQ - 1) ? r[l + 1] : 0.0f;
    float w0 = cw[od * 3], w1 = cw[od * 3 + 1], w2 = cw[od * 3 + 2];
    g_cv[(size_t)row * LSEQ + l] = w0 * left + w1 * mid + w2 * right + cb[od];
}

// ---------------------------------------------------------------------------
extern "C" void kernel_launch(void* const* d_in, const int* in_sizes, int n_in,
                              void* d_out, int out_size)
{
    const float* u          = (const float*)d_in[0];
    const float* w_in       = (const float*)d_in[1];
    const float* b_in       = (const float*)d_in[2];
    const float* conv_w     = (const float*)d_in[3];
    const float* conv_b     = (const float*)d_in[4];
    const float* w1         = (const float*)d_in[5];
    const float* b1         = (const float*)d_in[6];
    const float* w2         = (const float*)d_in[7];
    const float* b2         = (const float*)d_in[8];
    const float* filt_bias  = (const float*)d_in[9];
    const float* filt_decay = (const float*)d_in[10];
    const float* w_out      = (const float*)d_in[11];
    const float* b_out      = (const float*)d_in[12];
    float* out = (float*)d_out;

    static bool attr_set = false;
    if (!attr_set) {
        cudaFuncSetAttribute(hfft_kernel,    cudaFuncAttributeMaxDynamicSharedMemorySize, FFT_SMEM);
        cudaFuncSetAttribute(fftconv_kernel, cudaFuncAttributeMaxDynamicSharedMemorySize, FFT_SMEM);
        cudaFuncSetAttribute(gemm_in_mma,    cudaFuncAttributeMaxDynamicSharedMemorySize, GI_SMEM);
        cudaFuncSetAttribute(gemm_out_mma,   cudaFuncAttributeMaxDynamicSharedMemorySize, GO_SMEM);
        cudaFuncSetAttribute(filter_gemm,    cudaFuncAttributeMaxDynamicSharedMemorySize, 65536);
        attr_set = true;
    }

    uint32_t *p_wh, *p_wl, *p_uh, *p_ul, *p_oh, *p_ol;
    cudaGetSymbolAddress((void**)&p_wh, g_wh);
    cudaGetSymbolAddress((void**)&p_wl, g_wl);
    cudaGetSymbolAddress((void**)&p_uh, g_uh);
    cudaGetSymbolAddress((void**)&p_ul, g_ul);
    cudaGetSymbolAddress((void**)&p_oh, g_oh);
    cudaGetSymbolAddress((void**)&p_ol, g_ol);

    // Filter path first (hfft is launch #4 for the profiler window)
    init_kernel<<<32, 256>>>();
    sact_kernel<<<LSEQ * 64 / 256, 256>>>(w1, b1);
    filter_gemm<<<dim3(LSEQ / 128, 2 * DDIM / 128), 256, 65536>>>(w2, b2, filt_bias, filt_decay);
    hfft_kernel<<<2 * NPAIR, FFT_THREADS, FFT_SMEM>>>();

    // Operand conversions
    cvt_split<<<(ODIM * DDIM / 2 + 255) / 256, 256>>>(w_in, p_wh, p_wl, ODIM * DDIM / 2);
    cvt_split<<<(BSZ * LSEQ * DDIM / 2 + 255) / 256, 256>>>(u, p_uh, p_ul, BSZ * LSEQ * DDIM / 2);
    cvt_split<<<(DDIM * DDIM / 2 + 255) / 256, 256>>>(w_out, p_oh, p_ol, DDIM * DDIM / 2);

    // Main path
    gemm_in_mma<<<dim3(LSEQ / 128, ODIM / 128, BSZ), 256, GI_SMEM>>>(b_in);
    conv3_kernel<<<dim3(LSEQ / 256, BSZ * ODIM), 256>>>(conv_w, conv_b);
    fftconv_kernel<<<BSZ * NPAIR, FFT_THREADS, FFT_SMEM>>>();
    gemm_out_mma<<<dim3(DDIM / 128, LSEQ / 128, BSZ), 256, GO_SMEM>>>(b_out, out);
}

// round 8
// speedup vs baseline: 3.7648x; 1.0003x over previous
#include <cuda_runtime.h>
#include <cuda_bf16.h>
#include <cstdint>
#include <cstddef>

// ---------------------------------------------------------------------------
// Hyena operator: B=2, L=4096, D=1024, ORDER=2, OD=3072
// Round 7: 2-CTA/SM GEMM pipelines (2-stage cp.async), filter path as GEMM,
// 1024-thread FFTs. hfft placed as launch #4 for profiler visibility.
// ---------------------------------------------------------------------------

#define LSEQ 4096
#define NF   8192
#define DDIM 1024
#define ODIM 3072
#define BSZ  2
#define NPAIR 512
#define FFT_THREADS 1024
#define PADI(i) ((i) + ((i) >> 5))
#define SM_HALF 8448
#define FFT_SMEM (2 * SM_HALF * 4)

// Scratch (device .bss — allocation-free)
__device__ float  g_res[(size_t)BSZ * ODIM * LSEQ];
__device__ float  g_cv [(size_t)BSZ * ODIM * LSEQ];
__device__ float  g_h  [(size_t)2   * DDIM * LSEQ];
__device__ float  g_sact[(size_t)LSEQ * 64];
__device__ float2 g_A  [(size_t)2 * NPAIR * NF];
__device__ float2 g_B  [(size_t)2 * NPAIR * NF];
__device__ float2 g_tw [NF];
__device__ unsigned short g_refl[NF];
// packed bf16 hi/lo operands (uint32 = 2 bf16)
__device__ uint32_t g_wh[(size_t)ODIM * DDIM / 2];
__device__ uint32_t g_wl[(size_t)ODIM * DDIM / 2];
__device__ uint32_t g_uh[(size_t)BSZ * LSEQ * DDIM / 2];
__device__ uint32_t g_ul[(size_t)BSZ * LSEQ * DDIM / 2];
__device__ uint32_t g_oh[(size_t)DDIM * DDIM / 2];
__device__ uint32_t g_ol[(size_t)DDIM * DDIM / 2];
__device__ uint32_t g_vh[(size_t)BSZ * DDIM * LSEQ / 2];
__device__ uint32_t g_vl[(size_t)BSZ * DDIM * LSEQ / 2];

// ---------------------------------------------------------------------------
__device__ __forceinline__ uint32_t smem_u32(const void* p) {
    uint32_t a;
    asm("{ .reg .u64 t; cvta.to.shared.u64 t, %1; cvt.u32.u64 %0, t; }" : "=r"(a) : "l"(p));
    return a;
}

#define LDSM_X4(r0, r1, r2, r3, addr) \
    asm volatile("ldmatrix.sync.aligned.m8n8.x4.shared.b16 {%0,%1,%2,%3}, [%4];" \
                 : "=r"(r0), "=r"(r1), "=r"(r2), "=r"(r3) : "r"(addr))
#define LDSM_X4_T(r0, r1, r2, r3, addr) \
    asm volatile("ldmatrix.sync.aligned.m8n8.x4.trans.shared.b16 {%0,%1,%2,%3}, [%4];" \
                 : "=r"(r0), "=r"(r1), "=r"(r2), "=r"(r3) : "r"(addr))
#define LDSM_X2(r0, r1, addr) \
    asm volatile("ldmatrix.sync.aligned.m8n8.x2.shared.b16 {%0,%1}, [%2];" \
                 : "=r"(r0), "=r"(r1) : "r"(addr))
#define CP_ASYNC16(dst, src) \
    asm volatile("cp.async.cg.shared.global [%0], [%1], 16;" :: "r"(dst), "l"(src))
#define CP_COMMIT() asm volatile("cp.async.commit_group;" ::: "memory")
#define CP_WAIT1()  asm volatile("cp.async.wait_group 1;" ::: "memory")

__device__ __forceinline__ void mma_bf16(float* c, const uint32_t* a, const uint32_t* b) {
    asm volatile(
        "mma.sync.aligned.m16n8k16.row.col.f32.bf16.bf16.f32 "
        "{%0,%1,%2,%3}, {%4,%5,%6,%7}, {%8,%9}, {%0,%1,%2,%3};"
        : "+f"(c[0]), "+f"(c[1]), "+f"(c[2]), "+f"(c[3])
        : "r"(a[0]), "r"(a[1]), "r"(a[2]), "r"(a[3]), "r"(b[0]), "r"(b[1]));
}

__device__ __forceinline__ uint32_t pack_hi(float x, float y) {
    __nv_bfloat16 hx = __float2bfloat16(x);
    __nv_bfloat16 hy = __float2bfloat16(y);
    return (uint32_t)__bfloat16_as_ushort(hx) | ((uint32_t)__bfloat16_as_ushort(hy) << 16);
}
__device__ __forceinline__ uint32_t pack_lo(float x, float y) {
    __nv_bfloat16 hx = __float2bfloat16(x);
    __nv_bfloat16 hy = __float2bfloat16(y);
    __nv_bfloat16 lx = __float2bfloat16(x - __bfloat162float(hx));
    __nv_bfloat16 ly = __float2bfloat16(y - __bfloat162float(hy));
    return (uint32_t)__bfloat16_as_ushort(lx) | ((uint32_t)__bfloat16_as_ushort(ly) << 16);
}

// fp32 -> packed bf16 hi/lo
__global__ void cvt_split(const float* __restrict__ src, uint32_t* __restrict__ hi,
                          uint32_t* __restrict__ lo, int n2) {
    int i = blockIdx.x * 256 + threadIdx.x;
    if (i < n2) {
        float2 v = ((const float2*)src)[i];
        hi[i] = pack_hi(v.x, v.y);
        lo[i] = pack_lo(v.x, v.y);
    }
}

// ---------------------------------------------------------------------------
// gemm_in: g_res[b,od,l] = sum_d w_in[od,d]*u[b,l,d] + b_in[od]
// CTA 128x128, 8 warps (2x4), BK=32, 2-stage cp.async, 2 CTAs/SM.
#define GI_STAGE 40960
#define GI_SMEM  (2 * GI_STAGE)

__global__ __launch_bounds__(256, 2) void gemm_in_mma(const float* __restrict__ bias)
{
    extern __shared__ char smem[];
    const uint32_t sb = smem_u32(smem);
    const int tid  = threadIdx.x;
    const int lane = tid & 31;
    const int wid  = tid >> 5;
    const int warp_m = wid >> 2;
    const int warp_n = wid & 3;

    const int b  = blockIdx.z;
    const int m0 = blockIdx.y * 128;   // od
    const int n0 = blockIdx.x * 128;   // l
    float* C = g_res + (size_t)b * ODIM * LSEQ;

    const int tile = tid >> 6;
    const int tloc = tid & 63;
    const char* gbase;
    if      (tile == 0) gbase = (const char*)g_wh + (size_t)m0 * 2048;
    else if (tile == 1) gbase = (const char*)g_wl + (size_t)m0 * 2048;
    else if (tile == 2) gbase = (const char*)g_uh + (size_t)(b * LSEQ + n0) * 2048;
    else                gbase = (const char*)g_ul + (size_t)(b * LSEQ + n0) * 2048;

    float acc[4][4][4];
    #pragma unroll
    for (int i = 0; i < 4; i++)
        #pragma unroll
        for (int j = 0; j < 4; j++)
            #pragma unroll
            for (int r = 0; r < 4; r++) acc[i][j][r] = 0.0f;

    const int a_off = ((lane & 7) + ((lane & 8) ? 8 : 0)) * 80 + ((lane & 16) ? 16 : 0);
    const int b_off = (lane & 7) * 80 + ((lane & 8) ? 16 : 0);

    #pragma unroll
    for (int p = 0; p < 2; p++) {
        #pragma unroll
        for (int o = 0; o < 8; o++) {
            int idx = tloc + o * 64, row = idx >> 2, c = idx & 3;
            uint32_t dst = sb + p * GI_STAGE + tile * 10240 + row * 80 + c * 16;
            CP_ASYNC16(dst, gbase + (size_t)row * 2048 + p * 64 + c * 16);
        }
        CP_COMMIT();
    }

    for (int ch = 0; ch < 32; ch++) {
        CP_WAIT1();
        __syncthreads();
        const uint32_t sbase = sb + (ch & 1) * GI_STAGE;

        #pragma unroll
        for (int k16 = 0; k16 < 2; k16++) {
            uint32_t bh[4][2], bl[4][2];
            #pragma unroll
            for (int j = 0; j < 4; j++) {
                uint32_t rb = sbase + 20480 + (warp_n * 32 + j * 8) * 80 + k16 * 32 + b_off;
                LDSM_X2(bh[j][0], bh[j][1], rb);
                LDSM_X2(bl[j][0], bl[j][1], rb + 10240);
            }
            #pragma unroll
            for (int i = 0; i < 4; i++) {
                uint32_t ah[4], al[4];
                uint32_t ra = sbase + (warp_m * 64 + i * 16) * 80 + k16 * 32 + a_off;
                LDSM_X4(ah[0], ah[1], ah[2], ah[3], ra);
                LDSM_X4(al[0], al[1], al[2], al[3], ra + 10240);
                #pragma unroll
                for (int j = 0; j < 4; j++) {
                    mma_bf16(acc[i][j], ah, bh[j]);
                    mma_bf16(acc[i][j], ah, bl[j]);
                    mma_bf16(acc[i][j], al, bh[j]);
                }
            }
        }

        __syncthreads();
        if (ch + 2 < 32) {
            #pragma unroll
            for (int o = 0; o < 8; o++) {
                int idx = tloc + o * 64, row = idx >> 2, c = idx & 3;
                uint32_t dst = sb + (ch & 1) * GI_STAGE + tile * 10240 + row * 80 + c * 16;
                CP_ASYNC16(dst, gbase + (size_t)row * 2048 + (ch + 2) * 64 + c * 16);
            }
        }
        CP_COMMIT();
    }

    const int g = lane >> 2;
    const int t = lane & 3;
    #pragma unroll
    for (int i = 0; i < 4; i++) {
        int od0 = m0 + warp_m * 64 + i * 16 + g;
        float bv0 = bias[od0];
        float bv1 = bias[od0 + 8];
        #pragma unroll
        for (int j = 0; j < 4; j++) {
            int l = n0 + warp_n * 32 + j * 8 + t * 2;
            *(float2*)&C[(size_t)od0 * LSEQ + l] =
                make_float2(acc[i][j][0] + bv0, acc[i][j][1] + bv0);
            *(float2*)&C[(size_t)(od0 + 8) * LSEQ + l] =
                make_float2(acc[i][j][2] + bv1, acc[i][j][3] + bv1);
        }
    }
}

// ---------------------------------------------------------------------------
// gemm_out: out[b,l,e] = sum_d v[b,d,l]*w_out[e,d] + b_out[e]
#define GO_A_LO  8704
#define GO_B_HI  17408
#define GO_B_LO  27648
#define GO_STAGE 37888
#define GO_SMEM  (2 * GO_STAGE)

__global__ __launch_bounds__(256, 2) void gemm_out_mma(const float* __restrict__ bias,
                                                       float* __restrict__ O)
{
    extern __shared__ char smem[];
    const uint32_t sb = smem_u32(smem);
    const int tid  = threadIdx.x;
    const int lane = tid & 31;
    const int wid  = tid >> 5;
    const int warp_m = wid >> 2;
    const int warp_n = wid & 3;

    const int b  = blockIdx.z;
    const int m0 = blockIdx.y * 128;   // l
    const int n0 = blockIdx.x * 128;   // e
    float* C = O + (size_t)b * LSEQ * DDIM;

    const int tile = tid >> 6;     // 0:v_hi 1:v_lo 2:wo_hi 3:wo_lo
    const int tloc = tid & 63;
    const char* gbase;
    if      (tile == 0) gbase = (const char*)g_vh + (size_t)(b * DDIM) * 8192 + (size_t)m0 * 2;
    else if (tile == 1) gbase = (const char*)g_vl + (size_t)(b * DDIM) * 8192 + (size_t)m0 * 2;
    else if (tile == 2) gbase = (const char*)g_oh + (size_t)n0 * 2048;
    else                gbase = (const char*)g_ol + (size_t)n0 * 2048;

    float acc[4][4][4];
    #pragma unroll
    for (int i = 0; i < 4; i++)
        #pragma unroll
        for (int j = 0; j < 4; j++)
            #pragma unroll
            for (int r = 0; r < 4; r++) acc[i][j][r] = 0.0f;

    const int at_off = ((lane & 7) + ((lane & 16) ? 8 : 0)) * 272 + ((lane & 8) ? 16 : 0);
    const int b_off  = (lane & 7) * 80 + ((lane & 8) ? 16 : 0);

    #pragma unroll
    for (int p = 0; p < 2; p++) {
        if (tile < 2) {
            #pragma unroll
            for (int o = 0; o < 8; o++) {
                int idx = tloc + o * 64, row = idx >> 4, c = idx & 15;
                uint32_t dst = sb + p * GO_STAGE + tile * GO_A_LO + row * 272 + c * 16;
                CP_ASYNC16(dst, gbase + (size_t)(p * 32 + row) * 8192 + c * 16);
            }
        } else {
            #pragma unroll
            for (int o = 0; o < 8; o++) {
                int idx = tloc + o * 64, row = idx >> 2, c = idx & 3;
                uint32_t dst = sb + p * GO_STAGE + GO_B_HI + (tile - 2) * 10240 + row * 80 + c * 16;
                CP_ASYNC16(dst, gbase + (size_t)row * 2048 + p * 64 + c * 16);
            }
        }
        CP_COMMIT();
    }

    for (int ch = 0; ch < 32; ch++) {
        CP_WAIT1();
        __syncthreads();
        const uint32_t sbase = sb + (ch & 1) * GO_STAGE;

        #pragma unroll
        for (int k16 = 0; k16 < 2; k16++) {
            uint32_t bh[4][2], bl[4][2];
            #pragma unroll
            for (int j = 0; j < 4; j++) {
                uint32_t rb = sbase + GO_B_HI + (warp_n * 32 + j * 8) * 80 + k16 * 32 + b_off;
                LDSM_X2(bh[j][0], bh[j][1], rb);
                LDSM_X2(bl[j][0], bl[j][1], rb + 10240);
            }
            #pragma unroll
            for (int i = 0; i < 4; i++) {
                uint32_t ah[4], al[4];
                uint32_t ra = sbase + k16 * 16 * 272 + (warp_m * 64 + i * 16) * 2 + at_off;
                LDSM_X4_T(ah[0], ah[1], ah[2], ah[3], ra);
                LDSM_X4_T(al[0], al[1], al[2], al[3], ra + GO_A_LO);
                #pragma unroll
                for (int j = 0; j < 4; j++) {
                    mma_bf16(acc[i][j], ah, bh[j]);
                    mma_bf16(acc[i][j], ah, bl[j]);
                    mma_bf16(acc[i][j], al, bh[j]);
                }
            }
        }

        __syncthreads();
        if (ch + 2 < 32) {
            if (tile < 2) {
                #pragma unroll
                for (int o = 0; o < 8; o++) {
                    int idx = tloc + o * 64, row = idx >> 4, c = idx & 15;
                    uint32_t dst = sb + (ch & 1) * GO_STAGE + tile * GO_A_LO + row * 272 + c * 16;
                    CP_ASYNC16(dst, gbase + (size_t)((ch + 2) * 32 + row) * 8192 + c * 16);
                }
            } else {
                #pragma unroll
                for (int o = 0; o < 8; o++) {
                    int idx = tloc + o * 64, row = idx >> 2, c = idx & 3;
                    uint32_t dst = sb + (ch & 1) * GO_STAGE + GO_B_HI + (tile - 2) * 10240 + row * 80 + c * 16;
                    CP_ASYNC16(dst, gbase + (size_t)row * 2048 + (ch + 2) * 64 + c * 16);
                }
            }
        }
        CP_COMMIT();
    }

    const int g = lane >> 2;
    const int t = lane & 3;
    #pragma unroll
    for (int j = 0; j < 4; j++) {
        int e = n0 + warp_n * 32 + j * 8 + t * 2;
        float bb0 = bias[e];
        float bb1 = bias[e + 1];
        #pragma unroll
        for (int i = 0; i < 4; i++) {
            int l = m0 + warp_m * 64 + i * 16 + g;
            *(float2*)&C[(size_t)l * DDIM + e] =
                make_float2(acc[i][j][0] + bb0, acc[i][j][1] + bb1);
            *(float2*)&C[(size_t)(l + 8) * DDIM + e] =
                make_float2(acc[i][j][2] + bb0, acc[i][j][3] + bb1);
        }
    }
}

// ---------------------------------------------------------------------------
// digit-reversed slot <-> frequency maps (DIF ordering of this implementation)
__device__ __forceinline__ int slot_to_freq(int p) {
    int k = 0;
    k |= ((p >> 12) & 1) << 0;
    k |= ((p >> 10) & 1) << 1;
    k |= ((p >> 11) & 1) << 2;
    k |= ((p >>  8) & 1) << 3;
    k |= ((p >>  9) & 1) << 4;
    k |= ((p >>  6) & 1) << 5;
    k |= ((p >>  7) & 1) << 6;
    k |= ((p >>  4) & 1) << 7;
    k |= ((p >>  5) & 1) << 8;
    k |= ((p >>  2) & 1) << 9;
    k |= ((p >>  3) & 1) << 10;
    k |= ((p >>  0) & 1) << 11;
    k |= ((p >>  1) & 1) << 12;
    return k;
}
__device__ __forceinline__ int freq_to_slot(int k) {
    int p = 0;
    p |= ((k >>  0) & 1) << 12;
    p |= ((k >>  1) & 1) << 10;
    p |= ((k >>  2) & 1) << 11;
    p |= ((k >>  3) & 1) << 8;
    p |= ((k >>  4) & 1) << 9;
    p |= ((k >>  5) & 1) << 6;
    p |= ((k >>  6) & 1) << 7;
    p |= ((k >>  7) & 1) << 4;
    p |= ((k >>  8) & 1) << 5;
    p |= ((k >>  9) & 1) << 2;
    p |= ((k >> 10) & 1) << 3;
    p |= ((k >> 11) & 1) << 0;
    p |= ((k >> 12) & 1) << 1;
    return p;
}

__global__ void init_kernel() {
    int i = blockIdx.x * blockDim.x + threadIdx.x;
    if (i < NF) {
        double ang = -2.0 * 3.141592653589793238462643 * (double)i / (double)NF;
        g_tw[i] = make_float2((float)cos(ang), (float)sin(ang));
        int k  = slot_to_freq(i);
        int kp = (NF - k) & (NF - 1);
        g_refl[i] = (unsigned short)freq_to_slot(kp);
    }
}

// ---------------------------------------------------------------------------
// Filter path: sact[l][u] = sin(FREQ * (pe(l) . w1[u] + b1[u]))
__global__ __launch_bounds__(256) void sact_kernel(
    const float* __restrict__ w1, const float* __restrict__ b1)
{
    int idx = blockIdx.x * 256 + threadIdx.x;   // l*64 + u
    int l = idx >> 6;
    int u = idx & 63;
    float t = (float)l * (1.0f / (float)(LSEQ - 1));
    float z = b1[u];
    #pragma unroll
    for (int j = 0; j < 33; j++) z += sinf(t * (float)j * 10.0f) * w1[u * 33 + j];
    g_sact[idx] = sinf(10.0f * z);
}

// filter GEMM: g_h[o][l] = ((sum_k w2[o,k]*sact[l,k] + b2[o]) * exp(-exp(fd[o])*t_l)
//                           + fb[o]) / L.   Tile 128(o) x 128(l), K=64.
__global__ __launch_bounds__(256) void filter_gemm(
    const float* __restrict__ w2, const float* __restrict__ b2,
    const float* __restrict__ fb, const float* __restrict__ fd)
{
    extern __shared__ float fsm[];
    float (*As)[128] = (float(*)[128])fsm;              // [k][o]
    float (*Bs)[128] = (float(*)[128])(fsm + 64 * 128); // [k][l]
    const int o0 = blockIdx.y * 128;
    const int l0 = blockIdx.x * 128;
    const int tid = threadIdx.x;
    const int tm = tid >> 4;       // o micro
    const int tn = tid & 15;       // l micro
    const int lrow = tid >> 1;
    const int lk   = (tid & 1) * 32;

    #pragma unroll
    for (int f = 0; f < 8; f++) {
        float4 a = *(const float4*)&w2[(size_t)(o0 + lrow) * 64 + lk + f * 4];
        As[lk + f * 4 + 0][lrow] = a.x; As[lk + f * 4 + 1][lrow] = a.y;
        As[lk + f * 4 + 2][lrow] = a.z; As[lk + f * 4 + 3][lrow] = a.w;
        float4 s = *(const float4*)&g_sact[(size_t)(l0 + lrow) * 64 + lk + f * 4];
        Bs[lk + f * 4 + 0][lrow] = s.x; Bs[lk + f * 4 + 1][lrow] = s.y;
        Bs[lk + f * 4 + 2][lrow] = s.z; Bs[lk + f * 4 + 3][lrow] = s.w;
    }
    __syncthreads();

    float acc[8][8];
    #pragma unroll
    for (int i = 0; i < 8; i++)
        #pragma unroll
        for (int j = 0; j < 8; j++) acc[i][j] = 0.0f;

    #pragma unroll
    for (int k = 0; k < 64; k++) {
        float4 ra0 = *(const float4*)&As[k][tm * 8];
        float4 ra1 = *(const float4*)&As[k][tm * 8 + 4];
        float4 rb0 = *(const float4*)&Bs[k][tn * 8];
        float4 rb1 = *(const float4*)&Bs[k][tn * 8 + 4];
        float ra[8] = {ra0.x, ra0.y, ra0.z, ra0.w, ra1.x, ra1.y, ra1.z, ra1.w};
        float rb[8] = {rb0.x, rb0.y, rb0.z, rb0.w, rb1.x, rb1.y, rb1.z, rb1.w};
        #pragma unroll
        for (int i = 0; i < 8; i++)
            #pragma unroll
            for (int j = 0; j < 8; j++) acc[i][j] += ra[i] * rb[j];
    }

    #pragma unroll
    for (int i = 0; i < 8; i++) {
        int o = o0 + tm * 8 + i;
        float ed  = expf(fd[o]);
        float bb  = b2[o];
        float fbo = fb[o];
        float v[8];
        #pragma unroll
        for (int j = 0; j < 8; j++) {
            int l = l0 + tn * 8 + j;
            float t = (float)l * (1.0f / (float)(LSEQ - 1));
            v[j] = ((acc[i][j] + bb) * expf(-ed * t) + fbo) * (1.0f / (float)LSEQ);
        }
        *(float4*)&g_h[(size_t)o * LSEQ + l0 + tn * 8]     = make_float4(v[0], v[1], v[2], v[3]);
        *(float4*)&g_h[(size_t)o * LSEQ + l0 + tn * 8 + 4] = make_float4(v[4], v[5], v[6], v[7]);
    }
}

// ---------------------------------------------------------------------------
// FFT pieces (8192-pt, 1024 threads, split re/im padded smem)
__device__ __forceinline__ void fft_fwd_zp(float* __restrict__ SR, float* __restrict__ SI) {
    #pragma unroll
    for (int jj = 0; jj < 4096 / FFT_THREADS; jj++) {
        int j  = threadIdx.x + jj * FFT_THREADS;
        int i0 = PADI(j), i1 = PADI(j + 4096);
        float ar = SR[i0], ai = SI[i0];
        float2 w = g_tw[j];
        SR[i1] = ar * w.x - ai * w.y;
        SI[i1] = ar * w.y + ai * w.x;
    }
    __syncthreads();
    #pragma unroll
    for (int st = 0; st < 6; st++) {
        const int lm  = 10 - 2 * st;
        const int m   = 1 << lm;
        const int str = 2048 >> lm;
        #pragma unroll
        for (int jj = 0; jj < 2048 / FFT_THREADS; jj++) {
            int t = threadIdx.x + jj * FFT_THREADS;
            int q = t & (m - 1);
            int base = ((t >> lm) << (lm + 2)) | q;
            int i0 = PADI(base), i1 = PADI(base + m),
                i2 = PADI(base + 2 * m), i3 = PADI(base + 3 * m);
            float x0r = SR[i0], x0i = SI[i0];
            float x1r = SR[i1], x1i = SI[i1];
            float x2r = SR[i2], x2i = SI[i2];
            float x3r = SR[i3], x3i = SI[i3];
            float2 w1 = g_tw[q * str];
            float2 w2 = g_tw[2 * q * str];
            float2 w3 = g_tw[3 * q * str];
            float t0r = x0r + x2r, t0i = x0i + x2i;
            float t1r = x1r + x3r, t1i = x1i + x3i;
            float t2r = x0r - x2r, t2i = x0i - x2i;
            float t3r = x1i - x3i, t3i = x3r - x1r;
            SR[i0] = t0r + t1r; SI[i0] = t0i + t1i;
            float ur = t2r + t3r, ui = t2i + t3i;
            SR[i1] = ur * w1.x - ui * w1.y; SI[i1] = ur * w1.y + ui * w1.x;
            ur = t0r - t1r; ui = t0i - t1i;
            SR[i2] = ur * w2.x - ui * w2.y; SI[i2] = ur * w2.y + ui * w2.x;
            ur = t2r - t3r; ui = t2i - t3i;
            SR[i3] = ur * w3.x - ui * w3.y; SI[i3] = ur * w3.y + ui * w3.x;
        }
        __syncthreads();
    }
}

__device__ __forceinline__ void fft_inv_half(float* __restrict__ SR, float* __restrict__ SI) {
    #pragma unroll
    for (int st = 0; st < 6; st++) {
        const int lm  = 2 * st;
        const int m   = 1 << lm;
        const int str = 2048 >> lm;
        #pragma unroll
        for (int jj = 0; jj < 2048 / FFT_THREADS; jj++) {
            int t = threadIdx.x + jj * FFT_THREADS;
            int q = t & (m - 1);
            int base = ((t >> lm) << (lm + 2)) | q;
            int i0 = PADI(base), i1 = PADI(base + m),
                i2 = PADI(base + 2 * m), i3 = PADI(base + 3 * m);
            float u0r = SR[i0], u0i = SI[i0];
            float u1r = SR[i1], u1i = SI[i1];
            float u2r = SR[i2], u2i = SI[i2];
            float u3r = SR[i3], u3i = SI[i3];
            float2 w1 = g_tw[q * str];
            float2 w2 = g_tw[2 * q * str];
            float2 w3 = g_tw[3 * q * str];
            float c1r = u1r * w1.x + u1i * w1.y, c1i = u1i * w1.x - u1r * w1.y;
            float c2r = u2r * w2.x + u2i * w2.y, c2i = u2i * w2.x - u2r * w2.y;
            float c3r = u3r * w3.x + u3i * w3.y, c3i = u3i * w3.x - u3r * w3.y;
            float s0r = u0r + c2r, s0i = u0i + c2i;
            float s1r = u0r - c2r, s1i = u0i - c2i;
            float s2r = c1r + c3r, s2i = c1i + c3i;
            float s3r = c1r - c3r, s3i = c1i - c3i;
            SR[i0] = s0r + s2r; SI[i0] = s0i + s2i;
            SR[i2] = s0r - s2r; SI[i2] = s0i - s2i;
            SR[i1] = s1r - s3i; SI[i1] = s1i + s3r;
            SR[i3] = s1r + s3i; SI[i3] = s1i - s3r;
        }
        __syncthreads();
    }
    #pragma unroll
    for (int jj = 0; jj < 4096 / FFT_THREADS; jj++) {
        int j  = threadIdx.x + jj * FFT_THREADS;
        int i0 = PADI(j), i1 = PADI(j + 4096);
        float2 w = g_tw[j];
        float br = SR[i1], bi = SI[i1];
        float tr = br * w.x + bi * w.y;
        float ti = bi * w.x - br * w.y;
        SR[i0] += tr; SI[i0] += ti;
    }
    __syncthreads();
}

// ---------------------------------------------------------------------------
__global__ __launch_bounds__(FFT_THREADS) void hfft_kernel() {
    extern __shared__ float sm[];
    float* SR = sm;
    float* SI = sm + SM_HALF;
    const int c = blockIdx.x;
    const int n = c >> 9;
    const int dpair = c & (NPAIR - 1);
    const float* h0 = g_h + ((size_t)n * DDIM + 2 * dpair)     * LSEQ;
    const float* h1 = g_h + ((size_t)n * DDIM + 2 * dpair + 1) * LSEQ;

    for (int i = threadIdx.x; i < LSEQ; i += FFT_THREADS) {
        SR[PADI(i)] = h0[i]; SI[PADI(i)] = h1[i];
    }
    __syncthreads();
    fft_fwd_zp(SR, SI);

    float2* Ao = g_A + (size_t)c * NF;
    float2* Bo = g_B + (size_t)c * NF;
    for (int p = threadIdx.x; p < NF; p += FFT_THREADS) {
        int q = g_refl[p];
        float zpr = SR[PADI(p)], zpi = SI[PADI(p)];
        float zqr = SR[PADI(q)], zqi = SI[PADI(q)];
        float g0r = 0.5f * (zpr + zqr), g0i = 0.5f * (zpi - zqi);
        float g1r = 0.5f * (zpi + zqi), g1i = 0.5f * (zqr - zpr);
        Ao[p] = make_float2(0.5f * (g0r + g1r), 0.5f * (g0i + g1i));
        Bo[p] = make_float2(0.5f * (g0r - g1r), 0.5f * (g0i - g1i));
    }
}

// ---------------------------------------------------------------------------
__global__ __launch_bounds__(FFT_THREADS) void fftconv_kernel() {
    extern __shared__ float sm[];
    float* SR = sm;
    float* SI = sm + SM_HALF;
    const int c = blockIdx.x;
    const int b = c >> 9;
    const int dpair = c & (NPAIR - 1);
    const int ch0 = 2 * dpair, ch1 = ch0 + 1;
    const float inv = 1.0f / (float)NF;

    const float* v0 = &g_cv[((size_t)(b * 3 + 2) * DDIM + ch0) * LSEQ];
    const float* v1 = &g_cv[((size_t)(b * 3 + 2) * DDIM + ch1) * LSEQ];

    for (int i = threadIdx.x; i < LSEQ; i += FFT_THREADS) {
        SR[PADI(i)] = v0[i]; SI[PADI(i)] = v1[i];
    }
    __syncthreads();

    #pragma unroll 1
    for (int n = 0; n < 2; n++) {
        fft_fwd_zp(SR, SI);

        const float2* Ap = g_A + ((size_t)n * NPAIR + dpair) * NF;
        const float2* Bp = g_B + ((size_t)n * NPAIR + dpair) * NF;
        #pragma unroll
        for (int jj = 0; jj < NF / FFT_THREADS; jj++) {
            int p = threadIdx.x + jj * FFT_THREADS;
            int q = g_refl[p];
            if (q < p) continue;
            int ip = PADI(p), iq = PADI(q);
            float zr = SR[ip], zi = SI[ip];
            float wr = SR[iq], wi = SI[iq];
            float2 a  = Ap[p];
            float2 bb = Bp[p];
            float ypr = a.x * zr - a.y * zi + bb.x * wr + bb.y * wi;
            float ypi = a.x * zi + a.y * zr + bb.y * wr - bb.x * wi;
            float yqr = a.x * wr + a.y * wi + bb.x * zr - bb.y * zi;
            float yqi = a.x * wi - a.y * wr - bb.x * zi - bb.y * zr;
            SR[ip] = ypr; SI[ip] = ypi;
            SR[iq] = yqr; SI[iq] = yqi;
        }
        __syncthreads();

        fft_inv_half(SR, SI);

        if (n == 0) {
            const float* xa = &g_cv[((size_t)(b * 3 + 0) * DDIM + ch0) * LSEQ];
            const float* xb = &g_cv[((size_t)(b * 3 + 0) * DDIM + ch1) * LSEQ];
            for (int l = threadIdx.x; l < LSEQ; l += FFT_THREADS) {
                int ip = PADI(l);
                SR[ip] = SR[ip] * inv * xa[l];
                SI[ip] = SI[ip] * inv * xb[l];
            }
            __syncthreads();
        } else {
            const float* xa = &g_cv[((size_t)(b * 3 + 1) * DDIM + ch0) * LSEQ];
            const float* xb = &g_cv[((size_t)(b * 3 + 1) * DDIM + ch1) * LSEQ];
            uint32_t* vh0 = g_vh + ((size_t)(b * DDIM + ch0)) * (LSEQ / 2);
            uint32_t* vl0 = g_vl + ((size_t)(b * DDIM + ch0)) * (LSEQ / 2);
            uint32_t* vh1 = g_vh + ((size_t)(b * DDIM + ch1)) * (LSEQ / 2);
            uint32_t* vl1 = g_vl + ((size_t)(b * DDIM + ch1)) * (LSEQ / 2);
            for (int l2 = threadIdx.x; l2 < LSEQ / 2; l2 += FFT_THREADS) {
                int l = 2 * l2;
                float y0a = SR[PADI(l)]     * inv * xa[l];
                float y0b = SR[PADI(l + 1)] * inv * xa[l + 1];
                float y1a = SI[PADI(l)]     * inv * xb[l];
                float y1b = SI[PADI(l + 1)] * inv * xb[l + 1];
                vh0[l2] = pack_hi(y0a, y0b); vl0[l2] = pack_lo(y0a, y0b);
                vh1[l2] = pack_hi(y1a, y1b); vl1[l2] = pack_lo(y1a, y1b);
            }
        }
    }
}

// ---------------------------------------------------------------------------
__global__ void conv3_kernel(const float* __restrict__ cw, const float* __restrict__ cb) {
    const int row = blockIdx.y;            // b*3072 + od
    const int od  = row % ODIM;
    const int l   = blockIdx.x * 256 + threadIdx.x;
    const float* r = g_res + (size_t)row * LSEQ;
    float left  = (l > 0)        ? r[l - 1] : 0.0f;
    float mid   = r[l];
    float right = (l < LSEQ - 1) ? r[l + 1] : 0.0f;
    float w0 = cw[od * 3], w1 = cw[od * 3 + 1], w2 = cw[od * 3 + 2];
    g_cv[(size_t)row * LSEQ + l] = w0 * left + w1 * mid + w2 * right + cb[od];
}

// ---------------------------------------------------------------------------
extern "C" void kernel_launch(void* const* d_in, const int* in_sizes, int n_in,
                              void* d_out, int out_size)
{
    const float* u          = (const float*)d_in[0];
    const float* w_in       = (const float*)d_in[1];
    const float* b_in       = (const float*)d_in[2];
    const float* conv_w     = (const float*)d_in[3];
    const float* conv_b     = (const float*)d_in[4];
    const float* w1         = (const float*)d_in[5];
    const float* b1         = (const float*)d_in[6];
    const float* w2         = (const float*)d_in[7];
    const float* b2         = (const float*)d_in[8];
    const float* filt_bias  = (const float*)d_in[9];
    const float* filt_decay = (const float*)d_in[10];
    const float* w_out      = (const float*)d_in[11];
    const float* b_out      = (const float*)d_in[12];
    float* out = (float*)d_out;

    static bool attr_set = false;
    if (!attr_set) {
        cudaFuncSetAttribute(hfft_kernel,    cudaFuncAttributeMaxDynamicSharedMemorySize, FFT_SMEM);
        cudaFuncSetAttribute(fftconv_kernel, cudaFuncAttributeMaxDynamicSharedMemorySize, FFT_SMEM);
        cudaFuncSetAttribute(gemm_in_mma,    cudaFuncAttributeMaxDynamicSharedMemorySize, GI_SMEM);
        cudaFuncSetAttribute(gemm_out_mma,   cudaFuncAttributeMaxDynamicSharedMemorySize, GO_SMEM);
        cudaFuncSetAttribute(filter_gemm,    cudaFuncAttributeMaxDynamicSharedMemorySize, 65536);
        attr_set = true;
    }

    uint32_t *p_wh, *p_wl, *p_uh, *p_ul, *p_oh, *p_ol;
    cudaGetSymbolAddress((void**)&p_wh, g_wh);
    cudaGetSymbolAddress((void**)&p_wl, g_wl);
    cudaGetSymbolAddress((void**)&p_uh, g_uh);
    cudaGetSymbolAddress((void**)&p_ul, g_ul);
    cudaGetSymbolAddress((void**)&p_oh, g_oh);
    cudaGetSymbolAddress((void**)&p_ol, g_ol);

    // Filter path first (hfft is launch #4 for the profiler window)
    init_kernel<<<32, 256>>>();
    sact_kernel<<<LSEQ * 64 / 256, 256>>>(w1, b1);
    filter_gemm<<<dim3(LSEQ / 128, 2 * DDIM / 128), 256, 65536>>>(w2, b2, filt_bias, filt_decay);
    hfft_kernel<<<2 * NPAIR, FFT_THREADS, FFT_SMEM>>>();

    // Operand conversions
    cvt_split<<<(ODIM * DDIM / 2 + 255) / 256, 256>>>(w_in, p_wh, p_wl, ODIM * DDIM / 2);
    cvt_split<<<(BSZ * LSEQ * DDIM / 2 + 255) / 256, 256>>>(u, p_uh, p_ul, BSZ * LSEQ * DDIM / 2);
    cvt_split<<<(DDIM * DDIM / 2 + 255) / 256, 256>>>(w_out, p_oh, p_ol, DDIM * DDIM / 2);

    // Main path
    gemm_in_mma<<<dim3(LSEQ / 128, ODIM / 128, BSZ), 256, GI_SMEM>>>(b_in);
    conv3_kernel<<<dim3(LSEQ / 256, BSZ * ODIM), 256>>>(conv_w, conv_b);
    fftconv_kernel<<<BSZ * NPAIR, FFT_THREADS, FFT_SMEM>>>();
    gemm_out_mma<<<dim3(DDIM / 128, LSEQ / 128, BSZ), 256, GO_SMEM>>>(b_out, out);
}